// round 3
// baseline (speedup 1.0000x reference)
#include <cuda_runtime.h>
#include <math.h>

// ---------------------------------------------------------------------------
// Problem constants
// ---------------------------------------------------------------------------
#define NB   8
#define IMG  512

// ---------------------------------------------------------------------------
// Scratch (static device globals — no allocations allowed)
// ---------------------------------------------------------------------------
__device__ float g_gray  [NB*IMG*IMG];
__device__ float g_lap   [NB*IMG*IMG];
__device__ float g_flags [NB*127*127];
__device__ float g_maskR [NB*64*64];
__device__ float g_maskD [NB*64*64];
__device__ float g_t     [NB*256*64*64];   // conv output scratch (max = level 0)
__device__ float g_spmean[NB*64*64];
__device__ float g_spmax [NB*64*64];
__device__ float g_sw    [NB*64*64];
__device__ float g_gap   [NB*1024];
__device__ float g_cw    [NB*1024];
__device__ float g_bnA   [1024];
__device__ float g_bnB   [1024];
__device__ int   g_anyR;                   // 1 if rgb mask has any nonzero
__device__ int   g_anyD;                   // 1 if depth mask has any nonzero

// ---------------------------------------------------------------------------
// Stage A: blur mask from rgb image + depth mask
// ---------------------------------------------------------------------------
__global__ void k_zeroflags() {
    g_anyR = 0;
    g_anyD = 0;
}

__global__ void k_gray(const float* __restrict__ rgb) {
    int idx = blockIdx.x * blockDim.x + threadIdx.x;
    if (idx >= NB*IMG*IMG) return;
    int b = idx / (IMG*IMG);
    int p = idx - b * (IMG*IMG);
    const float* base = rgb + (size_t)b * 3 * IMG * IMG;
    float g = 0.299f*base[p] + 0.587f*base[IMG*IMG + p] + 0.114f*base[2*IMG*IMG + p];
    g *= 255.0f;
    g = fminf(fmaxf(g, 0.0f), 255.0f);
    g_gray[idx] = g;
}

__global__ void k_lap() {
    int idx = blockIdx.x * blockDim.x + threadIdx.x;
    if (idx >= NB*IMG*IMG) return;
    int b = idx / (IMG*IMG);
    int p = idx - b * (IMG*IMG);
    int y = p / IMG, x = p - y * IMG;
    const float* g = g_gray + (size_t)b * IMG * IMG;
    float c = g[y*IMG + x];
    float u = (y > 0)       ? g[(y-1)*IMG + x] : 0.0f;
    float d = (y < IMG-1)   ? g[(y+1)*IMG + x] : 0.0f;
    float l = (x > 0)       ? g[y*IMG + x-1]   : 0.0f;
    float r = (x < IMG-1)   ? g[y*IMG + x+1]   : 0.0f;
    g_lap[idx] = u + d + l + r - 4.0f*c;
}

__global__ void k_flags() {
    int idx = blockIdx.x * blockDim.x + threadIdx.x;
    if (idx >= NB*127*127) return;
    int b = idx / (127*127);
    int rem = idx - b * (127*127);
    int i = rem / 127, j = rem - i * 127;
    const float* lp = g_lap + (size_t)b * IMG * IMG + (4*i)*IMG + 4*j;
    float s1 = 0.0f, s2 = 0.0f;
    #pragma unroll
    for (int dy = 0; dy < 8; dy++) {
        #pragma unroll
        for (int dx = 0; dx < 8; dx++) {
            float v = lp[dy*IMG + dx];
            s1 += v; s2 += v*v;
        }
    }
    float var = (s2 - s1*s1*(1.0f/64.0f)) * (1.0f/63.0f);
    g_flags[idx] = (var < 50.0f) ? 1.0f : 0.0f;
}

__global__ void k_masks(const float* __restrict__ depth) {
    int idx = blockIdx.x * blockDim.x + threadIdx.x;
    if (idx >= NB*64*64) return;
    int b = idx / (64*64);
    int rem = idx - b * (64*64);
    int k = rem / 64, l = rem - k * 64;
    float f = 0.0f;
    #pragma unroll
    for (int da = 0; da < 2; da++) {
        int a = 2*k - da;
        if (a < 0) continue;
        #pragma unroll
        for (int db = 0; db < 2; db++) {
            int bb = 2*l - db;
            if (bb < 0) continue;
            f = fmaxf(f, g_flags[((size_t)b*127 + a)*127 + bb]);
        }
    }
    g_maskR[idx] = f;
    float dv = depth[((size_t)b*3 + 2)*IMG*IMG + (8*k)*IMG + 8*l];
    float md = (dv <= 0.0f) ? 1.0f : 0.0f;
    g_maskD[idx] = md;
    if (f  > 0.0f) atomicOr(&g_anyR, 1);
    if (md > 0.0f) atomicOr(&g_anyD, 1);
}

// ---------------------------------------------------------------------------
// 3x3 conv (pad=1, cross-correlation), NCHW.
// Block: 64 c_out x 128 pixels for one batch image. 128 threads, each 8x8.
// Early-exits (whole kernel) when the direction's mask is entirely zero.
// ---------------------------------------------------------------------------
template<int C, int S>
__global__ void __launch_bounds__(128) k_conv(const float* __restrict__ aux,
                                              const float* __restrict__ w,
                                              int useRmask) {
    if ((useRmask ? g_anyR : g_anyD) == 0) return;
    constexpr int R  = 128 / S;     // rows per pixel tile
    constexpr int BK = 8;
    __shared__ float sW[BK*9*64];
    __shared__ float sIn[BK*(R+2)*(S+2)];

    const int b      = blockIdx.z;
    const int coBase = blockIdx.y * 64;
    const int yBase  = blockIdx.x * R;
    const int t  = threadIdx.x;
    const int tx = t & 15;
    const int ty = t >> 4;
    const int px0 = tx * 8;
    const int r   = px0 / S;
    const int c0  = px0 - r * S;

    float acc[8][8];
    #pragma unroll
    for (int i = 0; i < 8; i++)
        #pragma unroll
        for (int j = 0; j < 8; j++) acc[i][j] = 0.0f;

    for (int ci0 = 0; ci0 < C; ci0 += BK) {
        __syncthreads();
        // weights: sW[(ci*9+tap)*64 + co]
        for (int i = t; i < 64*BK*9; i += 128) {
            int co = i / (BK*9);
            int rem = i - co * (BK*9);
            sW[rem*64 + co] = w[(size_t)(coBase + co)*C*9 + (size_t)ci0*9 + rem];
        }
        // input tile with halo: sIn[ci][rr][cc], rr=0..R+1 -> row yBase+rr-1, cc-1=col
        constexpr int ITOT = BK*(R+2)*(S+2);
        for (int i = t; i < ITOT; i += 128) {
            int ci  = i / ((R+2)*(S+2));
            int rem = i - ci * ((R+2)*(S+2));
            int rr  = rem / (S+2);
            int cc  = rem - rr * (S+2);
            int gy = yBase + rr - 1;
            int gx = cc - 1;
            float v = 0.0f;
            if (gy >= 0 && gy < S && gx >= 0 && gx < S)
                v = aux[(((size_t)b*C + ci0 + ci)*S + gy)*S + gx];
            sIn[i] = v;
        }
        __syncthreads();

        #pragma unroll 1
        for (int ci = 0; ci < BK; ci++) {
            const float* sI = &sIn[ci*(R+2)*(S+2) + r*(S+2) + c0];
            float in0[10], in1[10], in2[10];
            #pragma unroll
            for (int j = 0; j < 10; j++) {
                in0[j] = sI[j];
                in1[j] = sI[(S+2) + j];
                in2[j] = sI[2*(S+2) + j];
            }
            const float* sWc = &sW[ci*9*64 + ty*8];
            #pragma unroll
            for (int i = 0; i < 8; i++) {
                float w0 = sWc[0*64+i], w1 = sWc[1*64+i], w2 = sWc[2*64+i];
                float w3 = sWc[3*64+i], w4 = sWc[4*64+i], w5 = sWc[5*64+i];
                float w6 = sWc[6*64+i], w7 = sWc[7*64+i], w8 = sWc[8*64+i];
                #pragma unroll
                for (int j = 0; j < 8; j++) {
                    float s = acc[i][j];
                    s += w0*in0[j];   s += w1*in0[j+1]; s += w2*in0[j+2];
                    s += w3*in1[j];   s += w4*in1[j+1]; s += w5*in1[j+2];
                    s += w6*in2[j];   s += w7*in2[j+1]; s += w8*in2[j+2];
                    acc[i][j] = s;
                }
            }
        }
    }

    #pragma unroll
    for (int i = 0; i < 8; i++) {
        size_t base = (((size_t)b*C + coBase + ty*8 + i)*S + yBase + r)*S + c0;
        #pragma unroll
        for (int j = 0; j < 8; j++)
            g_t[base + j] = acc[i][j];
    }
}

// ---------------------------------------------------------------------------
// BN stats over (B, H, W) per channel -> fused scale/bias
// ---------------------------------------------------------------------------
__global__ void k_bnstats(const float* __restrict__ gamma,
                          const float* __restrict__ beta, int C, int S,
                          int useRmask) {
    if ((useRmask ? g_anyR : g_anyD) == 0) return;
    int c = blockIdx.x;
    int n = NB * S * S;
    float s = 0.0f, q = 0.0f;
    for (int i = threadIdx.x; i < n; i += 256) {
        int b = i / (S*S);
        int p = i - b * (S*S);
        float v = g_t[((size_t)b*C + c)*S*S + p];
        s += v; q += v*v;
    }
    __shared__ float ss[256], sq[256];
    ss[threadIdx.x] = s; sq[threadIdx.x] = q;
    __syncthreads();
    for (int o = 128; o > 0; o >>= 1) {
        if (threadIdx.x < o) {
            ss[threadIdx.x] += ss[threadIdx.x + o];
            sq[threadIdx.x] += sq[threadIdx.x + o];
        }
        __syncthreads();
    }
    if (threadIdx.x == 0) {
        float mean = ss[0] / (float)n;
        float var  = sq[0] / (float)n - mean*mean;
        float rstd = 1.0f / sqrtf(var + 1e-5f);
        float A = gamma[c] * rstd;
        g_bnA[c] = A;
        g_bnB[c] = beta[c] - mean * A;
    }
}

// ---------------------------------------------------------------------------
// Spatial attention: per-pixel channel mean/max, then 7x7 conv + sigmoid
// ---------------------------------------------------------------------------
__global__ void k_spstats(const float* __restrict__ mainp, int C, int S,
                          int useRmask) {
    if ((useRmask ? g_anyR : g_anyD) == 0) return;
    int b = blockIdx.y, y = blockIdx.x, x = threadIdx.x;
    const float* p = mainp + (size_t)b*C*S*S + y*S + x;
    float m = 0.0f, mx = -3.402823466e38f;
    for (int c = 0; c < C; c++) {
        float v = p[(size_t)c*S*S];
        m += v; mx = fmaxf(mx, v);
    }
    g_spmean[(size_t)b*S*S + y*S + x] = m / (float)C;
    g_spmax [(size_t)b*S*S + y*S + x] = mx;
}

__global__ void k_spconv(const float* __restrict__ saw, int S, int useRmask) {
    if ((useRmask ? g_anyR : g_anyD) == 0) return;
    __shared__ float sw_[196];
    int b = blockIdx.y, y = blockIdx.x, x = threadIdx.x;
    for (int i = x; i < 196; i += blockDim.x) sw_[i] = saw[i];
    __syncthreads();
    float step = 2.0f / (float)(S - 1);
    float acc = 0.0f;
    #pragma unroll
    for (int ky = 0; ky < 7; ky++) {
        int yy = y + ky - 3;
        if (yy < 0 || yy >= S) continue;
        #pragma unroll
        for (int kx = 0; kx < 7; kx++) {
            int xx = x + kx - 3;
            if (xx < 0 || xx >= S) continue;
            int widx = ky*7 + kx;
            acc += sw_[widx]        * g_spmean[(size_t)b*S*S + yy*S + xx];
            acc += sw_[49 + widx]   * g_spmax [(size_t)b*S*S + yy*S + xx];
            acc += sw_[98 + widx]   * (-1.0f + (float)xx * step);
            acc += sw_[147 + widx]  * (-1.0f + (float)yy * step);
        }
    }
    g_sw[(size_t)b*S*S + y*S + x] = 1.0f / (1.0f + expf(-acc));
}

// ---------------------------------------------------------------------------
// Channel attention: GAP -> ca1 -> relu -> ca2 -> sigmoid
// ---------------------------------------------------------------------------
__global__ void k_gap(const float* __restrict__ mainp, int C, int S,
                      int useRmask) {
    if ((useRmask ? g_anyR : g_anyD) == 0) return;
    int c = blockIdx.x, b = blockIdx.y;
    const float* p = mainp + ((size_t)b*C + c)*S*S;
    float s = 0.0f;
    for (int i = threadIdx.x; i < S*S; i += 128) s += p[i];
    __shared__ float sm[128];
    sm[threadIdx.x] = s;
    __syncthreads();
    for (int o = 64; o > 0; o >>= 1) {
        if (threadIdx.x < o) sm[threadIdx.x] += sm[threadIdx.x + o];
        __syncthreads();
    }
    if (threadIdx.x == 0) g_gap[b*C + c] = sm[0] / (float)(S*S);
}

__global__ void k_ca(const float* __restrict__ ca1, const float* __restrict__ ca2,
                     int C, int Rr, int useRmask) {
    if ((useRmask ? g_anyR : g_anyD) == 0) return;
    int b = blockIdx.x;
    __shared__ float sg[1024];
    __shared__ float sh[64];
    for (int c = threadIdx.x; c < C; c += 128) sg[c] = g_gap[b*C + c];
    __syncthreads();
    for (int rr = threadIdx.x; rr < Rr; rr += 128) {
        float h = 0.0f;
        for (int c = 0; c < C; c++) h += ca1[(size_t)rr*C + c] * sg[c];
        sh[rr] = fmaxf(h, 0.0f);
    }
    __syncthreads();
    for (int c = threadIdx.x; c < C; c += 128) {
        float v = 0.0f;
        for (int rr = 0; rr < Rr; rr++) v += ca2[(size_t)c*Rr + rr] * sh[rr];
        g_cw[b*C + c] = 1.0f / (1.0f + expf(-v));
    }
}

// ---------------------------------------------------------------------------
// Final blend: out = (inv==0) ? main : 2 * relu(A*t+B) * sw * cw
// ---------------------------------------------------------------------------
__global__ void k_final(const float* __restrict__ mainp, float* __restrict__ outp,
                        int C, int S, int step, int useRmask) {
    int idx = blockIdx.x * blockDim.x + threadIdx.x;
    int N = NB * C * S * S;
    if (idx >= N) return;
    int b   = idx / (C*S*S);
    int rem = idx - b * (C*S*S);
    int c   = rem / (S*S);
    int p   = rem - c * (S*S);
    int y = p / S, x = p - y * S;
    const float* maskp = useRmask ? g_maskR : g_maskD;
    float inv = maskp[((size_t)b*64 + y*step)*64 + x*step];
    float res;
    if (inv == 0.0f) {
        res = mainp[idx];
    } else {
        float tv = g_t[idx];
        float a  = fmaxf(g_bnA[c]*tv + g_bnB[c], 0.0f);
        res = ((a * g_sw[(size_t)b*S*S + p]) * g_cw[b*C + c]) * 2.0f;
    }
    outp[idx] = res;
}

// ---------------------------------------------------------------------------
// Host orchestration
// ---------------------------------------------------------------------------
struct LvlParams {
    const float *ft, *g, *b, *sa, *ca1, *ca2;
};

template<int C, int S>
static void run_dir(const float* mainp, const float* auxp, int useRmask,
                    float* outp, const LvlParams& P) {
    k_conv<C, S><<<dim3(S*S/128, C/64, NB), 128>>>(auxp, P.ft, useRmask);
    k_bnstats<<<C, 256>>>(P.g, P.b, C, S, useRmask);
    k_spstats<<<dim3(S, NB), S>>>(mainp, C, S, useRmask);
    k_spconv<<<dim3(S, NB), S>>>(P.sa, S, useRmask);
    k_gap<<<dim3(C, NB), 128>>>(mainp, C, S, useRmask);
    k_ca<<<NB, 128>>>(P.ca1, P.ca2, C, C/16, useRmask);
    int N = NB * C * S * S;
    k_final<<<(N + 255)/256, 256>>>(mainp, outp, C, S, 64/S, useRmask);
}

extern "C" void kernel_launch(void* const* d_in, const int* in_sizes, int n_in,
                              void* d_out, int out_size) {
    // metadata order follows setup_inputs() dict insertion order:
    // rgb_feat0, depth_feat0, rgb_feat1, depth_feat1, rgb_feat2, depth_feat2,
    // rgb_img, depth_img, then per level: ft_w, bn_g, bn_b, sa_w, ca1_w, ca2_w
    const float* rgbF[3] = {(const float*)d_in[0], (const float*)d_in[2], (const float*)d_in[4]};
    const float* depF[3] = {(const float*)d_in[1], (const float*)d_in[3], (const float*)d_in[5]};
    const float* rgb_img   = (const float*)d_in[6];
    const float* depth_img = (const float*)d_in[7];
    LvlParams P[3];
    for (int i = 0; i < 3; i++) {
        int base = 8 + i*6;
        P[i].ft  = (const float*)d_in[base + 0];
        P[i].g   = (const float*)d_in[base + 1];
        P[i].b   = (const float*)d_in[base + 2];
        P[i].sa  = (const float*)d_in[base + 3];
        P[i].ca1 = (const float*)d_in[base + 4];
        P[i].ca2 = (const float*)d_in[base + 5];
    }
    float* out = (float*)d_out;

    // masks
    int npix = NB * IMG * IMG;
    k_zeroflags<<<1, 1>>>();
    k_gray <<<(npix + 255)/256, 256>>>(rgb_img);
    k_lap  <<<(npix + 255)/256, 256>>>();
    k_flags<<<(NB*127*127 + 255)/256, 256>>>();
    k_masks<<<(NB*64*64 + 255)/256, 256>>>(depth_img);

    const size_t szR0 = (size_t)NB*256*64*64;   // 8388608
    const size_t szR1 = (size_t)NB*512*32*32;   // 4194304
    const size_t szR2 = (size_t)NB*1024*16*16;  // 2097152
    float* oR0 = out;
    float* oR1 = oR0 + szR0;
    float* oR2 = oR1 + szR1;
    float* oD0 = oR2 + szR2;
    float* oD1 = oD0 + szR0;
    float* oD2 = oD1 + szR1;

    // rgb outputs: main=rgb, aux=depth, rgb mask
    run_dir<256, 64>(rgbF[0], depF[0], 1, oR0, P[0]);
    run_dir<512, 32>(rgbF[1], depF[1], 1, oR1, P[1]);
    run_dir<1024,16>(rgbF[2], depF[2], 1, oR2, P[2]);
    // depth outputs: main=depth, aux=rgb, depth mask
    run_dir<256, 64>(depF[0], rgbF[0], 0, oD0, P[0]);
    run_dir<512, 32>(depF[1], rgbF[1], 0, oD1, P[1]);
    run_dir<1024,16>(depF[2], rgbF[2], 0, oD2, P[2]);
}

// round 4
// speedup vs baseline: 1.0459x; 1.0459x over previous
#include <cuda_runtime.h>
#include <math.h>

// ---------------------------------------------------------------------------
// Problem constants
// ---------------------------------------------------------------------------
#define NB   8
#define IMG  512

// ---------------------------------------------------------------------------
// Scratch (static device globals — no allocations allowed)
// ---------------------------------------------------------------------------
__device__ float g_gray  [NB*IMG*IMG];
__device__ float g_lap   [NB*IMG*IMG];
__device__ float g_flags [NB*127*127];
__device__ float g_maskR [NB*64*64];
__device__ float g_maskD [NB*64*64];
__device__ float g_t     [NB*256*64*64];   // conv output scratch (max = level 0)
__device__ float g_spmean[NB*64*64];
__device__ float g_spmax [NB*64*64];
__device__ float g_sw    [NB*64*64];
__device__ float g_gap   [NB*1024];
__device__ float g_cw    [NB*1024];
__device__ float g_bnA   [1024];
__device__ float g_bnB   [1024];
__device__ int   g_anyR;                   // 1 if rgb mask has any nonzero
__device__ int   g_anyD;                   // 1 if depth mask has any nonzero

// ---------------------------------------------------------------------------
// Packed f32x2 helpers (Blackwell dual-FMA; PTX-only, ptxas never emits it)
// ---------------------------------------------------------------------------
__device__ __forceinline__ unsigned long long pack2b(float v) {
    unsigned long long r;
    asm("mov.b64 %0, {%1, %1};" : "=l"(r) : "f"(v));
    return r;
}
__device__ __forceinline__ void fma2(unsigned long long& acc,
                                     unsigned long long a,
                                     unsigned long long b) {
    asm("fma.rn.f32x2 %0, %1, %2, %0;" : "+l"(acc) : "l"(a), "l"(b));
}
__device__ __forceinline__ void unpack2(unsigned long long v, float& lo, float& hi) {
    asm("mov.b64 {%0, %1}, %2;" : "=f"(lo), "=f"(hi) : "l"(v));
}

// ---------------------------------------------------------------------------
// Stage A: blur mask from rgb image + depth mask
// ---------------------------------------------------------------------------
__global__ void k_zeroflags() {
    g_anyR = 0;
    g_anyD = 0;
}

__global__ void k_gray(const float* __restrict__ rgb) {
    int idx = blockIdx.x * blockDim.x + threadIdx.x;
    if (idx >= NB*IMG*IMG) return;
    int b = idx / (IMG*IMG);
    int p = idx - b * (IMG*IMG);
    const float* base = rgb + (size_t)b * 3 * IMG * IMG;
    float g = 0.299f*base[p] + 0.587f*base[IMG*IMG + p] + 0.114f*base[2*IMG*IMG + p];
    g *= 255.0f;
    g = fminf(fmaxf(g, 0.0f), 255.0f);
    g_gray[idx] = g;
}

__global__ void k_lap() {
    int idx = blockIdx.x * blockDim.x + threadIdx.x;
    if (idx >= NB*IMG*IMG) return;
    int b = idx / (IMG*IMG);
    int p = idx - b * (IMG*IMG);
    int y = p / IMG, x = p - y * IMG;
    const float* g = g_gray + (size_t)b * IMG * IMG;
    float c = g[y*IMG + x];
    float u = (y > 0)       ? g[(y-1)*IMG + x] : 0.0f;
    float d = (y < IMG-1)   ? g[(y+1)*IMG + x] : 0.0f;
    float l = (x > 0)       ? g[y*IMG + x-1]   : 0.0f;
    float r = (x < IMG-1)   ? g[y*IMG + x+1]   : 0.0f;
    g_lap[idx] = u + d + l + r - 4.0f*c;
}

__global__ void k_flags() {
    int idx = blockIdx.x * blockDim.x + threadIdx.x;
    if (idx >= NB*127*127) return;
    int b = idx / (127*127);
    int rem = idx - b * (127*127);
    int i = rem / 127, j = rem - i * 127;
    const float* lp = g_lap + (size_t)b * IMG * IMG + (4*i)*IMG + 4*j;
    float s1 = 0.0f, s2 = 0.0f;
    #pragma unroll
    for (int dy = 0; dy < 8; dy++) {
        #pragma unroll
        for (int dx = 0; dx < 8; dx++) {
            float v = lp[dy*IMG + dx];
            s1 += v; s2 += v*v;
        }
    }
    float var = (s2 - s1*s1*(1.0f/64.0f)) * (1.0f/63.0f);
    g_flags[idx] = (var < 50.0f) ? 1.0f : 0.0f;
}

__global__ void k_masks(const float* __restrict__ depth) {
    int idx = blockIdx.x * blockDim.x + threadIdx.x;
    if (idx >= NB*64*64) return;
    int b = idx / (64*64);
    int rem = idx - b * (64*64);
    int k = rem / 64, l = rem - k * 64;
    float f = 0.0f;
    #pragma unroll
    for (int da = 0; da < 2; da++) {
        int a = 2*k - da;
        if (a < 0) continue;
        #pragma unroll
        for (int db = 0; db < 2; db++) {
            int bb = 2*l - db;
            if (bb < 0) continue;
            f = fmaxf(f, g_flags[((size_t)b*127 + a)*127 + bb]);
        }
    }
    g_maskR[idx] = f;
    float dv = depth[((size_t)b*3 + 2)*IMG*IMG + (8*k)*IMG + 8*l];
    float md = (dv <= 0.0f) ? 1.0f : 0.0f;
    g_maskD[idx] = md;
    if (f  > 0.0f) atomicOr(&g_anyR, 1);
    if (md > 0.0f) atomicOr(&g_anyD, 1);
}

// ---------------------------------------------------------------------------
// 3x3 conv (pad=1, cross-correlation), NCHW, packed-f32x2 dual-FMA inner loop.
// Block: 64 c_out x 128 pixels for one batch image. 128 threads.
// Each thread: 4 cout-pairs (8 couts) x 8 pixels, accumulators packed f32x2.
// Early-exits (whole kernel) when the direction's mask is entirely zero.
// ---------------------------------------------------------------------------
template<int C, int S>
__global__ void __launch_bounds__(128) k_conv(const float* __restrict__ aux,
                                              const float* __restrict__ w,
                                              int useRmask) {
    if ((useRmask ? g_anyR : g_anyD) == 0) return;
    constexpr int R  = 128 / S;     // rows per pixel tile
    constexpr int BK = 8;
    __shared__ float sW[BK*9*64];
    __shared__ float sIn[BK*(R+2)*(S+2)];

    const int b      = blockIdx.z;
    const int coBase = blockIdx.y * 64;
    const int yBase  = blockIdx.x * R;
    const int t  = threadIdx.x;
    const int tx = t & 15;
    const int ty = t >> 4;
    const int px0 = tx * 8;
    const int r   = px0 / S;
    const int c0  = px0 - r * S;

    unsigned long long acc[4][8];
    #pragma unroll
    for (int i = 0; i < 4; i++)
        #pragma unroll
        for (int j = 0; j < 8; j++) acc[i][j] = 0ULL;

    for (int ci0 = 0; ci0 < C; ci0 += BK) {
        __syncthreads();
        // weights: sW[(ci*9+tap)*64 + co]  (adjacent couts adjacent -> LDS.64 pairs)
        for (int i = t; i < 64*BK*9; i += 128) {
            int co = i / (BK*9);
            int rem = i - co * (BK*9);
            sW[rem*64 + co] = w[(size_t)(coBase + co)*C*9 + (size_t)ci0*9 + rem];
        }
        // input tile with halo: sIn[ci][rr][cc], rr=0..R+1 -> row yBase+rr-1, cc-1=col
        constexpr int ITOT = BK*(R+2)*(S+2);
        for (int i = t; i < ITOT; i += 128) {
            int ci  = i / ((R+2)*(S+2));
            int rem = i - ci * ((R+2)*(S+2));
            int rr  = rem / (S+2);
            int cc  = rem - rr * (S+2);
            int gy = yBase + rr - 1;
            int gx = cc - 1;
            float v = 0.0f;
            if (gy >= 0 && gy < S && gx >= 0 && gx < S)
                v = aux[(((size_t)b*C + ci0 + ci)*S + gy)*S + gx];
            sIn[i] = v;
        }
        __syncthreads();

        #pragma unroll 1
        for (int ci = 0; ci < BK; ci++) {
            const float* sI = &sIn[ci*(R+2)*(S+2) + r*(S+2) + c0];
            // broadcast-packed input rows (lo=hi=value)
            unsigned long long b0[10], b1[10], b2[10];
            #pragma unroll
            for (int j = 0; j < 10; j++) {
                b0[j] = pack2b(sI[j]);
                b1[j] = pack2b(sI[(S+2) + j]);
                b2[j] = pack2b(sI[2*(S+2) + j]);
            }
            const float* sWc = &sW[ci*9*64 + ty*8];
            #pragma unroll
            for (int i = 0; i < 4; i++) {
                // cout pair (2i, 2i+1): one 64-bit shared load per tap
                unsigned long long wp[9];
                #pragma unroll
                for (int tap = 0; tap < 9; tap++)
                    wp[tap] = *(const unsigned long long*)&sWc[tap*64 + 2*i];
                #pragma unroll
                for (int j = 0; j < 8; j++) {
                    fma2(acc[i][j], wp[0], b0[j]);
                    fma2(acc[i][j], wp[1], b0[j+1]);
                    fma2(acc[i][j], wp[2], b0[j+2]);
                    fma2(acc[i][j], wp[3], b1[j]);
                    fma2(acc[i][j], wp[4], b1[j+1]);
                    fma2(acc[i][j], wp[5], b1[j+2]);
                    fma2(acc[i][j], wp[6], b2[j]);
                    fma2(acc[i][j], wp[7], b2[j+1]);
                    fma2(acc[i][j], wp[8], b2[j+2]);
                }
            }
        }
    }

    #pragma unroll
    for (int i = 0; i < 4; i++) {
        size_t baseLo = (((size_t)b*C + coBase + ty*8 + 2*i    )*S + yBase + r)*S + c0;
        size_t baseHi = (((size_t)b*C + coBase + ty*8 + 2*i + 1)*S + yBase + r)*S + c0;
        #pragma unroll
        for (int j = 0; j < 8; j++) {
            float lo, hi;
            unpack2(acc[i][j], lo, hi);
            g_t[baseLo + j] = lo;
            g_t[baseHi + j] = hi;
        }
    }
}

// ---------------------------------------------------------------------------
// BN stats over (B, H, W) per channel -> fused scale/bias
// ---------------------------------------------------------------------------
__global__ void k_bnstats(const float* __restrict__ gamma,
                          const float* __restrict__ beta, int C, int S,
                          int useRmask) {
    if ((useRmask ? g_anyR : g_anyD) == 0) return;
    int c = blockIdx.x;
    int n = NB * S * S;
    float s = 0.0f, q = 0.0f;
    for (int i = threadIdx.x; i < n; i += 256) {
        int b = i / (S*S);
        int p = i - b * (S*S);
        float v = g_t[((size_t)b*C + c)*S*S + p];
        s += v; q += v*v;
    }
    __shared__ float ss[256], sq[256];
    ss[threadIdx.x] = s; sq[threadIdx.x] = q;
    __syncthreads();
    for (int o = 128; o > 0; o >>= 1) {
        if (threadIdx.x < o) {
            ss[threadIdx.x] += ss[threadIdx.x + o];
            sq[threadIdx.x] += sq[threadIdx.x + o];
        }
        __syncthreads();
    }
    if (threadIdx.x == 0) {
        float mean = ss[0] / (float)n;
        float var  = sq[0] / (float)n - mean*mean;
        float rstd = 1.0f / sqrtf(var + 1e-5f);
        float A = gamma[c] * rstd;
        g_bnA[c] = A;
        g_bnB[c] = beta[c] - mean * A;
    }
}

// ---------------------------------------------------------------------------
// Spatial attention: per-pixel channel mean/max, then 7x7 conv + sigmoid
// ---------------------------------------------------------------------------
__global__ void k_spstats(const float* __restrict__ mainp, int C, int S,
                          int useRmask) {
    if ((useRmask ? g_anyR : g_anyD) == 0) return;
    int b = blockIdx.y, y = blockIdx.x, x = threadIdx.x;
    const float* p = mainp + (size_t)b*C*S*S + y*S + x;
    float m = 0.0f, mx = -3.402823466e38f;
    for (int c = 0; c < C; c++) {
        float v = p[(size_t)c*S*S];
        m += v; mx = fmaxf(mx, v);
    }
    g_spmean[(size_t)b*S*S + y*S + x] = m / (float)C;
    g_spmax [(size_t)b*S*S + y*S + x] = mx;
}

__global__ void k_spconv(const float* __restrict__ saw, int S, int useRmask) {
    if ((useRmask ? g_anyR : g_anyD) == 0) return;
    __shared__ float sw_[196];
    int b = blockIdx.y, y = blockIdx.x, x = threadIdx.x;
    for (int i = x; i < 196; i += blockDim.x) sw_[i] = saw[i];
    __syncthreads();
    float step = 2.0f / (float)(S - 1);
    float acc = 0.0f;
    #pragma unroll
    for (int ky = 0; ky < 7; ky++) {
        int yy = y + ky - 3;
        if (yy < 0 || yy >= S) continue;
        #pragma unroll
        for (int kx = 0; kx < 7; kx++) {
            int xx = x + kx - 3;
            if (xx < 0 || xx >= S) continue;
            int widx = ky*7 + kx;
            acc += sw_[widx]        * g_spmean[(size_t)b*S*S + yy*S + xx];
            acc += sw_[49 + widx]   * g_spmax [(size_t)b*S*S + yy*S + xx];
            acc += sw_[98 + widx]   * (-1.0f + (float)xx * step);
            acc += sw_[147 + widx]  * (-1.0f + (float)yy * step);
        }
    }
    g_sw[(size_t)b*S*S + y*S + x] = 1.0f / (1.0f + expf(-acc));
}

// ---------------------------------------------------------------------------
// Channel attention: GAP -> ca1 -> relu -> ca2 -> sigmoid
// ---------------------------------------------------------------------------
__global__ void k_gap(const float* __restrict__ mainp, int C, int S,
                      int useRmask) {
    if ((useRmask ? g_anyR : g_anyD) == 0) return;
    int c = blockIdx.x, b = blockIdx.y;
    const float* p = mainp + ((size_t)b*C + c)*S*S;
    float s = 0.0f;
    for (int i = threadIdx.x; i < S*S; i += 128) s += p[i];
    __shared__ float sm[128];
    sm[threadIdx.x] = s;
    __syncthreads();
    for (int o = 64; o > 0; o >>= 1) {
        if (threadIdx.x < o) sm[threadIdx.x] += sm[threadIdx.x + o];
        __syncthreads();
    }
    if (threadIdx.x == 0) g_gap[b*C + c] = sm[0] / (float)(S*S);
}

__global__ void k_ca(const float* __restrict__ ca1, const float* __restrict__ ca2,
                     int C, int Rr, int useRmask) {
    if ((useRmask ? g_anyR : g_anyD) == 0) return;
    int b = blockIdx.x;
    __shared__ float sg[1024];
    __shared__ float sh[64];
    for (int c = threadIdx.x; c < C; c += 128) sg[c] = g_gap[b*C + c];
    __syncthreads();
    for (int rr = threadIdx.x; rr < Rr; rr += 128) {
        float h = 0.0f;
        for (int c = 0; c < C; c++) h += ca1[(size_t)rr*C + c] * sg[c];
        sh[rr] = fmaxf(h, 0.0f);
    }
    __syncthreads();
    for (int c = threadIdx.x; c < C; c += 128) {
        float v = 0.0f;
        for (int rr = 0; rr < Rr; rr++) v += ca2[(size_t)c*Rr + rr] * sh[rr];
        g_cw[b*C + c] = 1.0f / (1.0f + expf(-v));
    }
}

// ---------------------------------------------------------------------------
// Final blend: out = (inv==0) ? main : 2 * relu(A*t+B) * sw * cw
// ---------------------------------------------------------------------------
__global__ void k_final(const float* __restrict__ mainp, float* __restrict__ outp,
                        int C, int S, int step, int useRmask) {
    int idx = blockIdx.x * blockDim.x + threadIdx.x;
    int N = NB * C * S * S;
    if (idx >= N) return;
    int b   = idx / (C*S*S);
    int rem = idx - b * (C*S*S);
    int c   = rem / (S*S);
    int p   = rem - c * (S*S);
    int y = p / S, x = p - y * S;
    const float* maskp = useRmask ? g_maskR : g_maskD;
    float inv = maskp[((size_t)b*64 + y*step)*64 + x*step];
    float res;
    if (inv == 0.0f) {
        res = mainp[idx];
    } else {
        float tv = g_t[idx];
        float a  = fmaxf(g_bnA[c]*tv + g_bnB[c], 0.0f);
        res = ((a * g_sw[(size_t)b*S*S + p]) * g_cw[b*C + c]) * 2.0f;
    }
    outp[idx] = res;
}

// ---------------------------------------------------------------------------
// Host orchestration
// ---------------------------------------------------------------------------
struct LvlParams {
    const float *ft, *g, *b, *sa, *ca1, *ca2;
};

template<int C, int S>
static void run_dir(const float* mainp, const float* auxp, int useRmask,
                    float* outp, const LvlParams& P) {
    k_conv<C, S><<<dim3(S*S/128, C/64, NB), 128>>>(auxp, P.ft, useRmask);
    k_bnstats<<<C, 256>>>(P.g, P.b, C, S, useRmask);
    k_spstats<<<dim3(S, NB), S>>>(mainp, C, S, useRmask);
    k_spconv<<<dim3(S, NB), S>>>(P.sa, S, useRmask);
    k_gap<<<dim3(C, NB), 128>>>(mainp, C, S, useRmask);
    k_ca<<<NB, 128>>>(P.ca1, P.ca2, C, C/16, useRmask);
    int N = NB * C * S * S;
    k_final<<<(N + 255)/256, 256>>>(mainp, outp, C, S, 64/S, useRmask);
}

extern "C" void kernel_launch(void* const* d_in, const int* in_sizes, int n_in,
                              void* d_out, int out_size) {
    // metadata order follows setup_inputs() dict insertion order:
    // rgb_feat0, depth_feat0, rgb_feat1, depth_feat1, rgb_feat2, depth_feat2,
    // rgb_img, depth_img, then per level: ft_w, bn_g, bn_b, sa_w, ca1_w, ca2_w
    const float* rgbF[3] = {(const float*)d_in[0], (const float*)d_in[2], (const float*)d_in[4]};
    const float* depF[3] = {(const float*)d_in[1], (const float*)d_in[3], (const float*)d_in[5]};
    const float* rgb_img   = (const float*)d_in[6];
    const float* depth_img = (const float*)d_in[7];
    LvlParams P[3];
    for (int i = 0; i < 3; i++) {
        int base = 8 + i*6;
        P[i].ft  = (const float*)d_in[base + 0];
        P[i].g   = (const float*)d_in[base + 1];
        P[i].b   = (const float*)d_in[base + 2];
        P[i].sa  = (const float*)d_in[base + 3];
        P[i].ca1 = (const float*)d_in[base + 4];
        P[i].ca2 = (const float*)d_in[base + 5];
    }
    float* out = (float*)d_out;

    // masks
    int npix = NB * IMG * IMG;
    k_zeroflags<<<1, 1>>>();
    k_gray <<<(npix + 255)/256, 256>>>(rgb_img);
    k_lap  <<<(npix + 255)/256, 256>>>();
    k_flags<<<(NB*127*127 + 255)/256, 256>>>();
    k_masks<<<(NB*64*64 + 255)/256, 256>>>(depth_img);

    const size_t szR0 = (size_t)NB*256*64*64;   // 8388608
    const size_t szR1 = (size_t)NB*512*32*32;   // 4194304
    const size_t szR2 = (size_t)NB*1024*16*16;  // 2097152
    float* oR0 = out;
    float* oR1 = oR0 + szR0;
    float* oR2 = oR1 + szR1;
    float* oD0 = oR2 + szR2;
    float* oD1 = oD0 + szR0;
    float* oD2 = oD1 + szR1;

    // rgb outputs: main=rgb, aux=depth, rgb mask
    run_dir<256, 64>(rgbF[0], depF[0], 1, oR0, P[0]);
    run_dir<512, 32>(rgbF[1], depF[1], 1, oR1, P[1]);
    run_dir<1024,16>(rgbF[2], depF[2], 1, oR2, P[2]);
    // depth outputs: main=depth, aux=rgb, depth mask
    run_dir<256, 64>(depF[0], rgbF[0], 0, oD0, P[0]);
    run_dir<512, 32>(depF[1], rgbF[1], 0, oD1, P[1]);
    run_dir<1024,16>(depF[2], rgbF[2], 0, oD2, P[2]);
}

// round 6
// speedup vs baseline: 2.1186x; 2.0257x over previous
#include <cuda_runtime.h>
#include <cuda_bf16.h>
#include <math.h>
#include <stdint.h>

// ---------------------------------------------------------------------------
// Problem constants
// ---------------------------------------------------------------------------
#define NB   8
#define IMG  512

// ---------------------------------------------------------------------------
// Scratch (static device globals — no allocations allowed)
// ---------------------------------------------------------------------------
__device__ float g_gray  [NB*IMG*IMG];
__device__ float g_lap   [NB*IMG*IMG];
__device__ float g_flags [NB*127*127];
__device__ float g_maskR [NB*64*64];
__device__ float g_maskD [NB*64*64];
__device__ float g_t     [NB*256*64*64];   // conv output scratch (max = level 0)
__device__ float g_spmean[NB*64*64];
__device__ float g_spmax [NB*64*64];
__device__ float g_sw    [NB*64*64];
__device__ float g_gap   [NB*1024];
__device__ float g_cw    [NB*1024];
__device__ float g_bnA   [1024];
__device__ float g_bnB   [1024];
__device__ int   g_anyR;                   // 1 if rgb mask has any nonzero
__device__ int   g_anyD;                   // 1 if depth mask has any nonzero

// bf16 hi/lo split scratch for tensor-core conv
__device__ __nv_bfloat16 g_wh  [9*1024*1024];   // weights hi, [tap][co][ci]
__device__ __nv_bfloat16 g_wl  [9*1024*1024];   // weights lo
__device__ __nv_bfloat16 g_auxh[NB*256*64*64];  // aux features hi (NCHW)
__device__ __nv_bfloat16 g_auxl[NB*256*64*64];  // aux features lo

// ---------------------------------------------------------------------------
// MMA helpers
// ---------------------------------------------------------------------------
__device__ __forceinline__ uint32_t smem_u32(const void* p) {
    return (uint32_t)__cvta_generic_to_shared(p);
}
__device__ __forceinline__ void ldsm4(uint32_t* r, uint32_t addr) {
    asm volatile("ldmatrix.sync.aligned.m8n8.x4.shared.b16 {%0,%1,%2,%3}, [%4];"
                 : "=r"(r[0]), "=r"(r[1]), "=r"(r[2]), "=r"(r[3]) : "r"(addr));
}
__device__ __forceinline__ void ldsm2(uint32_t* r, uint32_t addr) {
    asm volatile("ldmatrix.sync.aligned.m8n8.x2.shared.b16 {%0,%1}, [%2];"
                 : "=r"(r[0]), "=r"(r[1]) : "r"(addr));
}
__device__ __forceinline__ void mma16816(float* c, const uint32_t* a, const uint32_t* b) {
    asm volatile("mma.sync.aligned.m16n8k16.row.col.f32.bf16.bf16.f32 "
                 "{%0,%1,%2,%3}, {%4,%5,%6,%7}, {%8,%9}, {%0,%1,%2,%3};"
                 : "+f"(c[0]), "+f"(c[1]), "+f"(c[2]), "+f"(c[3])
                 : "r"(a[0]), "r"(a[1]), "r"(a[2]), "r"(a[3]), "r"(b[0]), "r"(b[1]));
}

// ---------------------------------------------------------------------------
// Stage A: blur mask from rgb image + depth mask
// ---------------------------------------------------------------------------
__global__ void k_zeroflags() {
    g_anyR = 0;
    g_anyD = 0;
}

__global__ void k_gray(const float* __restrict__ rgb) {
    int idx = blockIdx.x * blockDim.x + threadIdx.x;
    if (idx >= NB*IMG*IMG) return;
    int b = idx / (IMG*IMG);
    int p = idx - b * (IMG*IMG);
    const float* base = rgb + (size_t)b * 3 * IMG * IMG;
    float g = 0.299f*base[p] + 0.587f*base[IMG*IMG + p] + 0.114f*base[2*IMG*IMG + p];
    g *= 255.0f;
    g = fminf(fmaxf(g, 0.0f), 255.0f);
    g_gray[idx] = g;
}

__global__ void k_lap() {
    int idx = blockIdx.x * blockDim.x + threadIdx.x;
    if (idx >= NB*IMG*IMG) return;
    int b = idx / (IMG*IMG);
    int p = idx - b * (IMG*IMG);
    int y = p / IMG, x = p - y * IMG;
    const float* g = g_gray + (size_t)b * IMG * IMG;
    float c = g[y*IMG + x];
    float u = (y > 0)       ? g[(y-1)*IMG + x] : 0.0f;
    float d = (y < IMG-1)   ? g[(y+1)*IMG + x] : 0.0f;
    float l = (x > 0)       ? g[y*IMG + x-1]   : 0.0f;
    float r = (x < IMG-1)   ? g[y*IMG + x+1]   : 0.0f;
    g_lap[idx] = u + d + l + r - 4.0f*c;
}

__global__ void k_flags() {
    int idx = blockIdx.x * blockDim.x + threadIdx.x;
    if (idx >= NB*127*127) return;
    int b = idx / (127*127);
    int rem = idx - b * (127*127);
    int i = rem / 127, j = rem - i * 127;
    const float* lp = g_lap + (size_t)b * IMG * IMG + (4*i)*IMG + 4*j;
    float s1 = 0.0f, s2 = 0.0f;
    #pragma unroll
    for (int dy = 0; dy < 8; dy++) {
        #pragma unroll
        for (int dx = 0; dx < 8; dx++) {
            float v = lp[dy*IMG + dx];
            s1 += v; s2 += v*v;
        }
    }
    float var = (s2 - s1*s1*(1.0f/64.0f)) * (1.0f/63.0f);
    g_flags[idx] = (var < 50.0f) ? 1.0f : 0.0f;
}

__global__ void k_masks(const float* __restrict__ depth) {
    int idx = blockIdx.x * blockDim.x + threadIdx.x;
    if (idx >= NB*64*64) return;
    int b = idx / (64*64);
    int rem = idx - b * (64*64);
    int k = rem / 64, l = rem - k * 64;
    float f = 0.0f;
    #pragma unroll
    for (int da = 0; da < 2; da++) {
        int a = 2*k - da;
        if (a < 0) continue;
        #pragma unroll
        for (int db = 0; db < 2; db++) {
            int bb = 2*l - db;
            if (bb < 0) continue;
            f = fmaxf(f, g_flags[((size_t)b*127 + a)*127 + bb]);
        }
    }
    g_maskR[idx] = f;
    float dv = depth[((size_t)b*3 + 2)*IMG*IMG + (8*k)*IMG + 8*l];
    float md = (dv <= 0.0f) ? 1.0f : 0.0f;
    g_maskD[idx] = md;
    if (f  > 0.0f) atomicOr(&g_anyR, 1);
    if (md > 0.0f) atomicOr(&g_anyD, 1);
}

// ---------------------------------------------------------------------------
// bf16 hi/lo conversion kernels
// ---------------------------------------------------------------------------
// Weights: w[co][ci][3][3] fp32 -> g_wh/g_wl [tap][co][ci]. Once per level.
__global__ void k_cvtw(const float* __restrict__ w, int C) {
    if (g_anyR == 0 && g_anyD == 0) return;
    int idx = blockIdx.x * blockDim.x + threadIdx.x;
    int n = 9 * C * C;
    if (idx >= n) return;
    int t   = idx / (C * C);
    int rem = idx - t * (C * C);
    int co  = rem / C;
    int ci  = rem - co * C;
    float v = w[((size_t)co * C + ci) * 9 + t];
    __nv_bfloat16 h = __float2bfloat16(v);
    g_wh[idx] = h;
    g_wl[idx] = __float2bfloat16(v - __bfloat162float(h));
}

// Aux features: fp32 NCHW -> hi/lo bf16, same layout. Per (level, direction).
__global__ void k_cvtaux(const float* __restrict__ aux, int n, int useRmask) {
    if ((useRmask ? g_anyR : g_anyD) == 0) return;
    int idx = blockIdx.x * blockDim.x + threadIdx.x;
    if (idx >= n) return;
    float v = aux[idx];
    __nv_bfloat16 h = __float2bfloat16(v);
    g_auxh[idx] = h;
    g_auxl[idx] = __float2bfloat16(v - __bfloat162float(h));
}

// ---------------------------------------------------------------------------
// Tensor-core 3x3 conv (pad=1, cross-correlation), NCHW.
// CTA: 64 couts x 128 pixels (16 rows x 8 cols). 8 warps (2M x 4N).
// K loop: 16 input channels per chunk x 9 taps. bf16 hi/lo, 3 mma passes.
// smem rows padded to 24 elems (48B) -> conflict-free ldmatrix.
// ---------------------------------------------------------------------------
#define CONV_SMEM_BYTES ((2*9*64*24 + 2*180*24) * 2)

template<int C, int S>
__global__ void __launch_bounds__(256) k_conv_mma(int useRmask) {
    if ((useRmask ? g_anyR : g_anyD) == 0) return;

    extern __shared__ __align__(16) char smem_raw[];
    __nv_bfloat16* sAh = (__nv_bfloat16*)smem_raw;      // 9*64*24
    __nv_bfloat16* sAl = sAh + 9*64*24;
    __nv_bfloat16* sBh = sAl + 9*64*24;                  // 180*24
    __nv_bfloat16* sBl = sBh + 180*24;

    const int b      = blockIdx.z;
    const int coBase = blockIdx.y * 64;
    constexpr int XT = S / 8;
    const int y0 = (blockIdx.x / XT) * 16;
    const int x0 = (blockIdx.x % XT) * 8;

    const int tid  = threadIdx.x;
    const int lane = tid & 31;
    const int wid  = tid >> 5;
    const int wm   = wid & 1;       // 0..1 : co 32-block
    const int wn   = wid >> 1;      // 0..3 : pixel-row 4-block

    // lane-dependent ldmatrix address components (element units)
    const int aM = ((lane >> 3) & 1) * 8 + (lane & 7);   // row within m16
    const int aK = (lane >> 4) * 8;                       // k offset 0/8
    const int lb = lane & 15;
    const int bRow = lb & 7;                              // pixel-col within n8
    const int bK   = (lb >> 3) * 8;                       // k offset 0/8

    const uint32_t sAh32 = smem_u32(sAh);
    const uint32_t sAl32 = smem_u32(sAl);
    const uint32_t sBh32 = smem_u32(sBh);
    const uint32_t sBl32 = smem_u32(sBl);

    float acc[2][4][4];
    #pragma unroll
    for (int mf = 0; mf < 2; mf++)
        #pragma unroll
        for (int nf = 0; nf < 4; nf++)
            #pragma unroll
            for (int k = 0; k < 4; k++) acc[mf][nf][k] = 0.0f;

    for (int ci0 = 0; ci0 < C; ci0 += 16) {
        if (ci0) __syncthreads();
        // --- stage A: weights [9][64co][16ci] hi+lo, rows padded to 24 ---
        for (int i = tid; i < 1152; i += 256) {
            int row = i >> 1, half = i & 1;
            int t = row >> 6, co = row & 63;
            size_t se = ((size_t)t * C + coBase + co) * C + ci0 + half * 8;
            int de = (t * 64 + co) * 24 + half * 8;
            *(uint4*)(sAh + de) = *(const uint4*)(g_wh + se);
            *(uint4*)(sAl + de) = *(const uint4*)(g_wl + se);
        }
        // --- stage B: input region [18y][10x][16ci] hi+lo, rows padded to 24 ---
        for (int i = tid; i < 2880; i += 256) {
            int pix = i % 180, ci = i / 180;
            int iy = pix / 10, ix = pix - iy * 10;
            int gy = y0 - 1 + iy, gx = x0 - 1 + ix;
            __nv_bfloat16 vh = __float2bfloat16(0.0f);
            __nv_bfloat16 vl = vh;
            if (gy >= 0 && gy < S && gx >= 0 && gx < S) {
                size_t gi = (((size_t)b * C + ci0 + ci) * S + gy) * S + gx;
                vh = g_auxh[gi];
                vl = g_auxl[gi];
            }
            sBh[pix * 24 + ci] = vh;
            sBl[pix * 24 + ci] = vl;
        }
        __syncthreads();

        for (int t = 0; t < 9; t++) {
            const int tty = t / 3, ttx = t - tty * 3;
            uint32_t Ah[2][4], Al[2][4];
            #pragma unroll
            for (int mf = 0; mf < 2; mf++) {
                int ea = (t * 64 + wm * 32 + mf * 16 + aM) * 24 + aK;
                ldsm4(Ah[mf], sAh32 + ea * 2);
                ldsm4(Al[mf], sAl32 + ea * 2);
            }
            #pragma unroll
            for (int nf = 0; nf < 4; nf++) {
                int eb = (((wn * 4 + nf + tty) * 10 + ttx + bRow)) * 24 + bK;
                uint32_t Bh[2], Bl[2];
                ldsm2(Bh, sBh32 + eb * 2);
                ldsm2(Bl, sBl32 + eb * 2);
                #pragma unroll
                for (int mf = 0; mf < 2; mf++) {
                    mma16816(acc[mf][nf], Ah[mf], Bh);
                    mma16816(acc[mf][nf], Ah[mf], Bl);
                    mma16816(acc[mf][nf], Al[mf], Bh);
                }
            }
        }
    }

    // --- epilogue: write fp32 to g_t (NCHW) ---
    #pragma unroll
    for (int mf = 0; mf < 2; mf++) {
        #pragma unroll
        for (int nf = 0; nf < 4; nf++) {
            int co = coBase + wm * 32 + mf * 16 + (lane >> 2);
            int y  = y0 + wn * 4 + nf;
            int x  = x0 + (lane & 3) * 2;
            size_t o = (((size_t)b * C + co) * S + y) * S + x;
            float2 lo; lo.x = acc[mf][nf][0]; lo.y = acc[mf][nf][1];
            float2 hi; hi.x = acc[mf][nf][2]; hi.y = acc[mf][nf][3];
            *(float2*)(g_t + o) = lo;                          // rows co
            *(float2*)(g_t + o + (size_t)8 * S * S) = hi;      // rows co+8
        }
    }
}

// ---------------------------------------------------------------------------
// BN stats over (B, H, W) per channel -> fused scale/bias
// ---------------------------------------------------------------------------
__global__ void k_bnstats(const float* __restrict__ gamma,
                          const float* __restrict__ beta, int C, int S,
                          int useRmask) {
    if ((useRmask ? g_anyR : g_anyD) == 0) return;
    int c = blockIdx.x;
    int n = NB * S * S;
    float s = 0.0f, q = 0.0f;
    for (int i = threadIdx.x; i < n; i += 256) {
        int b = i / (S*S);
        int p = i - b * (S*S);
        float v = g_t[((size_t)b*C + c)*S*S + p];
        s += v; q += v*v;
    }
    __shared__ float ss[256], sq[256];
    ss[threadIdx.x] = s; sq[threadIdx.x] = q;
    __syncthreads();
    for (int o = 128; o > 0; o >>= 1) {
        if (threadIdx.x < o) {
            ss[threadIdx.x] += ss[threadIdx.x + o];
            sq[threadIdx.x] += sq[threadIdx.x + o];
        }
        __syncthreads();
    }
    if (threadIdx.x == 0) {
        float mean = ss[0] / (float)n;
        float var  = sq[0] / (float)n - mean*mean;
        float rstd = 1.0f / sqrtf(var + 1e-5f);
        float A = gamma[c] * rstd;
        g_bnA[c] = A;
        g_bnB[c] = beta[c] - mean * A;
    }
}

// ---------------------------------------------------------------------------
// Spatial attention: per-pixel channel mean/max (coalesced), 7x7 conv + sigmoid
// ---------------------------------------------------------------------------
__global__ void k_spstats(const float* __restrict__ mainp, int C, int S,
                          int useRmask) {
    if ((useRmask ? g_anyR : g_anyD) == 0) return;
    int b = blockIdx.y;
    int p = blockIdx.x * blockDim.x + threadIdx.x;
    if (p >= S*S) return;
    const float* base = mainp + (size_t)b*C*S*S + p;
    float m = 0.0f, mx = -3.402823466e38f;
    #pragma unroll 4
    for (int c = 0; c < C; c++) {
        float v = base[(size_t)c*S*S];
        m += v; mx = fmaxf(mx, v);
    }
    g_spmean[(size_t)b*S*S + p] = m / (float)C;
    g_spmax [(size_t)b*S*S + p] = mx;
}

__global__ void k_spconv(const float* __restrict__ saw, int S, int useRmask) {
    if ((useRmask ? g_anyR : g_anyD) == 0) return;
    __shared__ float sw_[196];
    int b = blockIdx.y, y = blockIdx.x, x = threadIdx.x;
    for (int i = x; i < 196; i += blockDim.x) sw_[i] = saw[i];
    __syncthreads();
    float step = 2.0f / (float)(S - 1);
    float acc = 0.0f;
    #pragma unroll
    for (int ky = 0; ky < 7; ky++) {
        int yy = y + ky - 3;
        if (yy < 0 || yy >= S) continue;
        #pragma unroll
        for (int kx = 0; kx < 7; kx++) {
            int xx = x + kx - 3;
            if (xx < 0 || xx >= S) continue;
            int widx = ky*7 + kx;
            acc += sw_[widx]        * g_spmean[(size_t)b*S*S + yy*S + xx];
            acc += sw_[49 + widx]   * g_spmax [(size_t)b*S*S + yy*S + xx];
            acc += sw_[98 + widx]   * (-1.0f + (float)xx * step);
            acc += sw_[147 + widx]  * (-1.0f + (float)yy * step);
        }
    }
    g_sw[(size_t)b*S*S + y*S + x] = 1.0f / (1.0f + expf(-acc));
}

// ---------------------------------------------------------------------------
// Channel attention: GAP -> ca1 -> relu -> ca2 -> sigmoid
// ---------------------------------------------------------------------------
__global__ void k_gap(const float* __restrict__ mainp, int C, int S,
                      int useRmask) {
    if ((useRmask ? g_anyR : g_anyD) == 0) return;
    int c = blockIdx.x, b = blockIdx.y;
    const float* p = mainp + ((size_t)b*C + c)*S*S;
    float s = 0.0f;
    for (int i = threadIdx.x; i < S*S; i += 128) s += p[i];
    __shared__ float sm[128];
    sm[threadIdx.x] = s;
    __syncthreads();
    for (int o = 64; o > 0; o >>= 1) {
        if (threadIdx.x < o) sm[threadIdx.x] += sm[threadIdx.x + o];
        __syncthreads();
    }
    if (threadIdx.x == 0) g_gap[b*C + c] = sm[0] / (float)(S*S);
}

__global__ void k_ca(const float* __restrict__ ca1, const float* __restrict__ ca2,
                     int C, int Rr, int useRmask) {
    if ((useRmask ? g_anyR : g_anyD) == 0) return;
    int b = blockIdx.x;
    __shared__ float sg[1024];
    __shared__ float sh[64];
    for (int c = threadIdx.x; c < C; c += 128) sg[c] = g_gap[b*C + c];
    __syncthreads();
    for (int rr = threadIdx.x; rr < Rr; rr += 128) {
        float h = 0.0f;
        for (int c = 0; c < C; c++) h += ca1[(size_t)rr*C + c] * sg[c];
        sh[rr] = fmaxf(h, 0.0f);
    }
    __syncthreads();
    for (int c = threadIdx.x; c < C; c += 128) {
        float v = 0.0f;
        for (int rr = 0; rr < Rr; rr++) v += ca2[(size_t)c*Rr + rr] * sh[rr];
        g_cw[b*C + c] = 1.0f / (1.0f + expf(-v));
    }
}

// ---------------------------------------------------------------------------
// Final blend: out = (inv==0) ? main : 2 * relu(A*t+B) * sw * cw
// ---------------------------------------------------------------------------
__global__ void k_final(const float* __restrict__ mainp, float* __restrict__ outp,
                        int C, int S, int step, int useRmask) {
    int idx = blockIdx.x * blockDim.x + threadIdx.x;
    int N = NB * C * S * S;
    if (idx >= N) return;
    int b   = idx / (C*S*S);
    int rem = idx - b * (C*S*S);
    int c   = rem / (S*S);
    int p   = rem - c * (S*S);
    int y = p / S, x = p - y * S;
    const float* maskp = useRmask ? g_maskR : g_maskD;
    float inv = maskp[((size_t)b*64 + y*step)*64 + x*step];
    float res;
    if (inv == 0.0f) {
        res = mainp[idx];
    } else {
        float tv = g_t[idx];
        float a  = fmaxf(g_bnA[c]*tv + g_bnB[c], 0.0f);
        res = ((a * g_sw[(size_t)b*S*S + p]) * g_cw[b*C + c]) * 2.0f;
    }
    outp[idx] = res;
}

// ---------------------------------------------------------------------------
// Host orchestration
// ---------------------------------------------------------------------------
struct LvlParams {
    const float *ft, *g, *b, *sa, *ca1, *ca2;
};

template<int C, int S>
static void run_dir(const float* mainp, const float* auxp, int useRmask,
                    float* outp, const LvlParams& P) {
    int nAux = NB * C * S * S;
    k_cvtaux<<<(nAux + 255)/256, 256>>>(auxp, nAux, useRmask);
    cudaFuncSetAttribute(k_conv_mma<C, S>,
                         cudaFuncAttributeMaxDynamicSharedMemorySize,
                         CONV_SMEM_BYTES);
    dim3 cgrid((S/16)*(S/8), C/64, NB);
    k_conv_mma<C, S><<<cgrid, 256, CONV_SMEM_BYTES>>>(useRmask);
    k_bnstats<<<C, 256>>>(P.g, P.b, C, S, useRmask);
    k_spstats<<<dim3((S*S + 255)/256, NB), 256>>>(mainp, C, S, useRmask);
    k_spconv<<<dim3(S, NB), S>>>(P.sa, S, useRmask);
    k_gap<<<dim3(C, NB), 128>>>(mainp, C, S, useRmask);
    k_ca<<<NB, 128>>>(P.ca1, P.ca2, C, C/16, useRmask);
    int N = NB * C * S * S;
    k_final<<<(N + 255)/256, 256>>>(mainp, outp, C, S, 64/S, useRmask);
}

extern "C" void kernel_launch(void* const* d_in, const int* in_sizes, int n_in,
                              void* d_out, int out_size) {
    // metadata order follows setup_inputs() dict insertion order:
    // rgb_feat0, depth_feat0, rgb_feat1, depth_feat1, rgb_feat2, depth_feat2,
    // rgb_img, depth_img, then per level: ft_w, bn_g, bn_b, sa_w, ca1_w, ca2_w
    const float* rgbF[3] = {(const float*)d_in[0], (const float*)d_in[2], (const float*)d_in[4]};
    const float* depF[3] = {(const float*)d_in[1], (const float*)d_in[3], (const float*)d_in[5]};
    const float* rgb_img   = (const float*)d_in[6];
    const float* depth_img = (const float*)d_in[7];
    LvlParams P[3];
    for (int i = 0; i < 3; i++) {
        int base = 8 + i*6;
        P[i].ft  = (const float*)d_in[base + 0];
        P[i].g   = (const float*)d_in[base + 1];
        P[i].b   = (const float*)d_in[base + 2];
        P[i].sa  = (const float*)d_in[base + 3];
        P[i].ca1 = (const float*)d_in[base + 4];
        P[i].ca2 = (const float*)d_in[base + 5];
    }
    float* out = (float*)d_out;

    // masks
    int npix = NB * IMG * IMG;
    k_zeroflags<<<1, 1>>>();
    k_gray <<<(npix + 255)/256, 256>>>(rgb_img);
    k_lap  <<<(npix + 255)/256, 256>>>();
    k_flags<<<(NB*127*127 + 255)/256, 256>>>();
    k_masks<<<(NB*64*64 + 255)/256, 256>>>(depth_img);

    const size_t szR0 = (size_t)NB*256*64*64;   // 8388608
    const size_t szR1 = (size_t)NB*512*32*32;   // 4194304
    const size_t szR2 = (size_t)NB*1024*16*16;  // 2097152
    float* oR0 = out;
    float* oR1 = oR0 + szR0;
    float* oR2 = oR1 + szR1;
    float* oD0 = oR2 + szR2;
    float* oD1 = oD0 + szR0;
    float* oD2 = oD1 + szR1;

    // level 0
    k_cvtw<<<(9*256*256 + 255)/256, 256>>>(P[0].ft, 256);
    run_dir<256, 64>(rgbF[0], depF[0], 1, oR0, P[0]);
    run_dir<256, 64>(depF[0], rgbF[0], 0, oD0, P[0]);
    // level 1
    k_cvtw<<<(9*512*512 + 255)/256, 256>>>(P[1].ft, 512);
    run_dir<512, 32>(rgbF[1], depF[1], 1, oR1, P[1]);
    run_dir<512, 32>(depF[1], rgbF[1], 0, oD1, P[1]);
    // level 2
    k_cvtw<<<(9*1024*1024 + 255)/256, 256>>>(P[2].ft, 1024);
    run_dir<1024,16>(rgbF[2], depF[2], 1, oR2, P[2]);
    run_dir<1024,16>(depF[2], rgbF[2], 0, oD2, P[2]);
}

// round 9
// speedup vs baseline: 2.1418x; 1.0109x over previous
#include <cuda_runtime.h>
#include <cuda_bf16.h>
#include <math.h>
#include <stdint.h>

// ---------------------------------------------------------------------------
// Problem constants
// ---------------------------------------------------------------------------
#define NB   8
#define IMG  512

// ---------------------------------------------------------------------------
// Scratch (static device globals — no allocations allowed)
// ---------------------------------------------------------------------------
__device__ float g_gray  [NB*IMG*IMG];
__device__ float g_lap   [NB*IMG*IMG];
__device__ float g_flags [NB*127*127];
__device__ float g_maskR [NB*64*64];
__device__ float g_maskD [NB*64*64];
__device__ float g_t     [NB*256*64*64];   // conv output scratch (max = level 0)
__device__ float g_spmean[NB*64*64];
__device__ float g_spmax [NB*64*64];
__device__ float g_sw    [NB*64*64];
__device__ float g_gap   [NB*1024];
__device__ float g_cw    [NB*1024];
__device__ float g_bnA   [1024];
__device__ float g_bnB   [1024];
__device__ int   g_anyR;                   // 1 if rgb mask has any nonzero
__device__ int   g_anyD;                   // 1 if depth mask has any nonzero

// bf16 hi/lo split scratch for tensor-core conv
// weights: [tap][co][ci] (ci contiguous)
__device__ __nv_bfloat16 g_wh  [9*1024*1024];
__device__ __nv_bfloat16 g_wl  [9*1024*1024];
// aux features: halo-padded NHWC  [b][(S+2)][(S+2)][C]   (max = level 0: 8*66*66*256)
__device__ __nv_bfloat16 g_auxh[8921088];
__device__ __nv_bfloat16 g_auxl[8921088];

// ---------------------------------------------------------------------------
// MMA + cp.async helpers
// ---------------------------------------------------------------------------
__device__ __forceinline__ uint32_t smem_u32(const void* p) {
    return (uint32_t)__cvta_generic_to_shared(p);
}
__device__ __forceinline__ void ldsm4(uint32_t* r, uint32_t addr) {
    asm volatile("ldmatrix.sync.aligned.m8n8.x4.shared.b16 {%0,%1,%2,%3}, [%4];"
                 : "=r"(r[0]), "=r"(r[1]), "=r"(r[2]), "=r"(r[3]) : "r"(addr));
}
__device__ __forceinline__ void ldsm2(uint32_t* r, uint32_t addr) {
    asm volatile("ldmatrix.sync.aligned.m8n8.x2.shared.b16 {%0,%1}, [%2];"
                 : "=r"(r[0]), "=r"(r[1]) : "r"(addr));
}
__device__ __forceinline__ void mma16816(float* c, const uint32_t* a, const uint32_t* b) {
    asm volatile("mma.sync.aligned.m16n8k16.row.col.f32.bf16.bf16.f32 "
                 "{%0,%1,%2,%3}, {%4,%5,%6,%7}, {%8,%9}, {%0,%1,%2,%3};"
                 : "+f"(c[0]), "+f"(c[1]), "+f"(c[2]), "+f"(c[3])
                 : "r"(a[0]), "r"(a[1]), "r"(a[2]), "r"(a[3]), "r"(b[0]), "r"(b[1]));
}
__device__ __forceinline__ void cpa16(uint32_t dst, const void* src) {
    asm volatile("cp.async.cg.shared.global [%0], [%1], 16;" :: "r"(dst), "l"(src));
}
__device__ __forceinline__ void cpa_commit() {
    asm volatile("cp.async.commit_group;");
}
__device__ __forceinline__ void cpa_wait1() {
    asm volatile("cp.async.wait_group 1;");
}
__device__ __forceinline__ void cpa_wait0() {
    asm volatile("cp.async.wait_group 0;");
}

// ---------------------------------------------------------------------------
// Stage A: blur mask from rgb image + depth mask
// ---------------------------------------------------------------------------
__global__ void k_zeroflags() {
    g_anyR = 0;
    g_anyD = 0;
}

__global__ void k_gray(const float* __restrict__ rgb) {
    int idx = blockIdx.x * blockDim.x + threadIdx.x;
    if (idx >= NB*IMG*IMG) return;
    int b = idx / (IMG*IMG);
    int p = idx - b * (IMG*IMG);
    const float* base = rgb + (size_t)b * 3 * IMG * IMG;
    float g = 0.299f*base[p] + 0.587f*base[IMG*IMG + p] + 0.114f*base[2*IMG*IMG + p];
    g *= 255.0f;
    g = fminf(fmaxf(g, 0.0f), 255.0f);
    g_gray[idx] = g;
}

__global__ void k_lap() {
    int idx = blockIdx.x * blockDim.x + threadIdx.x;
    if (idx >= NB*IMG*IMG) return;
    int b = idx / (IMG*IMG);
    int p = idx - b * (IMG*IMG);
    int y = p / IMG, x = p - y * IMG;
    const float* g = g_gray + (size_t)b * IMG * IMG;
    float c = g[y*IMG + x];
    float u = (y > 0)       ? g[(y-1)*IMG + x] : 0.0f;
    float d = (y < IMG-1)   ? g[(y+1)*IMG + x] : 0.0f;
    float l = (x > 0)       ? g[y*IMG + x-1]   : 0.0f;
    float r = (x < IMG-1)   ? g[y*IMG + x+1]   : 0.0f;
    g_lap[idx] = u + d + l + r - 4.0f*c;
}

__global__ void k_flags() {
    int idx = blockIdx.x * blockDim.x + threadIdx.x;
    if (idx >= NB*127*127) return;
    int b = idx / (127*127);
    int rem = idx - b * (127*127);
    int i = rem / 127, j = rem - i * 127;
    const float* lp = g_lap + (size_t)b * IMG * IMG + (4*i)*IMG + 4*j;
    float s1 = 0.0f, s2 = 0.0f;
    #pragma unroll
    for (int dy = 0; dy < 8; dy++) {
        #pragma unroll
        for (int dx = 0; dx < 8; dx++) {
            float v = lp[dy*IMG + dx];
            s1 += v; s2 += v*v;
        }
    }
    float var = (s2 - s1*s1*(1.0f/64.0f)) * (1.0f/63.0f);
    g_flags[idx] = (var < 50.0f) ? 1.0f : 0.0f;
}

__global__ void k_masks(const float* __restrict__ depth) {
    int idx = blockIdx.x * blockDim.x + threadIdx.x;
    if (idx >= NB*64*64) return;
    int b = idx / (64*64);
    int rem = idx - b * (64*64);
    int k = rem / 64, l = rem - k * 64;
    float f = 0.0f;
    #pragma unroll
    for (int da = 0; da < 2; da++) {
        int a = 2*k - da;
        if (a < 0) continue;
        #pragma unroll
        for (int db = 0; db < 2; db++) {
            int bb = 2*l - db;
            if (bb < 0) continue;
            f = fmaxf(f, g_flags[((size_t)b*127 + a)*127 + bb]);
        }
    }
    g_maskR[idx] = f;
    float dv = depth[((size_t)b*3 + 2)*IMG*IMG + (8*k)*IMG + 8*l];
    float md = (dv <= 0.0f) ? 1.0f : 0.0f;
    g_maskD[idx] = md;
    if (f  > 0.0f) atomicOr(&g_anyR, 1);
    if (md > 0.0f) atomicOr(&g_anyD, 1);
}

// ---------------------------------------------------------------------------
// Conversion / layout kernels
// ---------------------------------------------------------------------------
// Weights: w[co][ci][3][3] fp32 -> g_wh/g_wl [tap][co][ci]. Once per level.
__global__ void k_cvtw(const float* __restrict__ w, int C) {
    if (g_anyR == 0 && g_anyD == 0) return;
    int idx = blockIdx.x * blockDim.x + threadIdx.x;
    int n = 9 * C * C;
    if (idx >= n) return;
    int t   = idx / (C * C);
    int rem = idx - t * (C * C);
    int co  = rem / C;
    int ci  = rem - co * C;
    float v = w[((size_t)co * C + ci) * 9 + t];
    __nv_bfloat16 h = __float2bfloat16(v);
    g_wh[idx] = h;
    g_wl[idx] = __float2bfloat16(v - __bfloat162float(h));
}

// Zero the padded NHWC aux arrays (cheap, guarantees halo zeros)
__global__ void k_zero_aux(int n4, int useRmask) {
    if ((useRmask ? g_anyR : g_anyD) == 0) return;
    int i = blockIdx.x * blockDim.x + threadIdx.x;
    if (i >= n4) return;
    uint4 z = {0, 0, 0, 0};
    ((uint4*)g_auxh)[i] = z;
    ((uint4*)g_auxl)[i] = z;
}

// NCHW fp32 -> padded NHWC bf16 hi/lo, smem-tiled transpose.
__global__ void k_cvtaux_pad(const float* __restrict__ aux, int C, int S,
                             int useRmask) {
    if ((useRmask ? g_anyR : g_anyD) == 0) return;
    __shared__ float tile[32][33];
    int S32 = (S + 31) / 32;
    int xt = blockIdx.x % S32;
    int ct = blockIdx.x / S32;
    int y  = blockIdx.y;
    int b  = blockIdx.z;
    int tx = threadIdx.x & 31;
    int tg = threadIdx.x >> 5;      // 0..7
    int S2 = S + 2;
    for (int cc = tg; cc < 32; cc += 8) {
        int x = xt * 32 + tx, c = ct * 32 + cc;
        float v = 0.0f;
        if (x < S) v = aux[(((size_t)b * C + c) * S + y) * S + x];
        tile[cc][tx] = v;
    }
    __syncthreads();
    for (int xx = tg; xx < 32; xx += 8) {
        int x = xt * 32 + xx, c = ct * 32 + tx;
        if (x < S) {
            float v = tile[tx][xx];
            __nv_bfloat16 h = __float2bfloat16(v);
            size_t o = (((size_t)b * S2 + y + 1) * S2 + x + 1) * C + c;
            g_auxh[o] = h;
            g_auxl[o] = __float2bfloat16(v - __bfloat162float(h));
        }
    }
}

// ---------------------------------------------------------------------------
// Tensor-core 3x3 conv (pad=1, cross-correlation), NCHW out.
// CTA: 64 couts x 128 pixels (16 rows x 8 cols). 8 warps (2M x 4N).
// cp.async double-buffered K-chunks of 16 input channels from NHWC-padded aux.
// smem rows padded to 24 elems (48B) -> conflict-free ldmatrix.
// ---------------------------------------------------------------------------
#define A_ELEMS (9*64*24)            // 13824 bf16 per half
#define B_ELEMS (180*24)             // 4320 bf16 per half
#define STAGE_ELEMS (2*A_ELEMS + 2*B_ELEMS)
#define CONV_SMEM_BYTES (2*STAGE_ELEMS*2)   // 145152

template<int C, int S>
__global__ void __launch_bounds__(256) k_conv_mma(int useRmask) {
    if ((useRmask ? g_anyR : g_anyD) == 0) return;

    extern __shared__ __align__(16) char smem_raw[];
    const uint32_t sm0 = smem_u32(smem_raw);

    constexpr int S2 = S + 2;
    const int b      = blockIdx.z;
    const int coBase = blockIdx.y * 64;
    constexpr int XT = S / 8;
    const int y0 = (blockIdx.x / XT) * 16;
    const int x0 = (blockIdx.x % XT) * 8;

    const int tid  = threadIdx.x;
    const int lane = tid & 31;
    const int wid  = tid >> 5;
    const int wm   = wid & 1;       // co 32-block
    const int wn   = wid >> 1;      // pixel-row 4-block

    const __nv_bfloat16* auxhB = g_auxh + (size_t)b * S2 * S2 * C;
    const __nv_bfloat16* auxlB = g_auxl + (size_t)b * S2 * S2 * C;

    // lane-dependent ldmatrix address components (element units)
    const int aM = ((lane >> 3) & 1) * 8 + (lane & 7);
    const int aK = (lane >> 4) * 8;
    const int lb = lane & 15;
    const int bRow = lb & 7;
    const int bK   = (lb >> 3) * 8;

    float acc[2][4][4];
    #pragma unroll
    for (int mf = 0; mf < 2; mf++)
        #pragma unroll
        for (int nf = 0; nf < 4; nf++)
            #pragma unroll
            for (int k = 0; k < 4; k++) acc[mf][nf][k] = 0.0f;

    constexpr int NCHUNK = C / 16;

    // ---- async fill of one stage for chunk ci0 ----
    auto fill = [&](int s, int ci0) {
        uint32_t base = sm0 + (uint32_t)(s * STAGE_ELEMS) * 2;
        // A: weights [9][64co][16ci] hi+lo (1152 16B-chunks per half)
        for (int i = tid; i < 1152; i += 256) {
            int row = i >> 1, half = i & 1;
            int t = row >> 6, co = row & 63;
            size_t se = ((size_t)t * C + coBase + co) * C + ci0 + half * 8;
            uint32_t d = base + (uint32_t)(row * 24 + half * 8) * 2;
            cpa16(d, g_wh + se);
            cpa16(d + A_ELEMS * 2, g_wl + se);
        }
        // B: input region [18y][10x][16ci] hi+lo (360 16B-chunks per half)
        uint32_t bb = base + (uint32_t)(2 * A_ELEMS) * 2;
        for (int i = tid; i < 360; i += 256) {
            int pix = i >> 1, half = i & 1;
            int iy = pix / 10, ix = pix - iy * 10;
            size_t so = (((size_t)(y0 + iy)) * S2 + x0 + ix) * C + ci0 + half * 8;
            uint32_t d = bb + (uint32_t)(pix * 24 + half * 8) * 2;
            cpa16(d, auxhB + so);
            cpa16(d + B_ELEMS * 2, auxlB + so);
        }
    };

    fill(0, 0);
    cpa_commit();

    for (int k = 0; k < NCHUNK; k++) {
        int s = k & 1;
        if (k + 1 < NCHUNK) {
            fill(s ^ 1, (k + 1) * 16);
            cpa_commit();
            cpa_wait1();
        } else {
            cpa_wait0();
        }
        __syncthreads();

        const uint32_t base  = sm0 + (uint32_t)(s * STAGE_ELEMS) * 2;
        const uint32_t sAh32 = base;
        const uint32_t sAl32 = base + A_ELEMS * 2;
        const uint32_t sBh32 = base + 2 * A_ELEMS * 2;
        const uint32_t sBl32 = base + (2 * A_ELEMS + B_ELEMS) * 2;

        for (int t = 0; t < 9; t++) {
            const int tty = t / 3, ttx = t - tty * 3;
            uint32_t Ah[2][4], Al[2][4];
            #pragma unroll
            for (int mf = 0; mf < 2; mf++) {
                int ea = (t * 64 + wm * 32 + mf * 16 + aM) * 24 + aK;
                ldsm4(Ah[mf], sAh32 + ea * 2);
                ldsm4(Al[mf], sAl32 + ea * 2);
            }
            #pragma unroll
            for (int nf = 0; nf < 4; nf++) {
                int eb = ((wn * 4 + nf + tty) * 10 + ttx + bRow) * 24 + bK;
                uint32_t Bh[2], Bl[2];
                ldsm2(Bh, sBh32 + eb * 2);
                ldsm2(Bl, sBl32 + eb * 2);
                #pragma unroll
                for (int mf = 0; mf < 2; mf++) {
                    mma16816(acc[mf][nf], Ah[mf], Bh);
                    mma16816(acc[mf][nf], Ah[mf], Bl);
                    mma16816(acc[mf][nf], Al[mf], Bh);
                }
            }
        }
        __syncthreads();
    }

    // --- epilogue: write fp32 to g_t (NCHW) ---
    #pragma unroll
    for (int mf = 0; mf < 2; mf++) {
        #pragma unroll
        for (int nf = 0; nf < 4; nf++) {
            int co = coBase + wm * 32 + mf * 16 + (lane >> 2);
            int y  = y0 + wn * 4 + nf;
            int x  = x0 + (lane & 3) * 2;
            size_t o = (((size_t)b * C + co) * S + y) * S + x;
            float2 lo; lo.x = acc[mf][nf][0]; lo.y = acc[mf][nf][1];
            float2 hi; hi.x = acc[mf][nf][2]; hi.y = acc[mf][nf][3];
            *(float2*)(g_t + o) = lo;
            *(float2*)(g_t + o + (size_t)8 * S * S) = hi;
        }
    }
}

// ---------------------------------------------------------------------------
// BN stats over (B, H, W) per channel -> fused scale/bias
// ---------------------------------------------------------------------------
__global__ void k_bnstats(const float* __restrict__ gamma,
                          const float* __restrict__ beta, int C, int S,
                          int useRmask) {
    if ((useRmask ? g_anyR : g_anyD) == 0) return;
    int c = blockIdx.x;
    int n = NB * S * S;
    float s = 0.0f, q = 0.0f;
    for (int i = threadIdx.x; i < n; i += 256) {
        int b = i / (S*S);
        int p = i - b * (S*S);
        float v = g_t[((size_t)b*C + c)*S*S + p];
        s += v; q += v*v;
    }
    __shared__ float ss[256], sq[256];
    ss[threadIdx.x] = s; sq[threadIdx.x] = q;
    __syncthreads();
    for (int o = 128; o > 0; o >>= 1) {
        if (threadIdx.x < o) {
            ss[threadIdx.x] += ss[threadIdx.x + o];
            sq[threadIdx.x] += sq[threadIdx.x + o];
        }
        __syncthreads();
    }
    if (threadIdx.x == 0) {
        float mean = ss[0] / (float)n;
        float var  = sq[0] / (float)n - mean*mean;
        float rstd = 1.0f / sqrtf(var + 1e-5f);
        float A = gamma[c] * rstd;
        g_bnA[c] = A;
        g_bnB[c] = beta[c] - mean * A;
    }
}

// ---------------------------------------------------------------------------
// Spatial attention: per-pixel channel mean/max (coalesced), 7x7 conv + sigmoid
// ---------------------------------------------------------------------------
__global__ void k_spstats(const float* __restrict__ mainp, int C, int S,
                          int useRmask) {
    if ((useRmask ? g_anyR : g_anyD) == 0) return;
    int b = blockIdx.y;
    int p = blockIdx.x * blockDim.x + threadIdx.x;
    if (p >= S*S) return;
    const float* base = mainp + (size_t)b*C*S*S + p;
    float m = 0.0f, mx = -3.402823466e38f;
    #pragma unroll 4
    for (int c = 0; c < C; c++) {
        float v = base[(size_t)c*S*S];
        m += v; mx = fmaxf(mx, v);
    }
    g_spmean[(size_t)b*S*S + p] = m / (float)C;
    g_spmax [(size_t)b*S*S + p] = mx;
}

__global__ void k_spconv(const float* __restrict__ saw, int S, int useRmask) {
    if ((useRmask ? g_anyR : g_anyD) == 0) return;
    __shared__ float sw_[196];
    int b = blockIdx.y, y = blockIdx.x, x = threadIdx.x;
    for (int i = x; i < 196; i += blockDim.x) sw_[i] = saw[i];
    __syncthreads();
    float step = 2.0f / (float)(S - 1);
    float acc = 0.0f;
    #pragma unroll
    for (int ky = 0; ky < 7; ky++) {
        int yy = y + ky - 3;
        if (yy < 0 || yy >= S) continue;
        #pragma unroll
        for (int kx = 0; kx < 7; kx++) {
            int xx = x + kx - 3;
            if (xx < 0 || xx >= S) continue;
            int widx = ky*7 + kx;
            acc += sw_[widx]        * g_spmean[(size_t)b*S*S + yy*S + xx];
            acc += sw_[49 + widx]   * g_spmax [(size_t)b*S*S + yy*S + xx];
            acc += sw_[98 + widx]   * (-1.0f + (float)xx * step);
            acc += sw_[147 + widx]  * (-1.0f + (float)yy * step);
        }
    }
    g_sw[(size_t)b*S*S + y*S + x] = 1.0f / (1.0f + expf(-acc));
}

// ---------------------------------------------------------------------------
// Channel attention: GAP -> ca1 -> relu -> ca2 -> sigmoid
// ---------------------------------------------------------------------------
__global__ void k_gap(const float* __restrict__ mainp, int C, int S,
                      int useRmask) {
    if ((useRmask ? g_anyR : g_anyD) == 0) return;
    int c = blockIdx.x, b = blockIdx.y;
    const float* p = mainp + ((size_t)b*C + c)*S*S;
    float s = 0.0f;
    for (int i = threadIdx.x; i < S*S; i += 128) s += p[i];
    __shared__ float sm[128];
    sm[threadIdx.x] = s;
    __syncthreads();
    for (int o = 64; o > 0; o >>= 1) {
        if (threadIdx.x < o) sm[threadIdx.x] += sm[threadIdx.x + o];
        __syncthreads();
    }
    if (threadIdx.x == 0) g_gap[b*C + c] = sm[0] / (float)(S*S);
}

__global__ void k_ca(const float* __restrict__ ca1, const float* __restrict__ ca2,
                     int C, int Rr, int useRmask) {
    if ((useRmask ? g_anyR : g_anyD) == 0) return;
    int b = blockIdx.x;
    __shared__ float sg[1024];
    __shared__ float sh[64];
    for (int c = threadIdx.x; c < C; c += 128) sg[c] = g_gap[b*C + c];
    __syncthreads();
    for (int rr = threadIdx.x; rr < Rr; rr += 128) {
        float h = 0.0f;
        for (int c = 0; c < C; c++) h += ca1[(size_t)rr*C + c] * sg[c];
        sh[rr] = fmaxf(h, 0.0f);
    }
    __syncthreads();
    for (int c = threadIdx.x; c < C; c += 128) {
        float v = 0.0f;
        for (int rr = 0; rr < Rr; rr++) v += ca2[(size_t)c*Rr + rr] * sh[rr];
        g_cw[b*C + c] = 1.0f / (1.0f + expf(-v));
    }
}

// ---------------------------------------------------------------------------
// Final blend: out = (inv==0) ? main : 2 * relu(A*t+B) * sw * cw
// ---------------------------------------------------------------------------
__global__ void k_final(const float* __restrict__ mainp, float* __restrict__ outp,
                        int C, int S, int step, int useRmask) {
    int idx = blockIdx.x * blockDim.x + threadIdx.x;
    int N = NB * C * S * S;
    if (idx >= N) return;
    int b   = idx / (C*S*S);
    int rem = idx - b * (C*S*S);
    int c   = rem / (S*S);
    int p   = rem - c * (S*S);
    int y = p / S, x = p - y * S;
    const float* maskp = useRmask ? g_maskR : g_maskD;
    float inv = maskp[((size_t)b*64 + y*step)*64 + x*step];
    float res;
    if (inv == 0.0f) {
        res = mainp[idx];
    } else {
        float tv = g_t[idx];
        float a  = fmaxf(g_bnA[c]*tv + g_bnB[c], 0.0f);
        res = ((a * g_sw[(size_t)b*S*S + p]) * g_cw[b*C + c]) * 2.0f;
    }
    outp[idx] = res;
}

// ---------------------------------------------------------------------------
// Host orchestration
// ---------------------------------------------------------------------------
struct LvlParams {
    const float *ft, *g, *b, *sa, *ca1, *ca2;
};

template<int C, int S>
static void run_dir(const float* mainp, const float* auxp, int useRmask,
                    float* outp, const LvlParams& P) {
    int S2 = S + 2;
    int nPad4 = NB * S2 * S2 * C / 8;
    k_zero_aux<<<(nPad4 + 255)/256, 256>>>(nPad4, useRmask);
    int S32 = (S + 31) / 32;
    k_cvtaux_pad<<<dim3(S32 * (C/32), S, NB), 256>>>(auxp, C, S, useRmask);
    cudaFuncSetAttribute(k_conv_mma<C, S>,
                         cudaFuncAttributeMaxDynamicSharedMemorySize,
                         CONV_SMEM_BYTES);
    dim3 cgrid((S/16)*(S/8), C/64, NB);
    k_conv_mma<C, S><<<cgrid, 256, CONV_SMEM_BYTES>>>(useRmask);
    k_bnstats<<<C, 256>>>(P.g, P.b, C, S, useRmask);
    k_spstats<<<dim3((S*S + 255)/256, NB), 256>>>(mainp, C, S, useRmask);
    k_spconv<<<dim3(S, NB), S>>>(P.sa, S, useRmask);
    k_gap<<<dim3(C, NB), 128>>>(mainp, C, S, useRmask);
    k_ca<<<NB, 128>>>(P.ca1, P.ca2, C, C/16, useRmask);
    int N = NB * C * S * S;
    k_final<<<(N + 255)/256, 256>>>(mainp, outp, C, S, 64/S, useRmask);
}

extern "C" void kernel_launch(void* const* d_in, const int* in_sizes, int n_in,
                              void* d_out, int out_size) {
    // metadata order follows setup_inputs() dict insertion order:
    // rgb_feat0, depth_feat0, rgb_feat1, depth_feat1, rgb_feat2, depth_feat2,
    // rgb_img, depth_img, then per level: ft_w, bn_g, bn_b, sa_w, ca1_w, ca2_w
    const float* rgbF[3] = {(const float*)d_in[0], (const float*)d_in[2], (const float*)d_in[4]};
    const float* depF[3] = {(const float*)d_in[1], (const float*)d_in[3], (const float*)d_in[5]};
    const float* rgb_img   = (const float*)d_in[6];
    const float* depth_img = (const float*)d_in[7];
    LvlParams P[3];
    for (int i = 0; i < 3; i++) {
        int base = 8 + i*6;
        P[i].ft  = (const float*)d_in[base + 0];
        P[i].g   = (const float*)d_in[base + 1];
        P[i].b   = (const float*)d_in[base + 2];
        P[i].sa  = (const float*)d_in[base + 3];
        P[i].ca1 = (const float*)d_in[base + 4];
        P[i].ca2 = (const float*)d_in[base + 5];
    }
    float* out = (float*)d_out;

    // masks
    int npix = NB * IMG * IMG;
    k_zeroflags<<<1, 1>>>();
    k_gray <<<(npix + 255)/256, 256>>>(rgb_img);
    k_lap  <<<(npix + 255)/256, 256>>>();
    k_flags<<<(NB*127*127 + 255)/256, 256>>>();
    k_masks<<<(NB*64*64 + 255)/256, 256>>>(depth_img);

    const size_t szR0 = (size_t)NB*256*64*64;   // 8388608
    const size_t szR1 = (size_t)NB*512*32*32;   // 4194304
    const size_t szR2 = (size_t)NB*1024*16*16;  // 2097152
    float* oR0 = out;
    float* oR1 = oR0 + szR0;
    float* oR2 = oR1 + szR1;
    float* oD0 = oR2 + szR2;
    float* oD1 = oD0 + szR0;
    float* oD2 = oD1 + szR1;

    // level 0
    k_cvtw<<<(9*256*256 + 255)/256, 256>>>(P[0].ft, 256);
    run_dir<256, 64>(rgbF[0], depF[0], 1, oR0, P[0]);
    run_dir<256, 64>(depF[0], rgbF[0], 0, oD0, P[0]);
    // level 1
    k_cvtw<<<(9*512*512 + 255)/256, 256>>>(P[1].ft, 512);
    run_dir<512, 32>(rgbF[1], depF[1], 1, oR1, P[1]);
    run_dir<512, 32>(depF[1], rgbF[1], 0, oD1, P[1]);
    // level 2
    k_cvtw<<<(9*1024*1024 + 255)/256, 256>>>(P[2].ft, 1024);
    run_dir<1024,16>(rgbF[2], depF[2], 1, oR2, P[2]);
    run_dir<1024,16>(depF[2], rgbF[2], 0, oD2, P[2]);
}

// round 11
// speedup vs baseline: 2.7285x; 1.2739x over previous
#include <cuda_runtime.h>
#include <cuda_fp16.h>
#include <math.h>
#include <stdint.h>

#define NB   8
#define IMG  512

// ---------------------------------------------------------------------------
// Scratch (static device globals — no allocations allowed)
// ---------------------------------------------------------------------------
__device__ float g_gray  [NB*IMG*IMG];
__device__ float g_lap   [NB*IMG*IMG];
__device__ float g_flags [NB*127*127];
__device__ float g_maskR [NB*64*64];
__device__ float g_maskD [NB*64*64];
__device__ float g_t     [NB*256*64*64];   // conv output scratch (max = level 0)
__device__ float g_spmean[NB*64*64];
__device__ float g_spmax [NB*64*64];
__device__ float g_sw    [NB*64*64];
__device__ float g_gap   [NB*1024];
__device__ float g_cw    [NB*1024];
__device__ float g_bnA   [1024];
__device__ float g_bnB   [1024];
__device__ int   g_anyR;
__device__ int   g_anyD;

// fp16 scratch: weights hi/lo [tap][co][ci]; aux activations single fp16,
// halo-padded NHWC [b][S+2][S+2][C] (max = level 0: 8*66*66*256)
__device__ __half g_wh  [9*1024*1024];
__device__ __half g_wl  [9*1024*1024];
__device__ __half g_auxh[8921088];

// ---------------------------------------------------------------------------
// MMA + cp.async helpers (legacy mma.sync path — tcgen05 not available:
// harness lowers via compute_100, which rejects all tcgen05/.cta_group ops)
// ---------------------------------------------------------------------------
__device__ __forceinline__ uint32_t smem_u32(const void* p) {
    return (uint32_t)__cvta_generic_to_shared(p);
}
__device__ __forceinline__ void ldsm4(uint32_t* r, uint32_t addr) {
    asm volatile("ldmatrix.sync.aligned.m8n8.x4.shared.b16 {%0,%1,%2,%3}, [%4];"
                 : "=r"(r[0]), "=r"(r[1]), "=r"(r[2]), "=r"(r[3]) : "r"(addr));
}
__device__ __forceinline__ void ldsm2(uint32_t* r, uint32_t addr) {
    asm volatile("ldmatrix.sync.aligned.m8n8.x2.shared.b16 {%0,%1}, [%2];"
                 : "=r"(r[0]), "=r"(r[1]) : "r"(addr));
}
__device__ __forceinline__ void mma16816h(float* c, const uint32_t* a, const uint32_t* b) {
    asm volatile("mma.sync.aligned.m16n8k16.row.col.f32.f16.f16.f32 "
                 "{%0,%1,%2,%3}, {%4,%5,%6,%7}, {%8,%9}, {%0,%1,%2,%3};"
                 : "+f"(c[0]), "+f"(c[1]), "+f"(c[2]), "+f"(c[3])
                 : "r"(a[0]), "r"(a[1]), "r"(a[2]), "r"(a[3]), "r"(b[0]), "r"(b[1]));
}
__device__ __forceinline__ void cpa16(uint32_t dst, const void* src) {
    asm volatile("cp.async.cg.shared.global [%0], [%1], 16;" :: "r"(dst), "l"(src));
}
__device__ __forceinline__ void cpa_commit() { asm volatile("cp.async.commit_group;"); }
__device__ __forceinline__ void cpa_wait0()  { asm volatile("cp.async.wait_group 0;"); }

// ---------------------------------------------------------------------------
// Stage A: blur mask from rgb image + depth mask
// ---------------------------------------------------------------------------
__global__ void k_zeroflags() { g_anyR = 0; g_anyD = 0; }

__global__ void k_gray(const float* __restrict__ rgb) {
    int idx = blockIdx.x * blockDim.x + threadIdx.x;
    if (idx >= NB*IMG*IMG) return;
    int b = idx / (IMG*IMG);
    int p = idx - b * (IMG*IMG);
    const float* base = rgb + (size_t)b * 3 * IMG * IMG;
    float g = 0.299f*base[p] + 0.587f*base[IMG*IMG + p] + 0.114f*base[2*IMG*IMG + p];
    g *= 255.0f;
    g = fminf(fmaxf(g, 0.0f), 255.0f);
    g_gray[idx] = g;
}

__global__ void k_lap() {
    int idx = blockIdx.x * blockDim.x + threadIdx.x;
    if (idx >= NB*IMG*IMG) return;
    int b = idx / (IMG*IMG);
    int p = idx - b * (IMG*IMG);
    int y = p / IMG, x = p - y * IMG;
    const float* g = g_gray + (size_t)b * IMG * IMG;
    float c = g[y*IMG + x];
    float u = (y > 0)       ? g[(y-1)*IMG + x] : 0.0f;
    float d = (y < IMG-1)   ? g[(y+1)*IMG + x] : 0.0f;
    float l = (x > 0)       ? g[y*IMG + x-1]   : 0.0f;
    float r = (x < IMG-1)   ? g[y*IMG + x+1]   : 0.0f;
    g_lap[idx] = u + d + l + r - 4.0f*c;
}

__global__ void k_flags() {
    int idx = blockIdx.x * blockDim.x + threadIdx.x;
    if (idx >= NB*127*127) return;
    int b = idx / (127*127);
    int rem = idx - b * (127*127);
    int i = rem / 127, j = rem - i * 127;
    const float* lp = g_lap + (size_t)b * IMG * IMG + (4*i)*IMG + 4*j;
    float s1 = 0.0f, s2 = 0.0f;
    #pragma unroll
    for (int dy = 0; dy < 8; dy++) {
        #pragma unroll
        for (int dx = 0; dx < 8; dx++) {
            float v = lp[dy*IMG + dx];
            s1 += v; s2 += v*v;
        }
    }
    float var = (s2 - s1*s1*(1.0f/64.0f)) * (1.0f/63.0f);
    g_flags[idx] = (var < 50.0f) ? 1.0f : 0.0f;
}

__global__ void k_masks(const float* __restrict__ depth) {
    int idx = blockIdx.x * blockDim.x + threadIdx.x;
    if (idx >= NB*64*64) return;
    int b = idx / (64*64);
    int rem = idx - b * (64*64);
    int k = rem / 64, l = rem - k * 64;
    float f = 0.0f;
    #pragma unroll
    for (int da = 0; da < 2; da++) {
        int a = 2*k - da;
        if (a < 0) continue;
        #pragma unroll
        for (int db = 0; db < 2; db++) {
            int bb = 2*l - db;
            if (bb < 0) continue;
            f = fmaxf(f, g_flags[((size_t)b*127 + a)*127 + bb]);
        }
    }
    g_maskR[idx] = f;
    float dv = depth[((size_t)b*3 + 2)*IMG*IMG + (8*k)*IMG + 8*l];
    float md = (dv <= 0.0f) ? 1.0f : 0.0f;
    g_maskD[idx] = md;
    if (f  > 0.0f) atomicOr(&g_anyR, 1);
    if (md > 0.0f) atomicOr(&g_anyD, 1);
}

// ---------------------------------------------------------------------------
// Conversion / layout kernels
// ---------------------------------------------------------------------------
// Weights fp32 -> fp16 hi + lo, [tap][co][ci]. Once per level.
__global__ void k_cvtw(const float* __restrict__ w, int C) {
    if (g_anyR == 0 && g_anyD == 0) return;
    int idx = blockIdx.x * blockDim.x + threadIdx.x;
    int n = 9 * C * C;
    if (idx >= n) return;
    int t   = idx / (C * C);
    int rem = idx - t * (C * C);
    int co  = rem / C;
    int ci  = rem - co * C;
    float v = w[((size_t)co * C + ci) * 9 + t];
    __half h = __float2half_rn(v);
    g_wh[idx] = h;
    g_wl[idx] = __float2half_rn(v - __half2float(h));
}

// Zero the padded NHWC aux array (guarantees halo zeros)
__global__ void k_zero_aux(int n4, int useRmask) {
    if ((useRmask ? g_anyR : g_anyD) == 0) return;
    int i = blockIdx.x * blockDim.x + threadIdx.x;
    if (i >= n4) return;
    uint4 z = {0, 0, 0, 0};
    ((uint4*)g_auxh)[i] = z;
}

// NCHW fp32 -> padded NHWC fp16, smem-tiled transpose.
__global__ void k_cvtaux_pad(const float* __restrict__ aux, int C, int S,
                             int useRmask) {
    if ((useRmask ? g_anyR : g_anyD) == 0) return;
    __shared__ float tile[32][33];
    int S32 = (S + 31) / 32;
    int xt = blockIdx.x % S32;
    int ct = blockIdx.x / S32;
    int y  = blockIdx.y;
    int b  = blockIdx.z;
    int tx = threadIdx.x & 31;
    int tg = threadIdx.x >> 5;
    int S2 = S + 2;
    for (int cc = tg; cc < 32; cc += 8) {
        int x = xt * 32 + tx, c = ct * 32 + cc;
        float v = 0.0f;
        if (x < S) v = aux[(((size_t)b * C + c) * S + y) * S + x];
        tile[cc][tx] = v;
    }
    __syncthreads();
    for (int xx = tg; xx < 32; xx += 8) {
        int x = xt * 32 + xx, c = ct * 32 + tx;
        if (x < S) {
            size_t o = (((size_t)b * S2 + y + 1) * S2 + x + 1) * C + c;
            g_auxh[o] = __float2half_rn(tile[tx][xx]);
        }
    }
}

// ---------------------------------------------------------------------------
// Tensor-core 3x3 conv (pad=1, cross-correlation), fp16 2-pass split:
//   out = Wh*B + Wl*B   (W = Wh+Wl exact to ~22 bits, B single fp16)
// CTA: 64 couts x 128 pixels (16y x 8x). 8 warps (2M x 4N).
// Single-buffered 64KB stage -> 2 CTAs/SM for fill/compute overlap.
// smem rows padded to 24 elems (48B) -> conflict-free ldmatrix.
// ---------------------------------------------------------------------------
#define A_ELEMS (9*64*24)            // 13824 fp16 per weight half
#define B_ELEMS (180*24)             // 4320 fp16
#define CONV_SMEM_BYTES ((2*A_ELEMS + B_ELEMS) * 2)   // 63936

template<int C, int S>
__global__ void __launch_bounds__(256, 2) k_conv_mma(int useRmask) {
    if ((useRmask ? g_anyR : g_anyD) == 0) return;

    extern __shared__ __align__(16) char smem_raw[];
    const uint32_t sm0 = smem_u32(smem_raw);
    const uint32_t sAh32 = sm0;
    const uint32_t sAl32 = sm0 + A_ELEMS * 2;
    const uint32_t sB32  = sm0 + 2 * A_ELEMS * 2;

    constexpr int S2 = S + 2;
    const int b      = blockIdx.z;
    const int coBase = blockIdx.y * 64;
    constexpr int XT = S / 8;
    const int y0 = (blockIdx.x / XT) * 16;
    const int x0 = (blockIdx.x % XT) * 8;

    const int tid  = threadIdx.x;
    const int lane = tid & 31;
    const int wid  = tid >> 5;
    const int wm   = wid & 1;       // co 32-block
    const int wn   = wid >> 1;      // pixel-row 4-block

    const __half* auxB = g_auxh + (size_t)b * S2 * S2 * C;

    // lane-dependent ldmatrix address components (element units)
    const int aM = ((lane >> 3) & 1) * 8 + (lane & 7);
    const int aK = (lane >> 4) * 8;
    const int lb = lane & 15;
    const int bRow = lb & 7;
    const int bK   = (lb >> 3) * 8;

    float acc[2][4][4];
    #pragma unroll
    for (int mf = 0; mf < 2; mf++)
        #pragma unroll
        for (int nf = 0; nf < 4; nf++)
            #pragma unroll
            for (int k = 0; k < 4; k++) acc[mf][nf][k] = 0.0f;

    constexpr int NCHUNK = C / 16;

    for (int k = 0; k < NCHUNK; k++) {
        const int ci0 = k * 16;
        // ---- fill A (weights hi+lo): 1152 16B-chunks per half ----
        for (int i = tid; i < 1152; i += 256) {
            int row = i >> 1, half = i & 1;
            int t = row >> 6, co = row & 63;
            size_t se = ((size_t)t * C + coBase + co) * C + ci0 + half * 8;
            uint32_t d = sm0 + (uint32_t)(row * 24 + half * 8) * 2;
            cpa16(d, g_wh + se);
            cpa16(d + A_ELEMS * 2, g_wl + se);
        }
        // ---- fill B (activations, single fp16): 360 16B-chunks ----
        for (int i = tid; i < 360; i += 256) {
            int pix = i >> 1, half = i & 1;
            int iy = pix / 10, ix = pix - iy * 10;
            size_t so = (((size_t)(y0 + iy)) * S2 + x0 + ix) * C + ci0 + half * 8;
            cpa16(sB32 + (uint32_t)(pix * 24 + half * 8) * 2, auxB + so);
        }
        cpa_commit();
        cpa_wait0();
        __syncthreads();

        for (int t = 0; t < 9; t++) {
            const int tty = t / 3, ttx = t - tty * 3;
            uint32_t Ah[2][4], Al[2][4];
            #pragma unroll
            for (int mf = 0; mf < 2; mf++) {
                int ea = (t * 64 + wm * 32 + mf * 16 + aM) * 24 + aK;
                ldsm4(Ah[mf], sAh32 + ea * 2);
                ldsm4(Al[mf], sAl32 + ea * 2);
            }
            #pragma unroll
            for (int nf = 0; nf < 4; nf++) {
                int eb = ((wn * 4 + nf + tty) * 10 + ttx + bRow) * 24 + bK;
                uint32_t Bf[2];
                ldsm2(Bf, sB32 + eb * 2);
                #pragma unroll
                for (int mf = 0; mf < 2; mf++) {
                    mma16816h(acc[mf][nf], Ah[mf], Bf);
                    mma16816h(acc[mf][nf], Al[mf], Bf);
                }
            }
        }
        __syncthreads();
    }

    // --- epilogue: write fp32 to g_t (NCHW) ---
    #pragma unroll
    for (int mf = 0; mf < 2; mf++) {
        #pragma unroll
        for (int nf = 0; nf < 4; nf++) {
            int co = coBase + wm * 32 + mf * 16 + (lane >> 2);
            int y  = y0 + wn * 4 + nf;
            int x  = x0 + (lane & 3) * 2;
            size_t o = (((size_t)b * C + co) * S + y) * S + x;
            float2 lo; lo.x = acc[mf][nf][0]; lo.y = acc[mf][nf][1];
            float2 hi; hi.x = acc[mf][nf][2]; hi.y = acc[mf][nf][3];
            *(float2*)(g_t + o) = lo;
            *(float2*)(g_t + o + (size_t)8 * S * S) = hi;
        }
    }
}

// ---------------------------------------------------------------------------
// BN stats over (B, H, W) per channel -> fused scale/bias
// ---------------------------------------------------------------------------
__global__ void k_bnstats(const float* __restrict__ gamma,
                          const float* __restrict__ beta, int C, int S,
                          int useRmask) {
    if ((useRmask ? g_anyR : g_anyD) == 0) return;
    int c = blockIdx.x;
    int n = NB * S * S;
    float s = 0.0f, q = 0.0f;
    for (int i = threadIdx.x; i < n; i += 256) {
        int b = i / (S*S);
        int p = i - b * (S*S);
        float v = g_t[((size_t)b*C + c)*S*S + p];
        s += v; q += v*v;
    }
    __shared__ float ss[256], sq[256];
    ss[threadIdx.x] = s; sq[threadIdx.x] = q;
    __syncthreads();
    for (int o = 128; o > 0; o >>= 1) {
        if (threadIdx.x < o) {
            ss[threadIdx.x] += ss[threadIdx.x + o];
            sq[threadIdx.x] += sq[threadIdx.x + o];
        }
        __syncthreads();
    }
    if (threadIdx.x == 0) {
        float mean = ss[0] / (float)n;
        float var  = sq[0] / (float)n - mean*mean;
        float rstd = 1.0f / sqrtf(var + 1e-5f);
        float A = gamma[c] * rstd;
        g_bnA[c] = A;
        g_bnB[c] = beta[c] - mean * A;
    }
}

// ---------------------------------------------------------------------------
// Spatial attention: per-pixel channel mean/max (coalesced), 7x7 conv + sigmoid
// ---------------------------------------------------------------------------
__global__ void k_spstats(const float* __restrict__ mainp, int C, int S,
                          int useRmask) {
    if ((useRmask ? g_anyR : g_anyD) == 0) return;
    int b = blockIdx.y;
    int p = blockIdx.x * blockDim.x + threadIdx.x;
    if (p >= S*S) return;
    const float* base = mainp + (size_t)b*C*S*S + p;
    float m = 0.0f, mx = -3.402823466e38f;
    #pragma unroll 4
    for (int c = 0; c < C; c++) {
        float v = base[(size_t)c*S*S];
        m += v; mx = fmaxf(mx, v);
    }
    g_spmean[(size_t)b*S*S + p] = m / (float)C;
    g_spmax [(size_t)b*S*S + p] = mx;
}

__global__ void k_spconv(const float* __restrict__ saw, int S, int useRmask) {
    if ((useRmask ? g_anyR : g_anyD) == 0) return;
    __shared__ float sw_[196];
    int b = blockIdx.y, y = blockIdx.x, x = threadIdx.x;
    for (int i = x; i < 196; i += blockDim.x) sw_[i] = saw[i];
    __syncthreads();
    float step = 2.0f / (float)(S - 1);
    float acc = 0.0f;
    #pragma unroll
    for (int ky = 0; ky < 7; ky++) {
        int yy = y + ky - 3;
        if (yy < 0 || yy >= S) continue;
        #pragma unroll
        for (int kx = 0; kx < 7; kx++) {
            int xx = x + kx - 3;
            if (xx < 0 || xx >= S) continue;
            int widx = ky*7 + kx;
            acc += sw_[widx]        * g_spmean[(size_t)b*S*S + yy*S + xx];
            acc += sw_[49 + widx]   * g_spmax [(size_t)b*S*S + yy*S + xx];
            acc += sw_[98 + widx]   * (-1.0f + (float)xx * step);
            acc += sw_[147 + widx]  * (-1.0f + (float)yy * step);
        }
    }
    g_sw[(size_t)b*S*S + y*S + x] = 1.0f / (1.0f + expf(-acc));
}

// ---------------------------------------------------------------------------
// Channel attention: GAP -> ca1 -> relu -> ca2 -> sigmoid
// ---------------------------------------------------------------------------
__global__ void k_gap(const float* __restrict__ mainp, int C, int S,
                      int useRmask) {
    if ((useRmask ? g_anyR : g_anyD) == 0) return;
    int c = blockIdx.x, b = blockIdx.y;
    const float* p = mainp + ((size_t)b*C + c)*S*S;
    float s = 0.0f;
    for (int i = threadIdx.x; i < S*S; i += 128) s += p[i];
    __shared__ float sm[128];
    sm[threadIdx.x] = s;
    __syncthreads();
    for (int o = 64; o > 0; o >>= 1) {
        if (threadIdx.x < o) sm[threadIdx.x] += sm[threadIdx.x + o];
        __syncthreads();
    }
    if (threadIdx.x == 0) g_gap[b*C + c] = sm[0] / (float)(S*S);
}

__global__ void k_ca(const float* __restrict__ ca1, const float* __restrict__ ca2,
                     int C, int Rr, int useRmask) {
    if ((useRmask ? g_anyR : g_anyD) == 0) return;
    int b = blockIdx.x;
    __shared__ float sg[1024];
    __shared__ float sh[64];
    for (int c = threadIdx.x; c < C; c += 128) sg[c] = g_gap[b*C + c];
    __syncthreads();
    for (int rr = threadIdx.x; rr < Rr; rr += 128) {
        float h = 0.0f;
        for (int c = 0; c < C; c++) h += ca1[(size_t)rr*C + c] * sg[c];
        sh[rr] = fmaxf(h, 0.0f);
    }
    __syncthreads();
    for (int c = threadIdx.x; c < C; c += 128) {
        float v = 0.0f;
        for (int rr = 0; rr < Rr; rr++) v += ca2[(size_t)c*Rr + rr] * sh[rr];
        g_cw[b*C + c] = 1.0f / (1.0f + expf(-v));
    }
}

// ---------------------------------------------------------------------------
// Final blend: out = (inv==0) ? main : 2 * relu(A*t+B) * sw * cw
// ---------------------------------------------------------------------------
__global__ void k_final(const float* __restrict__ mainp, float* __restrict__ outp,
                        int C, int S, int step, int useRmask) {
    int idx = blockIdx.x * blockDim.x + threadIdx.x;
    int N = NB * C * S * S;
    if (idx >= N) return;
    int b   = idx / (C*S*S);
    int rem = idx - b * (C*S*S);
    int c   = rem / (S*S);
    int p   = rem - c * (S*S);
    int y = p / S, x = p - y * S;
    const float* maskp = useRmask ? g_maskR : g_maskD;
    float inv = maskp[((size_t)b*64 + y*step)*64 + x*step];
    float res;
    if (inv == 0.0f) {
        res = mainp[idx];
    } else {
        float tv = g_t[idx];
        float a  = fmaxf(g_bnA[c]*tv + g_bnB[c], 0.0f);
        res = ((a * g_sw[(size_t)b*S*S + p]) * g_cw[b*C + c]) * 2.0f;
    }
    outp[idx] = res;
}

// ---------------------------------------------------------------------------
// Host orchestration
// ---------------------------------------------------------------------------
struct LvlParams {
    const float *ft, *g, *b, *sa, *ca1, *ca2;
};

template<int C, int S>
static void run_dir(const float* mainp, const float* auxp, int useRmask,
                    float* outp, const LvlParams& P) {
    int S2 = S + 2;
    int nPad4 = NB * S2 * S2 * C / 8;
    k_zero_aux<<<(nPad4 + 255)/256, 256>>>(nPad4, useRmask);
    int S32 = (S + 31) / 32;
    k_cvtaux_pad<<<dim3(S32 * (C/32), S, NB), 256>>>(auxp, C, S, useRmask);
    cudaFuncSetAttribute(k_conv_mma<C, S>,
                         cudaFuncAttributeMaxDynamicSharedMemorySize,
                         CONV_SMEM_BYTES);
    dim3 cgrid((S*S)/128, C/64, NB);
    k_conv_mma<C, S><<<cgrid, 256, CONV_SMEM_BYTES>>>(useRmask);
    k_bnstats<<<C, 256>>>(P.g, P.b, C, S, useRmask);
    k_spstats<<<dim3((S*S + 255)/256, NB), 256>>>(mainp, C, S, useRmask);
    k_spconv<<<dim3(S, NB), S>>>(P.sa, S, useRmask);
    k_gap<<<dim3(C, NB), 128>>>(mainp, C, S, useRmask);
    k_ca<<<NB, 128>>>(P.ca1, P.ca2, C, C/16, useRmask);
    int N = NB * C * S * S;
    k_final<<<(N + 255)/256, 256>>>(mainp, outp, C, S, 64/S, useRmask);
}

extern "C" void kernel_launch(void* const* d_in, const int* in_sizes, int n_in,
                              void* d_out, int out_size) {
    // metadata order follows setup_inputs() dict insertion order:
    // rgb_feat0, depth_feat0, rgb_feat1, depth_feat1, rgb_feat2, depth_feat2,
    // rgb_img, depth_img, then per level: ft_w, bn_g, bn_b, sa_w, ca1_w, ca2_w
    const float* rgbF[3] = {(const float*)d_in[0], (const float*)d_in[2], (const float*)d_in[4]};
    const float* depF[3] = {(const float*)d_in[1], (const float*)d_in[3], (const float*)d_in[5]};
    const float* rgb_img   = (const float*)d_in[6];
    const float* depth_img = (const float*)d_in[7];
    LvlParams P[3];
    for (int i = 0; i < 3; i++) {
        int base = 8 + i*6;
        P[i].ft  = (const float*)d_in[base + 0];
        P[i].g   = (const float*)d_in[base + 1];
        P[i].b   = (const float*)d_in[base + 2];
        P[i].sa  = (const float*)d_in[base + 3];
        P[i].ca1 = (const float*)d_in[base + 4];
        P[i].ca2 = (const float*)d_in[base + 5];
    }
    float* out = (float*)d_out;

    // masks
    int npix = NB * IMG * IMG;
    k_zeroflags<<<1, 1>>>();
    k_gray <<<(npix + 255)/256, 256>>>(rgb_img);
    k_lap  <<<(npix + 255)/256, 256>>>();
    k_flags<<<(NB*127*127 + 255)/256, 256>>>();
    k_masks<<<(NB*64*64 + 255)/256, 256>>>(depth_img);

    const size_t szR0 = (size_t)NB*256*64*64;
    const size_t szR1 = (size_t)NB*512*32*32;
    const size_t szR2 = (size_t)NB*1024*16*16;
    float* oR0 = out;
    float* oR1 = oR0 + szR0;
    float* oR2 = oR1 + szR1;
    float* oD0 = oR2 + szR2;
    float* oD1 = oD0 + szR0;
    float* oD2 = oD1 + szR1;

    // level 0
    k_cvtw<<<(9*256*256 + 255)/256, 256>>>(P[0].ft, 256);
    run_dir<256, 64>(rgbF[0], depF[0], 1, oR0, P[0]);
    run_dir<256, 64>(depF[0], rgbF[0], 0, oD0, P[0]);
    // level 1
    k_cvtw<<<(9*512*512 + 255)/256, 256>>>(P[1].ft, 512);
    run_dir<512, 32>(rgbF[1], depF[1], 1, oR1, P[1]);
    run_dir<512, 32>(depF[1], rgbF[1], 0, oD1, P[1]);
    // level 2
    k_cvtw<<<(9*1024*1024 + 255)/256, 256>>>(P[2].ft, 1024);
    run_dir<1024,16>(rgbF[2], depF[2], 1, oR2, P[2]);
    run_dir<1024,16>(depF[2], rgbF[2], 0, oD2, P[2]);
}

// round 12
// speedup vs baseline: 3.5109x; 1.2868x over previous
#include <cuda_runtime.h>
#include <cuda_fp16.h>
#include <math.h>
#include <stdint.h>

#define NB   8
#define IMG  512

// ---------------------------------------------------------------------------
// Scratch (static device globals — no allocations allowed)
// ---------------------------------------------------------------------------
__device__ float g_gray  [NB*IMG*IMG];
__device__ float g_lap   [NB*IMG*IMG];
__device__ float g_flags [NB*127*127];
__device__ float g_maskR [NB*64*64];
__device__ float g_maskD [NB*64*64];
__device__ float g_t     [NB*256*64*64];   // conv output scratch (max = level 0)
__device__ float g_spmean[NB*64*64];
__device__ float g_spmax [NB*64*64];
__device__ float g_sw    [NB*64*64];
__device__ float g_gap   [NB*1024];
__device__ float g_cw    [NB*1024];
__device__ float g_bnA   [1024];
__device__ float g_bnB   [1024];
__device__ int   g_anyR;
__device__ int   g_anyD;

// fp16 scratch: weights [tap][co][ci]; aux activations fp16,
// halo-padded NHWC [b][S+2][S+2][C] (max = level 0: 8*66*66*256)
__device__ __half g_wh  [9*1024*1024];
__device__ __half g_auxh[8921088];

// ---------------------------------------------------------------------------
// MMA + cp.async helpers (legacy mma.sync path — tcgen05 not available:
// harness lowers via compute_100, which rejects all tcgen05/.cta_group ops)
// ---------------------------------------------------------------------------
__device__ __forceinline__ uint32_t smem_u32(const void* p) {
    return (uint32_t)__cvta_generic_to_shared(p);
}
__device__ __forceinline__ void ldsm4(uint32_t* r, uint32_t addr) {
    asm volatile("ldmatrix.sync.aligned.m8n8.x4.shared.b16 {%0,%1,%2,%3}, [%4];"
                 : "=r"(r[0]), "=r"(r[1]), "=r"(r[2]), "=r"(r[3]) : "r"(addr));
}
__device__ __forceinline__ void ldsm2(uint32_t* r, uint32_t addr) {
    asm volatile("ldmatrix.sync.aligned.m8n8.x2.shared.b16 {%0,%1}, [%2];"
                 : "=r"(r[0]), "=r"(r[1]) : "r"(addr));
}
__device__ __forceinline__ void mma16816h(float* c, const uint32_t* a, const uint32_t* b) {
    asm volatile("mma.sync.aligned.m16n8k16.row.col.f32.f16.f16.f32 "
                 "{%0,%1,%2,%3}, {%4,%5,%6,%7}, {%8,%9}, {%0,%1,%2,%3};"
                 : "+f"(c[0]), "+f"(c[1]), "+f"(c[2]), "+f"(c[3])
                 : "r"(a[0]), "r"(a[1]), "r"(a[2]), "r"(a[3]), "r"(b[0]), "r"(b[1]));
}
__device__ __forceinline__ void cpa16(uint32_t dst, const void* src) {
    asm volatile("cp.async.cg.shared.global [%0], [%1], 16;" :: "r"(dst), "l"(src));
}
__device__ __forceinline__ void cpa_commit() { asm volatile("cp.async.commit_group;"); }
__device__ __forceinline__ void cpa_wait0()  { asm volatile("cp.async.wait_group 0;"); }

// ---------------------------------------------------------------------------
// Stage A: blur mask from rgb image + depth mask
// ---------------------------------------------------------------------------
__global__ void k_zeroflags() { g_anyR = 0; g_anyD = 0; }

__global__ void k_gray(const float* __restrict__ rgb) {
    int idx = blockIdx.x * blockDim.x + threadIdx.x;
    if (idx >= NB*IMG*IMG) return;
    int b = idx / (IMG*IMG);
    int p = idx - b * (IMG*IMG);
    const float* base = rgb + (size_t)b * 3 * IMG * IMG;
    float g = 0.299f*base[p] + 0.587f*base[IMG*IMG + p] + 0.114f*base[2*IMG*IMG + p];
    g *= 255.0f;
    g = fminf(fmaxf(g, 0.0f), 255.0f);
    g_gray[idx] = g;
}

__global__ void k_lap() {
    int idx = blockIdx.x * blockDim.x + threadIdx.x;
    if (idx >= NB*IMG*IMG) return;
    int b = idx / (IMG*IMG);
    int p = idx - b * (IMG*IMG);
    int y = p / IMG, x = p - y * IMG;
    const float* g = g_gray + (size_t)b * IMG * IMG;
    float c = g[y*IMG + x];
    float u = (y > 0)       ? g[(y-1)*IMG + x] : 0.0f;
    float d = (y < IMG-1)   ? g[(y+1)*IMG + x] : 0.0f;
    float l = (x > 0)       ? g[y*IMG + x-1]   : 0.0f;
    float r = (x < IMG-1)   ? g[y*IMG + x+1]   : 0.0f;
    g_lap[idx] = u + d + l + r - 4.0f*c;
}

__global__ void k_flags() {
    int idx = blockIdx.x * blockDim.x + threadIdx.x;
    if (idx >= NB*127*127) return;
    int b = idx / (127*127);
    int rem = idx - b * (127*127);
    int i = rem / 127, j = rem - i * 127;
    const float* lp = g_lap + (size_t)b * IMG * IMG + (4*i)*IMG + 4*j;
    float s1 = 0.0f, s2 = 0.0f;
    #pragma unroll
    for (int dy = 0; dy < 8; dy++) {
        #pragma unroll
        for (int dx = 0; dx < 8; dx++) {
            float v = lp[dy*IMG + dx];
            s1 += v; s2 += v*v;
        }
    }
    float var = (s2 - s1*s1*(1.0f/64.0f)) * (1.0f/63.0f);
    g_flags[idx] = (var < 50.0f) ? 1.0f : 0.0f;
}

__global__ void k_masks(const float* __restrict__ depth) {
    int idx = blockIdx.x * blockDim.x + threadIdx.x;
    if (idx >= NB*64*64) return;
    int b = idx / (64*64);
    int rem = idx - b * (64*64);
    int k = rem / 64, l = rem - k * 64;
    float f = 0.0f;
    #pragma unroll
    for (int da = 0; da < 2; da++) {
        int a = 2*k - da;
        if (a < 0) continue;
        #pragma unroll
        for (int db = 0; db < 2; db++) {
            int bb = 2*l - db;
            if (bb < 0) continue;
            f = fmaxf(f, g_flags[((size_t)b*127 + a)*127 + bb]);
        }
    }
    g_maskR[idx] = f;
    float dv = depth[((size_t)b*3 + 2)*IMG*IMG + (8*k)*IMG + 8*l];
    float md = (dv <= 0.0f) ? 1.0f : 0.0f;
    g_maskD[idx] = md;
    if (f  > 0.0f) atomicOr(&g_anyR, 1);
    if (md > 0.0f) atomicOr(&g_anyD, 1);
}

// ---------------------------------------------------------------------------
// Conversion / layout kernels
// ---------------------------------------------------------------------------
// Weights fp32 -> fp16, [tap][co][ci]. Once per level.
__global__ void k_cvtw(const float* __restrict__ w, int C) {
    if (g_anyR == 0 && g_anyD == 0) return;
    int idx = blockIdx.x * blockDim.x + threadIdx.x;
    int n = 9 * C * C;
    if (idx >= n) return;
    int t   = idx / (C * C);
    int rem = idx - t * (C * C);
    int co  = rem / C;
    int ci  = rem - co * C;
    g_wh[idx] = __float2half_rn(w[((size_t)co * C + ci) * 9 + t]);
}

// Zero the padded NHWC aux array (guarantees halo zeros)
__global__ void k_zero_aux(int n4, int useRmask) {
    if ((useRmask ? g_anyR : g_anyD) == 0) return;
    int i = blockIdx.x * blockDim.x + threadIdx.x;
    if (i >= n4) return;
    uint4 z = {0, 0, 0, 0};
    ((uint4*)g_auxh)[i] = z;
}

// NCHW fp32 -> padded NHWC fp16, smem-tiled transpose.
__global__ void k_cvtaux_pad(const float* __restrict__ aux, int C, int S,
                             int useRmask) {
    if ((useRmask ? g_anyR : g_anyD) == 0) return;
    __shared__ float tile[32][33];
    int S32 = (S + 31) / 32;
    int xt = blockIdx.x % S32;
    int ct = blockIdx.x / S32;
    int y  = blockIdx.y;
    int b  = blockIdx.z;
    int tx = threadIdx.x & 31;
    int tg = threadIdx.x >> 5;
    int S2 = S + 2;
    for (int cc = tg; cc < 32; cc += 8) {
        int x = xt * 32 + tx, c = ct * 32 + cc;
        float v = 0.0f;
        if (x < S) v = aux[(((size_t)b * C + c) * S + y) * S + x];
        tile[cc][tx] = v;
    }
    __syncthreads();
    for (int xx = tg; xx < 32; xx += 8) {
        int x = xt * 32 + xx, c = ct * 32 + tx;
        if (x < S) {
            size_t o = (((size_t)b * S2 + y + 1) * S2 + x + 1) * C + c;
            g_auxh[o] = __float2half_rn(tile[tx][xx]);
        }
    }
}

// ---------------------------------------------------------------------------
// Tensor-core 3x3 conv (pad=1, cross-correlation), single-pass fp16.
// CTA: 64 couts x 128 pixels (16y x 8x). 8 warps (2M x 4N).
// Single-buffered 36KB stage, 2 CTAs/SM.
// smem rows padded to 24 elems (48B) -> conflict-free ldmatrix.
// ---------------------------------------------------------------------------
#define A_ELEMS (9*64*24)            // 13824 fp16
#define B_ELEMS (180*24)             // 4320 fp16
#define CONV_SMEM_BYTES ((A_ELEMS + B_ELEMS) * 2)   // 36288

template<int C, int S>
__global__ void __launch_bounds__(256, 2) k_conv_mma(int useRmask) {
    if ((useRmask ? g_anyR : g_anyD) == 0) return;

    extern __shared__ __align__(16) char smem_raw[];
    const uint32_t sm0 = smem_u32(smem_raw);
    const uint32_t sA32 = sm0;
    const uint32_t sB32 = sm0 + A_ELEMS * 2;

    constexpr int S2 = S + 2;
    const int b      = blockIdx.z;
    const int coBase = blockIdx.y * 64;
    constexpr int XT = S / 8;
    const int y0 = (blockIdx.x / XT) * 16;
    const int x0 = (blockIdx.x % XT) * 8;

    const int tid  = threadIdx.x;
    const int lane = tid & 31;
    const int wid  = tid >> 5;
    const int wm   = wid & 1;       // co 32-block
    const int wn   = wid >> 1;      // pixel-row 4-block

    const __half* auxB = g_auxh + (size_t)b * S2 * S2 * C;

    // lane-dependent ldmatrix address components (element units)
    const int aM = ((lane >> 3) & 1) * 8 + (lane & 7);
    const int aK = (lane >> 4) * 8;
    const int lb = lane & 15;
    const int bRow = lb & 7;
    const int bK   = (lb >> 3) * 8;

    float acc[2][4][4];
    #pragma unroll
    for (int mf = 0; mf < 2; mf++)
        #pragma unroll
        for (int nf = 0; nf < 4; nf++)
            #pragma unroll
            for (int k = 0; k < 4; k++) acc[mf][nf][k] = 0.0f;

    constexpr int NCHUNK = C / 16;

    for (int k = 0; k < NCHUNK; k++) {
        const int ci0 = k * 16;
        // ---- fill A (weights): 1152 16B-chunks ----
        for (int i = tid; i < 1152; i += 256) {
            int row = i >> 1, half = i & 1;
            int t = row >> 6, co = row & 63;
            size_t se = ((size_t)t * C + coBase + co) * C + ci0 + half * 8;
            cpa16(sA32 + (uint32_t)(row * 24 + half * 8) * 2, g_wh + se);
        }
        // ---- fill B (activations): 360 16B-chunks ----
        for (int i = tid; i < 360; i += 256) {
            int pix = i >> 1, half = i & 1;
            int iy = pix / 10, ix = pix - iy * 10;
            size_t so = (((size_t)(y0 + iy)) * S2 + x0 + ix) * C + ci0 + half * 8;
            cpa16(sB32 + (uint32_t)(pix * 24 + half * 8) * 2, auxB + so);
        }
        cpa_commit();
        cpa_wait0();
        __syncthreads();

        for (int t = 0; t < 9; t++) {
            const int tty = t / 3, ttx = t - tty * 3;
            uint32_t Af[2][4];
            #pragma unroll
            for (int mf = 0; mf < 2; mf++) {
                int ea = (t * 64 + wm * 32 + mf * 16 + aM) * 24 + aK;
                ldsm4(Af[mf], sA32 + ea * 2);
            }
            #pragma unroll
            for (int nf = 0; nf < 4; nf++) {
                int eb = ((wn * 4 + nf + tty) * 10 + ttx + bRow) * 24 + bK;
                uint32_t Bf[2];
                ldsm2(Bf, sB32 + eb * 2);
                #pragma unroll
                for (int mf = 0; mf < 2; mf++)
                    mma16816h(acc[mf][nf], Af[mf], Bf);
            }
        }
        __syncthreads();
    }

    // --- epilogue: write fp32 to g_t (NCHW) ---
    #pragma unroll
    for (int mf = 0; mf < 2; mf++) {
        #pragma unroll
        for (int nf = 0; nf < 4; nf++) {
            int co = coBase + wm * 32 + mf * 16 + (lane >> 2);
            int y  = y0 + wn * 4 + nf;
            int x  = x0 + (lane & 3) * 2;
            size_t o = (((size_t)b * C + co) * S + y) * S + x;
            float2 lo; lo.x = acc[mf][nf][0]; lo.y = acc[mf][nf][1];
            float2 hi; hi.x = acc[mf][nf][2]; hi.y = acc[mf][nf][3];
            *(float2*)(g_t + o) = lo;
            *(float2*)(g_t + o + (size_t)8 * S * S) = hi;
        }
    }
}

// ---------------------------------------------------------------------------
// BN stats over (B, H, W) per channel -> fused scale/bias
// ---------------------------------------------------------------------------
__global__ void k_bnstats(const float* __restrict__ gamma,
                          const float* __restrict__ beta, int C, int S,
                          int useRmask) {
    if ((useRmask ? g_anyR : g_anyD) == 0) return;
    int c = blockIdx.x;
    int n = NB * S * S;
    float s = 0.0f, q = 0.0f;
    for (int i = threadIdx.x; i < n; i += 256) {
        int b = i / (S*S);
        int p = i - b * (S*S);
        float v = g_t[((size_t)b*C + c)*S*S + p];
        s += v; q += v*v;
    }
    __shared__ float ss[256], sq[256];
    ss[threadIdx.x] = s; sq[threadIdx.x] = q;
    __syncthreads();
    for (int o = 128; o > 0; o >>= 1) {
        if (threadIdx.x < o) {
            ss[threadIdx.x] += ss[threadIdx.x + o];
            sq[threadIdx.x] += sq[threadIdx.x + o];
        }
        __syncthreads();
    }
    if (threadIdx.x == 0) {
        float mean = ss[0] / (float)n;
        float var  = sq[0] / (float)n - mean*mean;
        float rstd = 1.0f / sqrtf(var + 1e-5f);
        float A = gamma[c] * rstd;
        g_bnA[c] = A;
        g_bnB[c] = beta[c] - mean * A;
    }
}

// ---------------------------------------------------------------------------
// Spatial attention: per-pixel channel mean/max (coalesced), 7x7 conv + sigmoid
// ---------------------------------------------------------------------------
__global__ void k_spstats(const float* __restrict__ mainp, int C, int S,
                          int useRmask) {
    if ((useRmask ? g_anyR : g_anyD) == 0) return;
    int b = blockIdx.y;
    int p = blockIdx.x * blockDim.x + threadIdx.x;
    if (p >= S*S) return;
    const float* base = mainp + (size_t)b*C*S*S + p;
    float m = 0.0f, mx = -3.402823466e38f;
    #pragma unroll 4
    for (int c = 0; c < C; c++) {
        float v = base[(size_t)c*S*S];
        m += v; mx = fmaxf(mx, v);
    }
    g_spmean[(size_t)b*S*S + p] = m / (float)C;
    g_spmax [(size_t)b*S*S + p] = mx;
}

__global__ void k_spconv(const float* __restrict__ saw, int S, int useRmask) {
    if ((useRmask ? g_anyR : g_anyD) == 0) return;
    __shared__ float sw_[196];
    int b = blockIdx.y, y = blockIdx.x, x = threadIdx.x;
    for (int i = x; i < 196; i += blockDim.x) sw_[i] = saw[i];
    __syncthreads();
    float step = 2.0f / (float)(S - 1);
    float acc = 0.0f;
    #pragma unroll
    for (int ky = 0; ky < 7; ky++) {
        int yy = y + ky - 3;
        if (yy < 0 || yy >= S) continue;
        #pragma unroll
        for (int kx = 0; kx < 7; kx++) {
            int xx = x + kx - 3;
            if (xx < 0 || xx >= S) continue;
            int widx = ky*7 + kx;
            acc += sw_[widx]        * g_spmean[(size_t)b*S*S + yy*S + xx];
            acc += sw_[49 + widx]   * g_spmax [(size_t)b*S*S + yy*S + xx];
            acc += sw_[98 + widx]   * (-1.0f + (float)xx * step);
            acc += sw_[147 + widx]  * (-1.0f + (float)yy * step);
        }
    }
    g_sw[(size_t)b*S*S + y*S + x] = 1.0f / (1.0f + expf(-acc));
}

// ---------------------------------------------------------------------------
// Channel attention: GAP -> ca1 -> relu -> ca2 -> sigmoid
// ---------------------------------------------------------------------------
__global__ void k_gap(const float* __restrict__ mainp, int C, int S,
                      int useRmask) {
    if ((useRmask ? g_anyR : g_anyD) == 0) return;
    int c = blockIdx.x, b = blockIdx.y;
    const float* p = mainp + ((size_t)b*C + c)*S*S;
    float s = 0.0f;
    for (int i = threadIdx.x; i < S*S; i += 128) s += p[i];
    __shared__ float sm[128];
    sm[threadIdx.x] = s;
    __syncthreads();
    for (int o = 64; o > 0; o >>= 1) {
        if (threadIdx.x < o) sm[threadIdx.x] += sm[threadIdx.x + o];
        __syncthreads();
    }
    if (threadIdx.x == 0) g_gap[b*C + c] = sm[0] / (float)(S*S);
}

__global__ void k_ca(const float* __restrict__ ca1, const float* __restrict__ ca2,
                     int C, int Rr, int useRmask) {
    if ((useRmask ? g_anyR : g_anyD) == 0) return;
    int b = blockIdx.x;
    __shared__ float sg[1024];
    __shared__ float sh[64];
    for (int c = threadIdx.x; c < C; c += 128) sg[c] = g_gap[b*C + c];
    __syncthreads();
    for (int rr = threadIdx.x; rr < Rr; rr += 128) {
        float h = 0.0f;
        for (int c = 0; c < C; c++) h += ca1[(size_t)rr*C + c] * sg[c];
        sh[rr] = fmaxf(h, 0.0f);
    }
    __syncthreads();
    for (int c = threadIdx.x; c < C; c += 128) {
        float v = 0.0f;
        for (int rr = 0; rr < Rr; rr++) v += ca2[(size_t)c*Rr + rr] * sh[rr];
        g_cw[b*C + c] = 1.0f / (1.0f + expf(-v));
    }
}

// ---------------------------------------------------------------------------
// Final blend: out = (inv==0) ? main : 2 * relu(A*t+B) * sw * cw
// ---------------------------------------------------------------------------
__global__ void k_final(const float* __restrict__ mainp, float* __restrict__ outp,
                        int C, int S, int step, int useRmask) {
    int idx = blockIdx.x * blockDim.x + threadIdx.x;
    int N = NB * C * S * S;
    if (idx >= N) return;
    int b   = idx / (C*S*S);
    int rem = idx - b * (C*S*S);
    int c   = rem / (S*S);
    int p   = rem - c * (S*S);
    int y = p / S, x = p - y * S;
    const float* maskp = useRmask ? g_maskR : g_maskD;
    float inv = maskp[((size_t)b*64 + y*step)*64 + x*step];
    float res;
    if (inv == 0.0f) {
        res = mainp[idx];
    } else {
        float tv = g_t[idx];
        float a  = fmaxf(g_bnA[c]*tv + g_bnB[c], 0.0f);
        res = ((a * g_sw[(size_t)b*S*S + p]) * g_cw[b*C + c]) * 2.0f;
    }
    outp[idx] = res;
}

// ---------------------------------------------------------------------------
// Host orchestration
// ---------------------------------------------------------------------------
struct LvlParams {
    const float *ft, *g, *b, *sa, *ca1, *ca2;
};

template<int C, int S>
static void run_dir(const float* mainp, const float* auxp, int useRmask,
                    float* outp, const LvlParams& P) {
    int S2 = S + 2;
    int nPad4 = NB * S2 * S2 * C / 8;
    k_zero_aux<<<(nPad4 + 255)/256, 256>>>(nPad4, useRmask);
    int S32 = (S + 31) / 32;
    k_cvtaux_pad<<<dim3(S32 * (C/32), S, NB), 256>>>(auxp, C, S, useRmask);
    cudaFuncSetAttribute(k_conv_mma<C, S>,
                         cudaFuncAttributeMaxDynamicSharedMemorySize,
                         CONV_SMEM_BYTES);
    dim3 cgrid((S*S)/128, C/64, NB);
    k_conv_mma<C, S><<<cgrid, 256, CONV_SMEM_BYTES>>>(useRmask);
    k_bnstats<<<C, 256>>>(P.g, P.b, C, S, useRmask);
    k_spstats<<<dim3((S*S + 255)/256, NB), 256>>>(mainp, C, S, useRmask);
    k_spconv<<<dim3(S, NB), S>>>(P.sa, S, useRmask);
    k_gap<<<dim3(C, NB), 128>>>(mainp, C, S, useRmask);
    k_ca<<<NB, 128>>>(P.ca1, P.ca2, C, C/16, useRmask);
    int N = NB * C * S * S;
    k_final<<<(N + 255)/256, 256>>>(mainp, outp, C, S, 64/S, useRmask);
}

extern "C" void kernel_launch(void* const* d_in, const int* in_sizes, int n_in,
                              void* d_out, int out_size) {
    // metadata order follows setup_inputs() dict insertion order:
    // rgb_feat0, depth_feat0, rgb_feat1, depth_feat1, rgb_feat2, depth_feat2,
    // rgb_img, depth_img, then per level: ft_w, bn_g, bn_b, sa_w, ca1_w, ca2_w
    const float* rgbF[3] = {(const float*)d_in[0], (const float*)d_in[2], (const float*)d_in[4]};
    const float* depF[3] = {(const float*)d_in[1], (const float*)d_in[3], (const float*)d_in[5]};
    const float* rgb_img   = (const float*)d_in[6];
    const float* depth_img = (const float*)d_in[7];
    LvlParams P[3];
    for (int i = 0; i < 3; i++) {
        int base = 8 + i*6;
        P[i].ft  = (const float*)d_in[base + 0];
        P[i].g   = (const float*)d_in[base + 1];
        P[i].b   = (const float*)d_in[base + 2];
        P[i].sa  = (const float*)d_in[base + 3];
        P[i].ca1 = (const float*)d_in[base + 4];
        P[i].ca2 = (const float*)d_in[base + 5];
    }
    float* out = (float*)d_out;

    // masks
    int npix = NB * IMG * IMG;
    k_zeroflags<<<1, 1>>>();
    k_gray <<<(npix + 255)/256, 256>>>(rgb_img);
    k_lap  <<<(npix + 255)/256, 256>>>();
    k_flags<<<(NB*127*127 + 255)/256, 256>>>();
    k_masks<<<(NB*64*64 + 255)/256, 256>>>(depth_img);

    const size_t szR0 = (size_t)NB*256*64*64;
    const size_t szR1 = (size_t)NB*512*32*32;
    const size_t szR2 = (size_t)NB*1024*16*16;
    float* oR0 = out;
    float* oR1 = oR0 + szR0;
    float* oR2 = oR1 + szR1;
    float* oD0 = oR2 + szR2;
    float* oD1 = oD0 + szR0;
    float* oD2 = oD1 + szR1;

    // level 0
    k_cvtw<<<(9*256*256 + 255)/256, 256>>>(P[0].ft, 256);
    run_dir<256, 64>(rgbF[0], depF[0], 1, oR0, P[0]);
    run_dir<256, 64>(depF[0], rgbF[0], 0, oD0, P[0]);
    // level 1
    k_cvtw<<<(9*512*512 + 255)/256, 256>>>(P[1].ft, 512);
    run_dir<512, 32>(rgbF[1], depF[1], 1, oR1, P[1]);
    run_dir<512, 32>(depF[1], rgbF[1], 0, oD1, P[1]);
    // level 2
    k_cvtw<<<(9*1024*1024 + 255)/256, 256>>>(P[2].ft, 1024);
    run_dir<1024,16>(rgbF[2], depF[2], 1, oR2, P[2]);
    run_dir<1024,16>(depF[2], rgbF[2], 0, oD2, P[2]);
}

// round 13
// speedup vs baseline: 3.5152x; 1.0012x over previous
#include <cuda_runtime.h>
#include <cuda_fp16.h>
#include <math.h>
#include <stdint.h>

#define NB   8
#define IMG  512

// ---------------------------------------------------------------------------
// Scratch (static device globals — no allocations allowed)
// ---------------------------------------------------------------------------
__device__ float g_gray  [NB*IMG*IMG];
__device__ float g_lap   [NB*IMG*IMG];
__device__ float g_flags [NB*127*127];
__device__ float g_maskR [NB*64*64];
__device__ float g_maskD [NB*64*64];
__device__ float g_t     [NB*256*64*64];   // conv output scratch (max = level 0)
__device__ float g_spmean[NB*64*64];
__device__ float g_spmax [NB*64*64];
__device__ float g_sw    [NB*64*64];
__device__ float g_gap   [NB*1024];
__device__ float g_cw    [NB*1024];
__device__ float g_bnA   [1024];
__device__ float g_bnB   [1024];
__device__ int   g_anyR;
__device__ int   g_anyD;

// fp16 scratch: weights [tap][co][ci]; aux activations fp16,
// halo-padded NHWC [b][S+2][S+2][C] (max = level 0: 8*66*66*256)
__device__ __half g_wh  [9*1024*1024];
__device__ __half g_auxh[8921088];

// ---------------------------------------------------------------------------
// MMA + cp.async helpers (legacy mma.sync path — tcgen05 not available:
// harness lowers via compute_100, which rejects all tcgen05/.cta_group ops)
// ---------------------------------------------------------------------------
__device__ __forceinline__ uint32_t smem_u32(const void* p) {
    return (uint32_t)__cvta_generic_to_shared(p);
}
__device__ __forceinline__ void ldsm4(uint32_t* r, uint32_t addr) {
    asm volatile("ldmatrix.sync.aligned.m8n8.x4.shared.b16 {%0,%1,%2,%3}, [%4];"
                 : "=r"(r[0]), "=r"(r[1]), "=r"(r[2]), "=r"(r[3]) : "r"(addr));
}
__device__ __forceinline__ void ldsm2(uint32_t* r, uint32_t addr) {
    asm volatile("ldmatrix.sync.aligned.m8n8.x2.shared.b16 {%0,%1}, [%2];"
                 : "=r"(r[0]), "=r"(r[1]) : "r"(addr));
}
__device__ __forceinline__ void mma16816h(float* c, const uint32_t* a, const uint32_t* b) {
    asm volatile("mma.sync.aligned.m16n8k16.row.col.f32.f16.f16.f32 "
                 "{%0,%1,%2,%3}, {%4,%5,%6,%7}, {%8,%9}, {%0,%1,%2,%3};"
                 : "+f"(c[0]), "+f"(c[1]), "+f"(c[2]), "+f"(c[3])
                 : "r"(a[0]), "r"(a[1]), "r"(a[2]), "r"(a[3]), "r"(b[0]), "r"(b[1]));
}
__device__ __forceinline__ void cpa16(uint32_t dst, const void* src) {
    asm volatile("cp.async.cg.shared.global [%0], [%1], 16;" :: "r"(dst), "l"(src));
}
__device__ __forceinline__ void cpa_commit() { asm volatile("cp.async.commit_group;"); }
__device__ __forceinline__ void cpa_wait1()  { asm volatile("cp.async.wait_group 1;"); }
__device__ __forceinline__ void cpa_wait0()  { asm volatile("cp.async.wait_group 0;"); }

// ---------------------------------------------------------------------------
// Stage A: blur mask from rgb image + depth mask
// ---------------------------------------------------------------------------
__global__ void k_zeroflags() { g_anyR = 0; g_anyD = 0; }

__global__ void k_gray(const float* __restrict__ rgb) {
    int idx = blockIdx.x * blockDim.x + threadIdx.x;
    if (idx >= NB*IMG*IMG) return;
    int b = idx / (IMG*IMG);
    int p = idx - b * (IMG*IMG);
    const float* base = rgb + (size_t)b * 3 * IMG * IMG;
    float g = 0.299f*base[p] + 0.587f*base[IMG*IMG + p] + 0.114f*base[2*IMG*IMG + p];
    g *= 255.0f;
    g = fminf(fmaxf(g, 0.0f), 255.0f);
    g_gray[idx] = g;
}

__global__ void k_lap() {
    int idx = blockIdx.x * blockDim.x + threadIdx.x;
    if (idx >= NB*IMG*IMG) return;
    int b = idx / (IMG*IMG);
    int p = idx - b * (IMG*IMG);
    int y = p / IMG, x = p - y * IMG;
    const float* g = g_gray + (size_t)b * IMG * IMG;
    float c = g[y*IMG + x];
    float u = (y > 0)       ? g[(y-1)*IMG + x] : 0.0f;
    float d = (y < IMG-1)   ? g[(y+1)*IMG + x] : 0.0f;
    float l = (x > 0)       ? g[y*IMG + x-1]   : 0.0f;
    float r = (x < IMG-1)   ? g[y*IMG + x+1]   : 0.0f;
    g_lap[idx] = u + d + l + r - 4.0f*c;
}

__global__ void k_flags() {
    int idx = blockIdx.x * blockDim.x + threadIdx.x;
    if (idx >= NB*127*127) return;
    int b = idx / (127*127);
    int rem = idx - b * (127*127);
    int i = rem / 127, j = rem - i * 127;
    const float* lp = g_lap + (size_t)b * IMG * IMG + (4*i)*IMG + 4*j;
    float s1 = 0.0f, s2 = 0.0f;
    #pragma unroll
    for (int dy = 0; dy < 8; dy++) {
        #pragma unroll
        for (int dx = 0; dx < 8; dx++) {
            float v = lp[dy*IMG + dx];
            s1 += v; s2 += v*v;
        }
    }
    float var = (s2 - s1*s1*(1.0f/64.0f)) * (1.0f/63.0f);
    g_flags[idx] = (var < 50.0f) ? 1.0f : 0.0f;
}

__global__ void k_masks(const float* __restrict__ depth) {
    int idx = blockIdx.x * blockDim.x + threadIdx.x;
    if (idx >= NB*64*64) return;
    int b = idx / (64*64);
    int rem = idx - b * (64*64);
    int k = rem / 64, l = rem - k * 64;
    float f = 0.0f;
    #pragma unroll
    for (int da = 0; da < 2; da++) {
        int a = 2*k - da;
        if (a < 0) continue;
        #pragma unroll
        for (int db = 0; db < 2; db++) {
            int bb = 2*l - db;
            if (bb < 0) continue;
            f = fmaxf(f, g_flags[((size_t)b*127 + a)*127 + bb]);
        }
    }
    g_maskR[idx] = f;
    float dv = depth[((size_t)b*3 + 2)*IMG*IMG + (8*k)*IMG + 8*l];
    float md = (dv <= 0.0f) ? 1.0f : 0.0f;
    g_maskD[idx] = md;
    if (f  > 0.0f) atomicOr(&g_anyR, 1);
    if (md > 0.0f) atomicOr(&g_anyD, 1);
}

// ---------------------------------------------------------------------------
// Conversion / layout kernels
// ---------------------------------------------------------------------------
// Weights fp32 -> fp16, [tap][co][ci]. Once per level.
__global__ void k_cvtw(const float* __restrict__ w, int C) {
    if (g_anyR == 0 && g_anyD == 0) return;
    int idx = blockIdx.x * blockDim.x + threadIdx.x;
    int n = 9 * C * C;
    if (idx >= n) return;
    int t   = idx / (C * C);
    int rem = idx - t * (C * C);
    int co  = rem / C;
    int ci  = rem - co * C;
    g_wh[idx] = __float2half_rn(w[((size_t)co * C + ci) * 9 + t]);
}

// Zero the padded NHWC aux array (guarantees halo zeros)
__global__ void k_zero_aux(int n4, int useRmask) {
    if ((useRmask ? g_anyR : g_anyD) == 0) return;
    int i = blockIdx.x * blockDim.x + threadIdx.x;
    if (i >= n4) return;
    uint4 z = {0, 0, 0, 0};
    ((uint4*)g_auxh)[i] = z;
}

// NCHW fp32 -> padded NHWC fp16, smem-tiled transpose.
__global__ void k_cvtaux_pad(const float* __restrict__ aux, int C, int S,
                             int useRmask) {
    if ((useRmask ? g_anyR : g_anyD) == 0) return;
    __shared__ float tile[32][33];
    int S32 = (S + 31) / 32;
    int xt = blockIdx.x % S32;
    int ct = blockIdx.x / S32;
    int y  = blockIdx.y;
    int b  = blockIdx.z;
    int tx = threadIdx.x & 31;
    int tg = threadIdx.x >> 5;
    int S2 = S + 2;
    for (int cc = tg; cc < 32; cc += 8) {
        int x = xt * 32 + tx, c = ct * 32 + cc;
        float v = 0.0f;
        if (x < S) v = aux[(((size_t)b * C + c) * S + y) * S + x];
        tile[cc][tx] = v;
    }
    __syncthreads();
    for (int xx = tg; xx < 32; xx += 8) {
        int x = xt * 32 + xx, c = ct * 32 + tx;
        if (x < S) {
            size_t o = (((size_t)b * S2 + y + 1) * S2 + x + 1) * C + c;
            g_auxh[o] = __float2half_rn(tile[tx][xx]);
        }
    }
}

// ---------------------------------------------------------------------------
// Tensor-core 3x3 conv (pad=1, cross-correlation), single-pass fp16,
// 2-stage cp.async double-buffered K-chunks (fill k+1 overlaps compute k).
// CTA: 64 couts x 128 pixels (16y x 8x). 8 warps (2M x 4N). 2 CTAs/SM.
// smem rows padded to 24 elems (48B) -> conflict-free ldmatrix.
// ---------------------------------------------------------------------------
#define A_ELEMS (9*64*24)            // 13824 fp16
#define B_ELEMS (180*24)             // 4320 fp16
#define STAGE_ELEMS (A_ELEMS + B_ELEMS)
#define CONV_SMEM_BYTES (2*STAGE_ELEMS*2)   // 72576

template<int C, int S>
__global__ void __launch_bounds__(256, 2) k_conv_mma(int useRmask) {
    if ((useRmask ? g_anyR : g_anyD) == 0) return;

    extern __shared__ __align__(16) char smem_raw[];
    const uint32_t sm0 = smem_u32(smem_raw);

    constexpr int S2 = S + 2;
    const int b      = blockIdx.z;
    const int coBase = blockIdx.y * 64;
    constexpr int XT = S / 8;
    const int y0 = (blockIdx.x / XT) * 16;
    const int x0 = (blockIdx.x % XT) * 8;

    const int tid  = threadIdx.x;
    const int lane = tid & 31;
    const int wid  = tid >> 5;
    const int wm   = wid & 1;       // co 32-block
    const int wn   = wid >> 1;      // pixel-row 4-block

    const __half* auxB = g_auxh + (size_t)b * S2 * S2 * C;

    // lane-dependent ldmatrix address components (element units)
    const int aM = ((lane >> 3) & 1) * 8 + (lane & 7);
    const int aK = (lane >> 4) * 8;
    const int lb = lane & 15;
    const int bRow = lb & 7;
    const int bK   = (lb >> 3) * 8;

    float acc[2][4][4];
    #pragma unroll
    for (int mf = 0; mf < 2; mf++)
        #pragma unroll
        for (int nf = 0; nf < 4; nf++)
            #pragma unroll
            for (int k = 0; k < 4; k++) acc[mf][nf][k] = 0.0f;

    constexpr int NCHUNK = C / 16;

    // ---- async fill of one stage for chunk ci0 ----
    auto fill = [&](int s, int ci0) {
        uint32_t base = sm0 + (uint32_t)(s * STAGE_ELEMS) * 2;
        // A (weights): 1152 16B-chunks
        for (int i = tid; i < 1152; i += 256) {
            int row = i >> 1, half = i & 1;
            int t = row >> 6, co = row & 63;
            size_t se = ((size_t)t * C + coBase + co) * C + ci0 + half * 8;
            cpa16(base + (uint32_t)(row * 24 + half * 8) * 2, g_wh + se);
        }
        // B (activations): 360 16B-chunks
        uint32_t bb = base + (uint32_t)A_ELEMS * 2;
        for (int i = tid; i < 360; i += 256) {
            int pix = i >> 1, half = i & 1;
            int iy = pix / 10, ix = pix - iy * 10;
            size_t so = (((size_t)(y0 + iy)) * S2 + x0 + ix) * C + ci0 + half * 8;
            cpa16(bb + (uint32_t)(pix * 24 + half * 8) * 2, auxB + so);
        }
    };

    fill(0, 0);
    cpa_commit();

    for (int k = 0; k < NCHUNK; k++) {
        int s = k & 1;
        if (k + 1 < NCHUNK) {
            fill(s ^ 1, (k + 1) * 16);
            cpa_commit();
            cpa_wait1();
        } else {
            cpa_wait0();
        }
        __syncthreads();

        const uint32_t base = sm0 + (uint32_t)(s * STAGE_ELEMS) * 2;
        const uint32_t sA32 = base;
        const uint32_t sB32 = base + (uint32_t)A_ELEMS * 2;

        for (int t = 0; t < 9; t++) {
            const int tty = t / 3, ttx = t - tty * 3;
            uint32_t Af[2][4];
            #pragma unroll
            for (int mf = 0; mf < 2; mf++) {
                int ea = (t * 64 + wm * 32 + mf * 16 + aM) * 24 + aK;
                ldsm4(Af[mf], sA32 + ea * 2);
            }
            #pragma unroll
            for (int nf = 0; nf < 4; nf++) {
                int eb = ((wn * 4 + nf + tty) * 10 + ttx + bRow) * 24 + bK;
                uint32_t Bf[2];
                ldsm2(Bf, sB32 + eb * 2);
                #pragma unroll
                for (int mf = 0; mf < 2; mf++)
                    mma16816h(acc[mf][nf], Af[mf], Bf);
            }
        }
        __syncthreads();
    }

    // --- epilogue: write fp32 to g_t (NCHW) ---
    #pragma unroll
    for (int mf = 0; mf < 2; mf++) {
        #pragma unroll
        for (int nf = 0; nf < 4; nf++) {
            int co = coBase + wm * 32 + mf * 16 + (lane >> 2);
            int y  = y0 + wn * 4 + nf;
            int x  = x0 + (lane & 3) * 2;
            size_t o = (((size_t)b * C + co) * S + y) * S + x;
            float2 lo; lo.x = acc[mf][nf][0]; lo.y = acc[mf][nf][1];
            float2 hi; hi.x = acc[mf][nf][2]; hi.y = acc[mf][nf][3];
            *(float2*)(g_t + o) = lo;
            *(float2*)(g_t + o + (size_t)8 * S * S) = hi;
        }
    }
}

// ---------------------------------------------------------------------------
// BN stats over (B, H, W) per channel -> fused scale/bias
// ---------------------------------------------------------------------------
__global__ void k_bnstats(const float* __restrict__ gamma,
                          const float* __restrict__ beta, int C, int S,
                          int useRmask) {
    if ((useRmask ? g_anyR : g_anyD) == 0) return;
    int c = blockIdx.x;
    int n = NB * S * S;
    float s = 0.0f, q = 0.0f;
    for (int i = threadIdx.x; i < n; i += 256) {
        int b = i / (S*S);
        int p = i - b * (S*S);
        float v = g_t[((size_t)b*C + c)*S*S + p];
        s += v; q += v*v;
    }
    __shared__ float ss[256], sq[256];
    ss[threadIdx.x] = s; sq[threadIdx.x] = q;
    __syncthreads();
    for (int o = 128; o > 0; o >>= 1) {
        if (threadIdx.x < o) {
            ss[threadIdx.x] += ss[threadIdx.x + o];
            sq[threadIdx.x] += sq[threadIdx.x + o];
        }
        __syncthreads();
    }
    if (threadIdx.x == 0) {
        float mean = ss[0] / (float)n;
        float var  = sq[0] / (float)n - mean*mean;
        float rstd = 1.0f / sqrtf(var + 1e-5f);
        float A = gamma[c] * rstd;
        g_bnA[c] = A;
        g_bnB[c] = beta[c] - mean * A;
    }
}

// ---------------------------------------------------------------------------
// Spatial attention: per-pixel channel mean/max (coalesced), 7x7 conv + sigmoid
// ---------------------------------------------------------------------------
__global__ void k_spstats(const float* __restrict__ mainp, int C, int S,
                          int useRmask) {
    if ((useRmask ? g_anyR : g_anyD) == 0) return;
    int b = blockIdx.y;
    int p = blockIdx.x * blockDim.x + threadIdx.x;
    if (p >= S*S) return;
    const float* base = mainp + (size_t)b*C*S*S + p;
    float m = 0.0f, mx = -3.402823466e38f;
    #pragma unroll 4
    for (int c = 0; c < C; c++) {
        float v = base[(size_t)c*S*S];
        m += v; mx = fmaxf(mx, v);
    }
    g_spmean[(size_t)b*S*S + p] = m / (float)C;
    g_spmax [(size_t)b*S*S + p] = mx;
}

__global__ void k_spconv(const float* __restrict__ saw, int S, int useRmask) {
    if ((useRmask ? g_anyR : g_anyD) == 0) return;
    __shared__ float sw_[196];
    int b = blockIdx.y, y = blockIdx.x, x = threadIdx.x;
    for (int i = x; i < 196; i += blockDim.x) sw_[i] = saw[i];
    __syncthreads();
    float step = 2.0f / (float)(S - 1);
    float acc = 0.0f;
    #pragma unroll
    for (int ky = 0; ky < 7; ky++) {
        int yy = y + ky - 3;
        if (yy < 0 || yy >= S) continue;
        #pragma unroll
        for (int kx = 0; kx < 7; kx++) {
            int xx = x + kx - 3;
            if (xx < 0 || xx >= S) continue;
            int widx = ky*7 + kx;
            acc += sw_[widx]        * g_spmean[(size_t)b*S*S + yy*S + xx];
            acc += sw_[49 + widx]   * g_spmax [(size_t)b*S*S + yy*S + xx];
            acc += sw_[98 + widx]   * (-1.0f + (float)xx * step);
            acc += sw_[147 + widx]  * (-1.0f + (float)yy * step);
        }
    }
    g_sw[(size_t)b*S*S + y*S + x] = 1.0f / (1.0f + expf(-acc));
}

// ---------------------------------------------------------------------------
// Channel attention: GAP -> ca1 -> relu -> ca2 -> sigmoid
// ---------------------------------------------------------------------------
__global__ void k_gap(const float* __restrict__ mainp, int C, int S,
                      int useRmask) {
    if ((useRmask ? g_anyR : g_anyD) == 0) return;
    int c = blockIdx.x, b = blockIdx.y;
    const float* p = mainp + ((size_t)b*C + c)*S*S;
    float s = 0.0f;
    for (int i = threadIdx.x; i < S*S; i += 128) s += p[i];
    __shared__ float sm[128];
    sm[threadIdx.x] = s;
    __syncthreads();
    for (int o = 64; o > 0; o >>= 1) {
        if (threadIdx.x < o) sm[threadIdx.x] += sm[threadIdx.x + o];
        __syncthreads();
    }
    if (threadIdx.x == 0) g_gap[b*C + c] = sm[0] / (float)(S*S);
}

__global__ void k_ca(const float* __restrict__ ca1, const float* __restrict__ ca2,
                     int C, int Rr, int useRmask) {
    if ((useRmask ? g_anyR : g_anyD) == 0) return;
    int b = blockIdx.x;
    __shared__ float sg[1024];
    __shared__ float sh[64];
    for (int c = threadIdx.x; c < C; c += 128) sg[c] = g_gap[b*C + c];
    __syncthreads();
    for (int rr = threadIdx.x; rr < Rr; rr += 128) {
        float h = 0.0f;
        for (int c = 0; c < C; c++) h += ca1[(size_t)rr*C + c] * sg[c];
        sh[rr] = fmaxf(h, 0.0f);
    }
    __syncthreads();
    for (int c = threadIdx.x; c < C; c += 128) {
        float v = 0.0f;
        for (int rr = 0; rr < Rr; rr++) v += ca2[(size_t)c*Rr + rr] * sh[rr];
        g_cw[b*C + c] = 1.0f / (1.0f + expf(-v));
    }
}

// ---------------------------------------------------------------------------
// Final blend: out = (inv==0) ? main : 2 * relu(A*t+B) * sw * cw
// ---------------------------------------------------------------------------
__global__ void k_final(const float* __restrict__ mainp, float* __restrict__ outp,
                        int C, int S, int step, int useRmask) {
    int idx = blockIdx.x * blockDim.x + threadIdx.x;
    int N = NB * C * S * S;
    if (idx >= N) return;
    int b   = idx / (C*S*S);
    int rem = idx - b * (C*S*S);
    int c   = rem / (S*S);
    int p   = rem - c * (S*S);
    int y = p / S, x = p - y * S;
    const float* maskp = useRmask ? g_maskR : g_maskD;
    float inv = maskp[((size_t)b*64 + y*step)*64 + x*step];
    float res;
    if (inv == 0.0f) {
        res = mainp[idx];
    } else {
        float tv = g_t[idx];
        float a  = fmaxf(g_bnA[c]*tv + g_bnB[c], 0.0f);
        res = ((a * g_sw[(size_t)b*S*S + p]) * g_cw[b*C + c]) * 2.0f;
    }
    outp[idx] = res;
}

// ---------------------------------------------------------------------------
// Host orchestration
// ---------------------------------------------------------------------------
struct LvlParams {
    const float *ft, *g, *b, *sa, *ca1, *ca2;
};

template<int C, int S>
static void run_dir(const float* mainp, const float* auxp, int useRmask,
                    float* outp, const LvlParams& P) {
    int S2 = S + 2;
    int nPad4 = NB * S2 * S2 * C / 8;
    k_zero_aux<<<(nPad4 + 255)/256, 256>>>(nPad4, useRmask);
    int S32 = (S + 31) / 32;
    k_cvtaux_pad<<<dim3(S32 * (C/32), S, NB), 256>>>(auxp, C, S, useRmask);
    cudaFuncSetAttribute(k_conv_mma<C, S>,
                         cudaFuncAttributeMaxDynamicSharedMemorySize,
                         CONV_SMEM_BYTES);
    dim3 cgrid((S*S)/128, C/64, NB);
    k_conv_mma<C, S><<<cgrid, 256, CONV_SMEM_BYTES>>>(useRmask);
    k_bnstats<<<C, 256>>>(P.g, P.b, C, S, useRmask);
    k_spstats<<<dim3((S*S + 255)/256, NB), 256>>>(mainp, C, S, useRmask);
    k_spconv<<<dim3(S, NB), S>>>(P.sa, S, useRmask);
    k_gap<<<dim3(C, NB), 128>>>(mainp, C, S, useRmask);
    k_ca<<<NB, 128>>>(P.ca1, P.ca2, C, C/16, useRmask);
    int N = NB * C * S * S;
    k_final<<<(N + 255)/256, 256>>>(mainp, outp, C, S, 64/S, useRmask);
}

extern "C" void kernel_launch(void* const* d_in, const int* in_sizes, int n_in,
                              void* d_out, int out_size) {
    // metadata order follows setup_inputs() dict insertion order:
    // rgb_feat0, depth_feat0, rgb_feat1, depth_feat1, rgb_feat2, depth_feat2,
    // rgb_img, depth_img, then per level: ft_w, bn_g, bn_b, sa_w, ca1_w, ca2_w
    const float* rgbF[3] = {(const float*)d_in[0], (const float*)d_in[2], (const float*)d_in[4]};
    const float* depF[3] = {(const float*)d_in[1], (const float*)d_in[3], (const float*)d_in[5]};
    const float* rgb_img   = (const float*)d_in[6];
    const float* depth_img = (const float*)d_in[7];
    LvlParams P[3];
    for (int i = 0; i < 3; i++) {
        int base = 8 + i*6;
        P[i].ft  = (const float*)d_in[base + 0];
        P[i].g   = (const float*)d_in[base + 1];
        P[i].b   = (const float*)d_in[base + 2];
        P[i].sa  = (const float*)d_in[base + 3];
        P[i].ca1 = (const float*)d_in[base + 4];
        P[i].ca2 = (const float*)d_in[base + 5];
    }
    float* out = (float*)d_out;

    // masks
    int npix = NB * IMG * IMG;
    k_zeroflags<<<1, 1>>>();
    k_gray <<<(npix + 255)/256, 256>>>(rgb_img);
    k_lap  <<<(npix + 255)/256, 256>>>();
    k_flags<<<(NB*127*127 + 255)/256, 256>>>();
    k_masks<<<(NB*64*64 + 255)/256, 256>>>(depth_img);

    const size_t szR0 = (size_t)NB*256*64*64;
    const size_t szR1 = (size_t)NB*512*32*32;
    const size_t szR2 = (size_t)NB*1024*16*16;
    float* oR0 = out;
    float* oR1 = oR0 + szR0;
    float* oR2 = oR1 + szR1;
    float* oD0 = oR2 + szR2;
    float* oD1 = oD0 + szR0;
    float* oD2 = oD1 + szR1;

    // level 0
    k_cvtw<<<(9*256*256 + 255)/256, 256>>>(P[0].ft, 256);
    run_dir<256, 64>(rgbF[0], depF[0], 1, oR0, P[0]);
    run_dir<256, 64>(depF[0], rgbF[0], 0, oD0, P[0]);
    // level 1
    k_cvtw<<<(9*512*512 + 255)/256, 256>>>(P[1].ft, 512);
    run_dir<512, 32>(rgbF[1], depF[1], 1, oR1, P[1]);
    run_dir<512, 32>(depF[1], rgbF[1], 0, oD1, P[1]);
    // level 2
    k_cvtw<<<(9*1024*1024 + 255)/256, 256>>>(P[2].ft, 1024);
    run_dir<1024,16>(rgbF[2], depF[2], 1, oR2, P[2]);
    run_dir<1024,16>(depF[2], rgbF[2], 0, oD2, P[2]);
}

// round 14
// speedup vs baseline: 3.6570x; 1.0403x over previous
#include <cuda_runtime.h>
#include <cuda_fp16.h>
#include <math.h>
#include <stdint.h>

#define NB   8
#define IMG  512

// ---------------------------------------------------------------------------
// Scratch (static device globals — no allocations allowed)
// ---------------------------------------------------------------------------
__device__ float g_gray  [NB*IMG*IMG];
__device__ float g_lap   [NB*IMG*IMG];
__device__ float g_flags [NB*127*127];
__device__ float g_maskR [NB*64*64];
__device__ float g_maskD [NB*64*64];
__device__ float g_t     [NB*256*64*64];   // conv output scratch (max = level 0)
__device__ float g_spmean[NB*64*64];
__device__ float g_spmax [NB*64*64];
__device__ float g_sw    [NB*64*64];
__device__ float g_gap   [NB*1024];
__device__ float g_cw    [NB*1024];
__device__ float g_bnA   [1024];
__device__ float g_bnB   [1024];
__device__ int   g_anyR;
__device__ int   g_anyD;

// aux activations fp16, halo-padded NHWC [b][S+2][S+2][C] (max 8*66*66*256)
__device__ __half g_auxh[8921088];
// Winograd F(2x2,3x3) buffers:
//   U [k=16][co][ci] fp16           (max 16*1024*1024)
//   V [k=16][n=b*T+t][ci] fp16      (max 16*8192*256)
//   M [k=16][co][n] fp32            (max 16*256*8192)
__device__ __half g_U[16*1024*1024];
__device__ __half g_V[16*8192*256];
__device__ float  g_M[16*256*8192];

// ---------------------------------------------------------------------------
// MMA + cp.async helpers (legacy mma.sync path — tcgen05 rejected by the
// harness's compute_100 lowering; legacy HMMA runs ~quarter-rate on sm_100,
// hence the Winograd transform to cut mma count 2.25x)
// ---------------------------------------------------------------------------
__device__ __forceinline__ uint32_t smem_u32(const void* p) {
    return (uint32_t)__cvta_generic_to_shared(p);
}
__device__ __forceinline__ void ldsm4(uint32_t* r, uint32_t addr) {
    asm volatile("ldmatrix.sync.aligned.m8n8.x4.shared.b16 {%0,%1,%2,%3}, [%4];"
                 : "=r"(r[0]), "=r"(r[1]), "=r"(r[2]), "=r"(r[3]) : "r"(addr));
}
__device__ __forceinline__ void ldsm2(uint32_t* r, uint32_t addr) {
    asm volatile("ldmatrix.sync.aligned.m8n8.x2.shared.b16 {%0,%1}, [%2];"
                 : "=r"(r[0]), "=r"(r[1]) : "r"(addr));
}
__device__ __forceinline__ void mma16816h(float* c, const uint32_t* a, const uint32_t* b) {
    asm volatile("mma.sync.aligned.m16n8k16.row.col.f32.f16.f16.f32 "
                 "{%0,%1,%2,%3}, {%4,%5,%6,%7}, {%8,%9}, {%0,%1,%2,%3};"
                 : "+f"(c[0]), "+f"(c[1]), "+f"(c[2]), "+f"(c[3])
                 : "r"(a[0]), "r"(a[1]), "r"(a[2]), "r"(a[3]), "r"(b[0]), "r"(b[1]));
}
__device__ __forceinline__ void cpa16(uint32_t dst, const void* src) {
    asm volatile("cp.async.cg.shared.global [%0], [%1], 16;" :: "r"(dst), "l"(src));
}
__device__ __forceinline__ void cpa_commit() { asm volatile("cp.async.commit_group;"); }
__device__ __forceinline__ void cpa_wait1()  { asm volatile("cp.async.wait_group 1;"); }
__device__ __forceinline__ void cpa_wait0()  { asm volatile("cp.async.wait_group 0;"); }

// ---------------------------------------------------------------------------
// Stage A: blur mask from rgb image + depth mask
// ---------------------------------------------------------------------------
__global__ void k_zeroflags() { g_anyR = 0; g_anyD = 0; }

__global__ void k_gray(const float* __restrict__ rgb) {
    int idx = blockIdx.x * blockDim.x + threadIdx.x;
    if (idx >= NB*IMG*IMG) return;
    int b = idx / (IMG*IMG);
    int p = idx - b * (IMG*IMG);
    const float* base = rgb + (size_t)b * 3 * IMG * IMG;
    float g = 0.299f*base[p] + 0.587f*base[IMG*IMG + p] + 0.114f*base[2*IMG*IMG + p];
    g *= 255.0f;
    g = fminf(fmaxf(g, 0.0f), 255.0f);
    g_gray[idx] = g;
}

__global__ void k_lap() {
    int idx = blockIdx.x * blockDim.x + threadIdx.x;
    if (idx >= NB*IMG*IMG) return;
    int b = idx / (IMG*IMG);
    int p = idx - b * (IMG*IMG);
    int y = p / IMG, x = p - y * IMG;
    const float* g = g_gray + (size_t)b * IMG * IMG;
    float c = g[y*IMG + x];
    float u = (y > 0)       ? g[(y-1)*IMG + x] : 0.0f;
    float d = (y < IMG-1)   ? g[(y+1)*IMG + x] : 0.0f;
    float l = (x > 0)       ? g[y*IMG + x-1]   : 0.0f;
    float r = (x < IMG-1)   ? g[y*IMG + x+1]   : 0.0f;
    g_lap[idx] = u + d + l + r - 4.0f*c;
}

__global__ void k_flags() {
    int idx = blockIdx.x * blockDim.x + threadIdx.x;
    if (idx >= NB*127*127) return;
    int b = idx / (127*127);
    int rem = idx - b * (127*127);
    int i = rem / 127, j = rem - i * 127;
    const float* lp = g_lap + (size_t)b * IMG * IMG + (4*i)*IMG + 4*j;
    float s1 = 0.0f, s2 = 0.0f;
    #pragma unroll
    for (int dy = 0; dy < 8; dy++) {
        #pragma unroll
        for (int dx = 0; dx < 8; dx++) {
            float v = lp[dy*IMG + dx];
            s1 += v; s2 += v*v;
        }
    }
    float var = (s2 - s1*s1*(1.0f/64.0f)) * (1.0f/63.0f);
    g_flags[idx] = (var < 50.0f) ? 1.0f : 0.0f;
}

__global__ void k_masks(const float* __restrict__ depth) {
    int idx = blockIdx.x * blockDim.x + threadIdx.x;
    if (idx >= NB*64*64) return;
    int b = idx / (64*64);
    int rem = idx - b * (64*64);
    int k = rem / 64, l = rem - k * 64;
    float f = 0.0f;
    #pragma unroll
    for (int da = 0; da < 2; da++) {
        int a = 2*k - da;
        if (a < 0) continue;
        #pragma unroll
        for (int db = 0; db < 2; db++) {
            int bb = 2*l - db;
            if (bb < 0) continue;
            f = fmaxf(f, g_flags[((size_t)b*127 + a)*127 + bb]);
        }
    }
    g_maskR[idx] = f;
    float dv = depth[((size_t)b*3 + 2)*IMG*IMG + (8*k)*IMG + 8*l];
    float md = (dv <= 0.0f) ? 1.0f : 0.0f;
    g_maskD[idx] = md;
    if (f  > 0.0f) atomicOr(&g_anyR, 1);
    if (md > 0.0f) atomicOr(&g_anyD, 1);
}

// ---------------------------------------------------------------------------
// Layout kernels
// ---------------------------------------------------------------------------
// Zero the padded NHWC aux array (guarantees halo zeros)
__global__ void k_zero_aux(int n4, int useRmask) {
    if ((useRmask ? g_anyR : g_anyD) == 0) return;
    int i = blockIdx.x * blockDim.x + threadIdx.x;
    if (i >= n4) return;
    uint4 z = {0, 0, 0, 0};
    ((uint4*)g_auxh)[i] = z;
}

// NCHW fp32 -> padded NHWC fp16, smem-tiled transpose.
__global__ void k_cvtaux_pad(const float* __restrict__ aux, int C, int S,
                             int useRmask) {
    if ((useRmask ? g_anyR : g_anyD) == 0) return;
    __shared__ float tile[32][33];
    int S32 = (S + 31) / 32;
    int xt = blockIdx.x % S32;
    int ct = blockIdx.x / S32;
    int y  = blockIdx.y;
    int b  = blockIdx.z;
    int tx = threadIdx.x & 31;
    int tg = threadIdx.x >> 5;
    int S2 = S + 2;
    for (int cc = tg; cc < 32; cc += 8) {
        int x = xt * 32 + tx, c = ct * 32 + cc;
        float v = 0.0f;
        if (x < S) v = aux[(((size_t)b * C + c) * S + y) * S + x];
        tile[cc][tx] = v;
    }
    __syncthreads();
    for (int xx = tg; xx < 32; xx += 8) {
        int x = xt * 32 + xx, c = ct * 32 + tx;
        if (x < S) {
            size_t o = (((size_t)b * S2 + y + 1) * S2 + x + 1) * C + c;
            g_auxh[o] = __float2half_rn(tile[tx][xx]);
        }
    }
}

// ---------------------------------------------------------------------------
// Winograd F(2x2,3x3) transforms
// ---------------------------------------------------------------------------
// Weights: U = G g G^T.  g from w[co][ci][3][3] fp32. Per level (shared by
// both directions).
__global__ void k_wino_w(const float* __restrict__ w, int C) {
    if (g_anyR == 0 && g_anyD == 0) return;
    int idx = blockIdx.x * blockDim.x + threadIdx.x;
    if (idx >= C * C) return;
    int co = idx / C, ci = idx - co * C;
    const float* gp = w + ((size_t)co * C + ci) * 9;
    float g[3][3];
    #pragma unroll
    for (int i = 0; i < 3; i++)
        #pragma unroll
        for (int j = 0; j < 3; j++) g[i][j] = gp[i*3 + j];
    float q[4][3];
    #pragma unroll
    for (int j = 0; j < 3; j++) {
        q[0][j] = g[0][j];
        q[1][j] = 0.5f * (g[0][j] + g[1][j] + g[2][j]);
        q[2][j] = 0.5f * (g[0][j] - g[1][j] + g[2][j]);
        q[3][j] = g[2][j];
    }
    #pragma unroll
    for (int i = 0; i < 4; i++) {
        float u0 = q[i][0];
        float u1 = 0.5f * (q[i][0] + q[i][1] + q[i][2]);
        float u2 = 0.5f * (q[i][0] - q[i][1] + q[i][2]);
        float u3 = q[i][2];
        g_U[((size_t)(i*4 + 0) * C + co) * C + ci] = __float2half_rn(u0);
        g_U[((size_t)(i*4 + 1) * C + co) * C + ci] = __float2half_rn(u1);
        g_U[((size_t)(i*4 + 2) * C + co) * C + ci] = __float2half_rn(u2);
        g_U[((size_t)(i*4 + 3) * C + co) * C + ci] = __float2half_rn(u3);
    }
}

// Input: V = B^T d B per 4x4 tile (stride 2) from padded NHWC fp16 aux.
// n = b*T + t (t = ty*(S/2)+tx). Output V[k][n][ci], ci contiguous.
__global__ void k_wino_in(int C, int S, int T, int NBT, int useRmask) {
    if ((useRmask ? g_anyR : g_anyD) == 0) return;
    int idx = blockIdx.x * blockDim.x + threadIdx.x;
    if (idx >= NBT * C) return;
    int ci = idx % C;
    int n  = idx / C;
    int b  = n / T;
    int t  = n - b * T;
    int W  = S >> 1;
    int ty = t / W, tx = t - ty * W;
    int S2 = S + 2;
    const __half* src = g_auxh + (((size_t)b * S2 + 2*ty) * S2 + 2*tx) * C + ci;
    float d[4][4];
    #pragma unroll
    for (int i = 0; i < 4; i++)
        #pragma unroll
        for (int j = 0; j < 4; j++)
            d[i][j] = __half2float(src[((size_t)i * S2 + j) * C]);
    // row transform (y): a0=d0-d2, a1=d1+d2, a2=d2-d1, a3=d1-d3
    float a[4][4];
    #pragma unroll
    for (int j = 0; j < 4; j++) {
        a[0][j] = d[0][j] - d[2][j];
        a[1][j] = d[1][j] + d[2][j];
        a[2][j] = d[2][j] - d[1][j];
        a[3][j] = d[1][j] - d[3][j];
    }
    #pragma unroll
    for (int i = 0; i < 4; i++) {
        float v0 = a[i][0] - a[i][2];
        float v1 = a[i][1] + a[i][2];
        float v2 = a[i][2] - a[i][1];
        float v3 = a[i][1] - a[i][3];
        g_V[((size_t)(i*4 + 0) * NBT + n) * C + ci] = __float2half_rn(v0);
        g_V[((size_t)(i*4 + 1) * NBT + n) * C + ci] = __float2half_rn(v1);
        g_V[((size_t)(i*4 + 2) * NBT + n) * C + ci] = __float2half_rn(v2);
        g_V[((size_t)(i*4 + 3) * NBT + n) * C + ci] = __float2half_rn(v3);
    }
}

// ---------------------------------------------------------------------------
// 16 batched GEMMs (grid.z = k): M_k[co][n] = U_k[co][:] . V_k[n][:]
// CTA: 64 co x 128 n, 8 warps (2M x 4N), fp16 mma, fp32 accum.
// Double-buffered cp.async K-chunks of 16. smem rows padded to 24 elems.
// ---------------------------------------------------------------------------
#define WA_ELEMS (64*24)
#define WB_ELEMS (128*24)
#define WSTAGE (WA_ELEMS + WB_ELEMS)

template<int C>
__global__ void __launch_bounds__(256) k_wino_mm(int NBT, int useRmask) {
    if ((useRmask ? g_anyR : g_anyD) == 0) return;

    __shared__ __align__(16) __half smem[2*WSTAGE];
    const uint32_t sm0 = smem_u32(smem);

    const int k     = blockIdx.z;
    const int coBase = blockIdx.y * 64;
    const int nBase  = blockIdx.x * 128;

    const int tid  = threadIdx.x;
    const int lane = tid & 31;
    const int wid  = tid >> 5;
    const int wm   = wid & 1;
    const int wn   = wid >> 1;

    const __half* Ubase = g_U + (size_t)k * C * C;
    const __half* Vbase = g_V + (size_t)k * NBT * C;

    const int aM = ((lane >> 3) & 1) * 8 + (lane & 7);
    const int aK = (lane >> 4) * 8;
    const int lb = lane & 15;
    const int bRow = lb & 7;
    const int bK   = (lb >> 3) * 8;

    float acc[2][4][4];
    #pragma unroll
    for (int mf = 0; mf < 2; mf++)
        #pragma unroll
        for (int nf = 0; nf < 4; nf++)
            #pragma unroll
            for (int q = 0; q < 4; q++) acc[mf][nf][q] = 0.0f;

    constexpr int NCHUNK = C / 16;

    auto fill = [&](int s, int ci0) {
        uint32_t base = sm0 + (uint32_t)(s * WSTAGE) * 2;
        // A: 64 rows x 16 ci = 128 16B-chunks
        for (int i = tid; i < 128; i += 256) {
            int row = i >> 1, half = i & 1;
            cpa16(base + (uint32_t)(row * 24 + half * 8) * 2,
                  Ubase + ((size_t)(coBase + row)) * C + ci0 + half * 8);
        }
        // B: 128 rows x 16 ci = 256 16B-chunks
        uint32_t bb = base + (uint32_t)WA_ELEMS * 2;
        for (int i = tid; i < 256; i += 256) {
            int row = i >> 1, half = i & 1;
            cpa16(bb + (uint32_t)(row * 24 + half * 8) * 2,
                  Vbase + ((size_t)(nBase + row)) * C + ci0 + half * 8);
        }
    };

    fill(0, 0);
    cpa_commit();

    for (int kk = 0; kk < NCHUNK; kk++) {
        int s = kk & 1;
        if (kk + 1 < NCHUNK) {
            fill(s ^ 1, (kk + 1) * 16);
            cpa_commit();
            cpa_wait1();
        } else {
            cpa_wait0();
        }
        __syncthreads();

        const uint32_t base = sm0 + (uint32_t)(s * WSTAGE) * 2;
        const uint32_t sA32 = base;
        const uint32_t sB32 = base + (uint32_t)WA_ELEMS * 2;

        uint32_t Af[2][4];
        #pragma unroll
        for (int mf = 0; mf < 2; mf++) {
            int ea = (wm * 32 + mf * 16 + aM) * 24 + aK;
            ldsm4(Af[mf], sA32 + ea * 2);
        }
        #pragma unroll
        for (int nf = 0; nf < 4; nf++) {
            int eb = (wn * 32 + nf * 8 + bRow) * 24 + bK;
            uint32_t Bf[2];
            ldsm2(Bf, sB32 + eb * 2);
            #pragma unroll
            for (int mf = 0; mf < 2; mf++)
                mma16816h(acc[mf][nf], Af[mf], Bf);
        }
        __syncthreads();
    }

    // epilogue: M[k][co][n] fp32
    float* Mb = g_M + (size_t)k * C * NBT;
    #pragma unroll
    for (int mf = 0; mf < 2; mf++) {
        #pragma unroll
        for (int nf = 0; nf < 4; nf++) {
            int co = coBase + wm * 32 + mf * 16 + (lane >> 2);
            int n  = nBase + wn * 32 + nf * 8 + (lane & 3) * 2;
            float2 lo; lo.x = acc[mf][nf][0]; lo.y = acc[mf][nf][1];
            float2 hi; hi.x = acc[mf][nf][2]; hi.y = acc[mf][nf][3];
            *(float2*)(Mb + (size_t)co * NBT + n) = lo;
            *(float2*)(Mb + (size_t)(co + 8) * NBT + n) = hi;
        }
    }
}

// Output: o = A^T m A -> 2x2 per (co, tile) into g_t NCHW.
__global__ void k_wino_out(int C, int S, int T, int NBT, int useRmask) {
    if ((useRmask ? g_anyR : g_anyD) == 0) return;
    int idx = blockIdx.x * blockDim.x + threadIdx.x;
    if (idx >= C * NBT) return;
    int n  = idx % NBT;
    int co = idx / NBT;
    int b  = n / T;
    int t  = n - b * T;
    int W  = S >> 1;
    int ty = t / W, tx = t - ty * W;

    float m[4][4];
    #pragma unroll
    for (int i = 0; i < 4; i++)
        #pragma unroll
        for (int j = 0; j < 4; j++)
            m[i][j] = g_M[((size_t)(i*4 + j) * C + co) * NBT + n];

    float r[2][4];
    #pragma unroll
    for (int j = 0; j < 4; j++) {
        r[0][j] = m[0][j] + m[1][j] + m[2][j];
        r[1][j] = m[1][j] - m[2][j] - m[3][j];
    }
    float o00 = r[0][0] + r[0][1] + r[0][2];
    float o01 = r[0][1] - r[0][2] - r[0][3];
    float o10 = r[1][0] + r[1][1] + r[1][2];
    float o11 = r[1][1] - r[1][2] - r[1][3];

    float* dst = g_t + (((size_t)b * C + co) * S + 2*ty) * S + 2*tx;
    float2 row0; row0.x = o00; row0.y = o01;
    float2 row1; row1.x = o10; row1.y = o11;
    *(float2*)dst = row0;
    *(float2*)(dst + S) = row1;
}

// ---------------------------------------------------------------------------
// BN stats over (B, H, W) per channel -> fused scale/bias
// ---------------------------------------------------------------------------
__global__ void k_bnstats(const float* __restrict__ gamma,
                          const float* __restrict__ beta, int C, int S,
                          int useRmask) {
    if ((useRmask ? g_anyR : g_anyD) == 0) return;
    int c = blockIdx.x;
    int n = NB * S * S;
    float s = 0.0f, q = 0.0f;
    for (int i = threadIdx.x; i < n; i += 256) {
        int b = i / (S*S);
        int p = i - b * (S*S);
        float v = g_t[((size_t)b*C + c)*S*S + p];
        s += v; q += v*v;
    }
    __shared__ float ss[256], sq[256];
    ss[threadIdx.x] = s; sq[threadIdx.x] = q;
    __syncthreads();
    for (int o = 128; o > 0; o >>= 1) {
        if (threadIdx.x < o) {
            ss[threadIdx.x] += ss[threadIdx.x + o];
            sq[threadIdx.x] += sq[threadIdx.x + o];
        }
        __syncthreads();
    }
    if (threadIdx.x == 0) {
        float mean = ss[0] / (float)n;
        float var  = sq[0] / (float)n - mean*mean;
        float rstd = 1.0f / sqrtf(var + 1e-5f);
        float A = gamma[c] * rstd;
        g_bnA[c] = A;
        g_bnB[c] = beta[c] - mean * A;
    }
}

// ---------------------------------------------------------------------------
// Spatial attention: per-pixel channel mean/max (coalesced), 7x7 conv + sigmoid
// ---------------------------------------------------------------------------
__global__ void k_spstats(const float* __restrict__ mainp, int C, int S,
                          int useRmask) {
    if ((useRmask ? g_anyR : g_anyD) == 0) return;
    int b = blockIdx.y;
    int p = blockIdx.x * blockDim.x + threadIdx.x;
    if (p >= S*S) return;
    const float* base = mainp + (size_t)b*C*S*S + p;
    float m = 0.0f, mx = -3.402823466e38f;
    #pragma unroll 4
    for (int c = 0; c < C; c++) {
        float v = base[(size_t)c*S*S];
        m += v; mx = fmaxf(mx, v);
    }
    g_spmean[(size_t)b*S*S + p] = m / (float)C;
    g_spmax [(size_t)b*S*S + p] = mx;
}

__global__ void k_spconv(const float* __restrict__ saw, int S, int useRmask) {
    if ((useRmask ? g_anyR : g_anyD) == 0) return;
    __shared__ float sw_[196];
    int b = blockIdx.y, y = blockIdx.x, x = threadIdx.x;
    for (int i = x; i < 196; i += blockDim.x) sw_[i] = saw[i];
    __syncthreads();
    float step = 2.0f / (float)(S - 1);
    float acc = 0.0f;
    #pragma unroll
    for (int ky = 0; ky < 7; ky++) {
        int yy = y + ky - 3;
        if (yy < 0 || yy >= S) continue;
        #pragma unroll
        for (int kx = 0; kx < 7; kx++) {
            int xx = x + kx - 3;
            if (xx < 0 || xx >= S) continue;
            int widx = ky*7 + kx;
            acc += sw_[widx]        * g_spmean[(size_t)b*S*S + yy*S + xx];
            acc += sw_[49 + widx]   * g_spmax [(size_t)b*S*S + yy*S + xx];
            acc += sw_[98 + widx]   * (-1.0f + (float)xx * step);
            acc += sw_[147 + widx]  * (-1.0f + (float)yy * step);
        }
    }
    g_sw[(size_t)b*S*S + y*S + x] = 1.0f / (1.0f + expf(-acc));
}

// ---------------------------------------------------------------------------
// Channel attention: GAP -> ca1 -> relu -> ca2 -> sigmoid
// ---------------------------------------------------------------------------
__global__ void k_gap(const float* __restrict__ mainp, int C, int S,
                      int useRmask) {
    if ((useRmask ? g_anyR : g_anyD) == 0) return;
    int c = blockIdx.x, b = blockIdx.y;
    const float* p = mainp + ((size_t)b*C + c)*S*S;
    float s = 0.0f;
    for (int i = threadIdx.x; i < S*S; i += 128) s += p[i];
    __shared__ float sm[128];
    sm[threadIdx.x] = s;
    __syncthreads();
    for (int o = 64; o > 0; o >>= 1) {
        if (threadIdx.x < o) sm[threadIdx.x] += sm[threadIdx.x + o];
        __syncthreads();
    }
    if (threadIdx.x == 0) g_gap[b*C + c] = sm[0] / (float)(S*S);
}

__global__ void k_ca(const float* __restrict__ ca1, const float* __restrict__ ca2,
                     int C, int Rr, int useRmask) {
    if ((useRmask ? g_anyR : g_anyD) == 0) return;
    int b = blockIdx.x;
    __shared__ float sg[1024];
    __shared__ float sh[64];
    for (int c = threadIdx.x; c < C; c += 128) sg[c] = g_gap[b*C + c];
    __syncthreads();
    for (int rr = threadIdx.x; rr < Rr; rr += 128) {
        float h = 0.0f;
        for (int c = 0; c < C; c++) h += ca1[(size_t)rr*C + c] * sg[c];
        sh[rr] = fmaxf(h, 0.0f);
    }
    __syncthreads();
    for (int c = threadIdx.x; c < C; c += 128) {
        float v = 0.0f;
        for (int rr = 0; rr < Rr; rr++) v += ca2[(size_t)c*Rr + rr] * sh[rr];
        g_cw[b*C + c] = 1.0f / (1.0f + expf(-v));
    }
}

// ---------------------------------------------------------------------------
// Final blend: out = (inv==0) ? main : 2 * relu(A*t+B) * sw * cw
// ---------------------------------------------------------------------------
__global__ void k_final(const float* __restrict__ mainp, float* __restrict__ outp,
                        int C, int S, int step, int useRmask) {
    int idx = blockIdx.x * blockDim.x + threadIdx.x;
    int N = NB * C * S * S;
    if (idx >= N) return;
    int b   = idx / (C*S*S);
    int rem = idx - b * (C*S*S);
    int c   = rem / (S*S);
    int p   = rem - c * (S*S);
    int y = p / S, x = p - y * S;
    const float* maskp = useRmask ? g_maskR : g_maskD;
    float inv = maskp[((size_t)b*64 + y*step)*64 + x*step];
    float res;
    if (inv == 0.0f) {
        res = mainp[idx];
    } else {
        float tv = g_t[idx];
        float a  = fmaxf(g_bnA[c]*tv + g_bnB[c], 0.0f);
        res = ((a * g_sw[(size_t)b*S*S + p]) * g_cw[b*C + c]) * 2.0f;
    }
    outp[idx] = res;
}

// ---------------------------------------------------------------------------
// Host orchestration
// ---------------------------------------------------------------------------
struct LvlParams {
    const float *ft, *g, *b, *sa, *ca1, *ca2;
};

template<int C, int S>
static void run_dir(const float* mainp, const float* auxp, int useRmask,
                    float* outp, const LvlParams& P) {
    int S2 = S + 2;
    int nPad4 = NB * S2 * S2 * C / 8;
    k_zero_aux<<<(nPad4 + 255)/256, 256>>>(nPad4, useRmask);
    int S32 = (S + 31) / 32;
    k_cvtaux_pad<<<dim3(S32 * (C/32), S, NB), 256>>>(auxp, C, S, useRmask);

    constexpr int T = (S/2) * (S/2);
    constexpr int NBT = NB * T;
    k_wino_in<<<(NBT * C + 255)/256, 256>>>(C, S, T, NBT, useRmask);
    dim3 mgrid(NBT/128, C/64, 16);
    k_wino_mm<C><<<mgrid, 256>>>(NBT, useRmask);
    k_wino_out<<<(C * NBT + 255)/256, 256>>>(C, S, T, NBT, useRmask);

    k_bnstats<<<C, 256>>>(P.g, P.b, C, S, useRmask);
    k_spstats<<<dim3((S*S + 255)/256, NB), 256>>>(mainp, C, S, useRmask);
    k_spconv<<<dim3(S, NB), S>>>(P.sa, S, useRmask);
    k_gap<<<dim3(C, NB), 128>>>(mainp, C, S, useRmask);
    k_ca<<<NB, 128>>>(P.ca1, P.ca2, C, C/16, useRmask);
    int N = NB * C * S * S;
    k_final<<<(N + 255)/256, 256>>>(mainp, outp, C, S, 64/S, useRmask);
}

extern "C" void kernel_launch(void* const* d_in, const int* in_sizes, int n_in,
                              void* d_out, int out_size) {
    // metadata order follows setup_inputs() dict insertion order:
    // rgb_feat0, depth_feat0, rgb_feat1, depth_feat1, rgb_feat2, depth_feat2,
    // rgb_img, depth_img, then per level: ft_w, bn_g, bn_b, sa_w, ca1_w, ca2_w
    const float* rgbF[3] = {(const float*)d_in[0], (const float*)d_in[2], (const float*)d_in[4]};
    const float* depF[3] = {(const float*)d_in[1], (const float*)d_in[3], (const float*)d_in[5]};
    const float* rgb_img   = (const float*)d_in[6];
    const float* depth_img = (const float*)d_in[7];
    LvlParams P[3];
    for (int i = 0; i < 3; i++) {
        int base = 8 + i*6;
        P[i].ft  = (const float*)d_in[base + 0];
        P[i].g   = (const float*)d_in[base + 1];
        P[i].b   = (const float*)d_in[base + 2];
        P[i].sa  = (const float*)d_in[base + 3];
        P[i].ca1 = (const float*)d_in[base + 4];
        P[i].ca2 = (const float*)d_in[base + 5];
    }
    float* out = (float*)d_out;

    // masks
    int npix = NB * IMG * IMG;
    k_zeroflags<<<1, 1>>>();
    k_gray <<<(npix + 255)/256, 256>>>(rgb_img);
    k_lap  <<<(npix + 255)/256, 256>>>();
    k_flags<<<(NB*127*127 + 255)/256, 256>>>();
    k_masks<<<(NB*64*64 + 255)/256, 256>>>(depth_img);

    const size_t szR0 = (size_t)NB*256*64*64;
    const size_t szR1 = (size_t)NB*512*32*32;
    const size_t szR2 = (size_t)NB*1024*16*16;
    float* oR0 = out;
    float* oR1 = oR0 + szR0;
    float* oR2 = oR1 + szR1;
    float* oD0 = oR2 + szR2;
    float* oD1 = oD0 + szR0;
    float* oD2 = oD1 + szR1;

    // level 0
    k_wino_w<<<(256*256 + 255)/256, 256>>>(P[0].ft, 256);
    run_dir<256, 64>(rgbF[0], depF[0], 1, oR0, P[0]);
    run_dir<256, 64>(depF[0], rgbF[0], 0, oD0, P[0]);
    // level 1
    k_wino_w<<<(512*512 + 255)/256, 256>>>(P[1].ft, 512);
    run_dir<512, 32>(rgbF[1], depF[1], 1, oR1, P[1]);
    run_dir<512, 32>(depF[1], rgbF[1], 0, oD1, P[1]);
    // level 2
    k_wino_w<<<(1024*1024 + 255)/256, 256>>>(P[2].ft, 1024);
    run_dir<1024,16>(rgbF[2], depF[2], 1, oR2, P[2]);
    run_dir<1024,16>(depF[2], rgbF[2], 0, oD2, P[2]);
}

// round 15
// speedup vs baseline: 3.9516x; 1.0806x over previous
#include <cuda_runtime.h>
#include <cuda_fp16.h>
#include <math.h>
#include <stdint.h>

#define NB   8
#define IMG  512

// ---------------------------------------------------------------------------
// Scratch (static device globals — no allocations allowed)
// ---------------------------------------------------------------------------
__device__ float g_gray  [NB*IMG*IMG];
__device__ float g_lap   [NB*IMG*IMG];
__device__ float g_flags [NB*127*127];
__device__ float g_maskR [NB*64*64];
__device__ float g_maskD [NB*64*64];
__device__ float g_t     [NB*256*64*64];   // conv output scratch (max = level 0)
__device__ float g_spmean[NB*64*64];
__device__ float g_spmax [NB*64*64];
__device__ float g_sw    [NB*64*64];
__device__ float g_gap   [NB*1024];
__device__ float g_cw    [NB*1024];
__device__ float g_bnA   [1024];
__device__ float g_bnB   [1024];
__device__ int   g_anyR;
__device__ int   g_anyD;

// aux activations fp16, halo-padded NHWC [b][S+2][S+2][C] (max 8*66*66*256)
__device__ __half g_auxh[8921088];
// Winograd F(2x2,3x3) buffers:
//   U [k=16][co][ci] fp16           (max 16*1024*1024)
//   V [k=16][n=b*T+t][ci] fp16      (max 16*8192*256)
//   M [k=16][co][n] fp16            (max 16*256*8192)
__device__ __half g_U[16*1024*1024];
__device__ __half g_V[16*8192*256];
__device__ __half g_M[16*256*8192];

// ---------------------------------------------------------------------------
// MMA + cp.async helpers (legacy mma.sync path — tcgen05 rejected by the
// harness's compute_100 lowering; legacy HMMA runs ~quarter-rate on sm_100,
// hence Winograd to cut mma count 2.25x)
// ---------------------------------------------------------------------------
__device__ __forceinline__ uint32_t smem_u32(const void* p) {
    return (uint32_t)__cvta_generic_to_shared(p);
}
__device__ __forceinline__ void ldsm4(uint32_t* r, uint32_t addr) {
    asm volatile("ldmatrix.sync.aligned.m8n8.x4.shared.b16 {%0,%1,%2,%3}, [%4];"
                 : "=r"(r[0]), "=r"(r[1]), "=r"(r[2]), "=r"(r[3]) : "r"(addr));
}
__device__ __forceinline__ void ldsm2(uint32_t* r, uint32_t addr) {
    asm volatile("ldmatrix.sync.aligned.m8n8.x2.shared.b16 {%0,%1}, [%2];"
                 : "=r"(r[0]), "=r"(r[1]) : "r"(addr));
}
__device__ __forceinline__ void mma16816h(float* c, const uint32_t* a, const uint32_t* b) {
    asm volatile("mma.sync.aligned.m16n8k16.row.col.f32.f16.f16.f32 "
                 "{%0,%1,%2,%3}, {%4,%5,%6,%7}, {%8,%9}, {%0,%1,%2,%3};"
                 : "+f"(c[0]), "+f"(c[1]), "+f"(c[2]), "+f"(c[3])
                 : "r"(a[0]), "r"(a[1]), "r"(a[2]), "r"(a[3]), "r"(b[0]), "r"(b[1]));
}
__device__ __forceinline__ void cpa16(uint32_t dst, const void* src) {
    asm volatile("cp.async.cg.shared.global [%0], [%1], 16;" :: "r"(dst), "l"(src));
}
__device__ __forceinline__ void cpa_commit() { asm volatile("cp.async.commit_group;"); }
__device__ __forceinline__ void cpa_wait1()  { asm volatile("cp.async.wait_group 1;"); }
__device__ __forceinline__ void cpa_wait0()  { asm volatile("cp.async.wait_group 0;"); }

// ---------------------------------------------------------------------------
// Stage A: blur mask from rgb image + depth mask
// ---------------------------------------------------------------------------
__global__ void k_zeroflags() { g_anyR = 0; g_anyD = 0; }

__global__ void k_gray(const float* __restrict__ rgb) {
    int idx = blockIdx.x * blockDim.x + threadIdx.x;
    if (idx >= NB*IMG*IMG) return;
    int b = idx / (IMG*IMG);
    int p = idx - b * (IMG*IMG);
    const float* base = rgb + (size_t)b * 3 * IMG * IMG;
    float g = 0.299f*base[p] + 0.587f*base[IMG*IMG + p] + 0.114f*base[2*IMG*IMG + p];
    g *= 255.0f;
    g = fminf(fmaxf(g, 0.0f), 255.0f);
    g_gray[idx] = g;
}

__global__ void k_lap() {
    int idx = blockIdx.x * blockDim.x + threadIdx.x;
    if (idx >= NB*IMG*IMG) return;
    int b = idx / (IMG*IMG);
    int p = idx - b * (IMG*IMG);
    int y = p / IMG, x = p - y * IMG;
    const float* g = g_gray + (size_t)b * IMG * IMG;
    float c = g[y*IMG + x];
    float u = (y > 0)       ? g[(y-1)*IMG + x] : 0.0f;
    float d = (y < IMG-1)   ? g[(y+1)*IMG + x] : 0.0f;
    float l = (x > 0)       ? g[y*IMG + x-1]   : 0.0f;
    float r = (x < IMG-1)   ? g[y*IMG + x+1]   : 0.0f;
    g_lap[idx] = u + d + l + r - 4.0f*c;
}

__global__ void k_flags() {
    int idx = blockIdx.x * blockDim.x + threadIdx.x;
    if (idx >= NB*127*127) return;
    int b = idx / (127*127);
    int rem = idx - b * (127*127);
    int i = rem / 127, j = rem - i * 127;
    const float* lp = g_lap + (size_t)b * IMG * IMG + (4*i)*IMG + 4*j;
    float s1 = 0.0f, s2 = 0.0f;
    #pragma unroll
    for (int dy = 0; dy < 8; dy++) {
        #pragma unroll
        for (int dx = 0; dx < 8; dx++) {
            float v = lp[dy*IMG + dx];
            s1 += v; s2 += v*v;
        }
    }
    float var = (s2 - s1*s1*(1.0f/64.0f)) * (1.0f/63.0f);
    g_flags[idx] = (var < 50.0f) ? 1.0f : 0.0f;
}

__global__ void k_masks(const float* __restrict__ depth) {
    int idx = blockIdx.x * blockDim.x + threadIdx.x;
    if (idx >= NB*64*64) return;
    int b = idx / (64*64);
    int rem = idx - b * (64*64);
    int k = rem / 64, l = rem - k * 64;
    float f = 0.0f;
    #pragma unroll
    for (int da = 0; da < 2; da++) {
        int a = 2*k - da;
        if (a < 0) continue;
        #pragma unroll
        for (int db = 0; db < 2; db++) {
            int bb = 2*l - db;
            if (bb < 0) continue;
            f = fmaxf(f, g_flags[((size_t)b*127 + a)*127 + bb]);
        }
    }
    g_maskR[idx] = f;
    float dv = depth[((size_t)b*3 + 2)*IMG*IMG + (8*k)*IMG + 8*l];
    float md = (dv <= 0.0f) ? 1.0f : 0.0f;
    g_maskD[idx] = md;
    if (f  > 0.0f) atomicOr(&g_anyR, 1);
    if (md > 0.0f) atomicOr(&g_anyD, 1);
}

// ---------------------------------------------------------------------------
// Layout kernels
// ---------------------------------------------------------------------------
__global__ void k_zero_aux(int n4, int useRmask) {
    if ((useRmask ? g_anyR : g_anyD) == 0) return;
    int i = blockIdx.x * blockDim.x + threadIdx.x;
    if (i >= n4) return;
    uint4 z = {0, 0, 0, 0};
    ((uint4*)g_auxh)[i] = z;
}

__global__ void k_cvtaux_pad(const float* __restrict__ aux, int C, int S,
                             int useRmask) {
    if ((useRmask ? g_anyR : g_anyD) == 0) return;
    __shared__ float tile[32][33];
    int S32 = (S + 31) / 32;
    int xt = blockIdx.x % S32;
    int ct = blockIdx.x / S32;
    int y  = blockIdx.y;
    int b  = blockIdx.z;
    int tx = threadIdx.x & 31;
    int tg = threadIdx.x >> 5;
    int S2 = S + 2;
    for (int cc = tg; cc < 32; cc += 8) {
        int x = xt * 32 + tx, c = ct * 32 + cc;
        float v = 0.0f;
        if (x < S) v = aux[(((size_t)b * C + c) * S + y) * S + x];
        tile[cc][tx] = v;
    }
    __syncthreads();
    for (int xx = tg; xx < 32; xx += 8) {
        int x = xt * 32 + xx, c = ct * 32 + tx;
        if (x < S) {
            size_t o = (((size_t)b * S2 + y + 1) * S2 + x + 1) * C + c;
            g_auxh[o] = __float2half_rn(tile[tx][xx]);
        }
    }
}

// ---------------------------------------------------------------------------
// Winograd F(2x2,3x3) transforms
// ---------------------------------------------------------------------------
__global__ void k_wino_w(const float* __restrict__ w, int C) {
    if (g_anyR == 0 && g_anyD == 0) return;
    int idx = blockIdx.x * blockDim.x + threadIdx.x;
    if (idx >= C * C) return;
    int co = idx / C, ci = idx - co * C;
    const float* gp = w + ((size_t)co * C + ci) * 9;
    float g[3][3];
    #pragma unroll
    for (int i = 0; i < 3; i++)
        #pragma unroll
        for (int j = 0; j < 3; j++) g[i][j] = gp[i*3 + j];
    float q[4][3];
    #pragma unroll
    for (int j = 0; j < 3; j++) {
        q[0][j] = g[0][j];
        q[1][j] = 0.5f * (g[0][j] + g[1][j] + g[2][j]);
        q[2][j] = 0.5f * (g[0][j] - g[1][j] + g[2][j]);
        q[3][j] = g[2][j];
    }
    #pragma unroll
    for (int i = 0; i < 4; i++) {
        float u0 = q[i][0];
        float u1 = 0.5f * (q[i][0] + q[i][1] + q[i][2]);
        float u2 = 0.5f * (q[i][0] - q[i][1] + q[i][2]);
        float u3 = q[i][2];
        g_U[((size_t)(i*4 + 0) * C + co) * C + ci] = __float2half_rn(u0);
        g_U[((size_t)(i*4 + 1) * C + co) * C + ci] = __float2half_rn(u1);
        g_U[((size_t)(i*4 + 2) * C + co) * C + ci] = __float2half_rn(u2);
        g_U[((size_t)(i*4 + 3) * C + co) * C + ci] = __float2half_rn(u3);
    }
}

__global__ void k_wino_in(int C, int S, int T, int NBT, int useRmask) {
    if ((useRmask ? g_anyR : g_anyD) == 0) return;
    int idx = blockIdx.x * blockDim.x + threadIdx.x;
    if (idx >= NBT * C) return;
    int ci = idx % C;
    int n  = idx / C;
    int b  = n / T;
    int t  = n - b * T;
    int W  = S >> 1;
    int ty = t / W, tx = t - ty * W;
    int S2 = S + 2;
    const __half* src = g_auxh + (((size_t)b * S2 + 2*ty) * S2 + 2*tx) * C + ci;
    float d[4][4];
    #pragma unroll
    for (int i = 0; i < 4; i++)
        #pragma unroll
        for (int j = 0; j < 4; j++)
            d[i][j] = __half2float(src[((size_t)i * S2 + j) * C]);
    float a[4][4];
    #pragma unroll
    for (int j = 0; j < 4; j++) {
        a[0][j] = d[0][j] - d[2][j];
        a[1][j] = d[1][j] + d[2][j];
        a[2][j] = d[2][j] - d[1][j];
        a[3][j] = d[1][j] - d[3][j];
    }
    #pragma unroll
    for (int i = 0; i < 4; i++) {
        float v0 = a[i][0] - a[i][2];
        float v1 = a[i][1] + a[i][2];
        float v2 = a[i][2] - a[i][1];
        float v3 = a[i][1] - a[i][3];
        g_V[((size_t)(i*4 + 0) * NBT + n) * C + ci] = __float2half_rn(v0);
        g_V[((size_t)(i*4 + 1) * NBT + n) * C + ci] = __float2half_rn(v1);
        g_V[((size_t)(i*4 + 2) * NBT + n) * C + ci] = __float2half_rn(v2);
        g_V[((size_t)(i*4 + 3) * NBT + n) * C + ci] = __float2half_rn(v3);
    }
}

// ---------------------------------------------------------------------------
// 16 batched GEMMs (grid.z = k): M_k[co][n] = U_k[co][:] . V_k[n][:]
// CTA: 64 co x 256 n, 8 warps (2M x 4N, warp = 32co x 64n), K-chunk 32.
// fp16 mma, fp32 accum, fp16 M output. Double-buffered cp.async.
// smem rows padded to 40 elems (80B) -> conflict-free ldmatrix.
// ---------------------------------------------------------------------------
#define WROW 40
#define WA_ELEMS (64*WROW)            // 2560
#define WB_ELEMS (256*WROW)           // 10240
#define WSTAGE (WA_ELEMS + WB_ELEMS)  // 12800
#define WSMEM_BYTES (2*WSTAGE*2)      // 51200

template<int C>
__global__ void __launch_bounds__(256) k_wino_mm(int NBT, int useRmask) {
    if ((useRmask ? g_anyR : g_anyD) == 0) return;

    extern __shared__ __align__(16) char smem_raw[];
    const uint32_t sm0 = smem_u32(smem_raw);

    const int k      = blockIdx.z;
    const int coBase = blockIdx.y * 64;
    const int nBase  = blockIdx.x * 256;

    const int tid  = threadIdx.x;
    const int lane = tid & 31;
    const int wid  = tid >> 5;
    const int wm   = wid & 1;       // 2 x 32co
    const int wn   = wid >> 1;      // 4 x 64n

    const __half* Ubase = g_U + (size_t)k * C * C;
    const __half* Vbase = g_V + (size_t)k * NBT * C;

    const int aM = ((lane >> 3) & 1) * 8 + (lane & 7);
    const int aK = (lane >> 4) * 8;
    const int lb = lane & 15;
    const int bRow = lb & 7;
    const int bK   = (lb >> 3) * 8;

    float acc[2][8][4];
    #pragma unroll
    for (int mf = 0; mf < 2; mf++)
        #pragma unroll
        for (int nf = 0; nf < 8; nf++)
            #pragma unroll
            for (int q = 0; q < 4; q++) acc[mf][nf][q] = 0.0f;

    constexpr int NCHUNK = C / 32;

    auto fill = [&](int s, int ci0) {
        uint32_t base = sm0 + (uint32_t)(s * WSTAGE) * 2;
        // A: 64 rows x 32 ci = 256 16B-chunks
        for (int i = tid; i < 256; i += 256) {
            int row = i >> 2, j = i & 3;
            cpa16(base + (uint32_t)(row * WROW + j * 8) * 2,
                  Ubase + ((size_t)(coBase + row)) * C + ci0 + j * 8);
        }
        // B: 256 rows x 32 ci = 1024 16B-chunks
        uint32_t bb = base + (uint32_t)WA_ELEMS * 2;
        for (int i = tid; i < 1024; i += 256) {
            int row = i >> 2, j = i & 3;
            cpa16(bb + (uint32_t)(row * WROW + j * 8) * 2,
                  Vbase + ((size_t)(nBase + row)) * C + ci0 + j * 8);
        }
    };

    fill(0, 0);
    cpa_commit();

    for (int kk = 0; kk < NCHUNK; kk++) {
        int s = kk & 1;
        if (kk + 1 < NCHUNK) {
            fill(s ^ 1, (kk + 1) * 32);
            cpa_commit();
            cpa_wait1();
        } else {
            cpa_wait0();
        }
        __syncthreads();

        const uint32_t base = sm0 + (uint32_t)(s * WSTAGE) * 2;
        const uint32_t sA32 = base;
        const uint32_t sB32 = base + (uint32_t)WA_ELEMS * 2;

        #pragma unroll
        for (int ks = 0; ks < 2; ks++) {
            uint32_t Af[2][4];
            #pragma unroll
            for (int mf = 0; mf < 2; mf++) {
                int ea = (wm * 32 + mf * 16 + aM) * WROW + ks * 16 + aK;
                ldsm4(Af[mf], sA32 + ea * 2);
            }
            #pragma unroll
            for (int nf = 0; nf < 8; nf++) {
                int eb = (wn * 64 + nf * 8 + bRow) * WROW + ks * 16 + bK;
                uint32_t Bf[2];
                ldsm2(Bf, sB32 + eb * 2);
                #pragma unroll
                for (int mf = 0; mf < 2; mf++)
                    mma16816h(acc[mf][nf], Af[mf], Bf);
            }
        }
        __syncthreads();
    }

    // epilogue: M[k][co][n] fp16
    __half* Mb = g_M + (size_t)k * C * NBT;
    #pragma unroll
    for (int mf = 0; mf < 2; mf++) {
        #pragma unroll
        for (int nf = 0; nf < 8; nf++) {
            int co = coBase + wm * 32 + mf * 16 + (lane >> 2);
            int n  = nBase + wn * 64 + nf * 8 + (lane & 3) * 2;
            __half2 lo = __floats2half2_rn(acc[mf][nf][0], acc[mf][nf][1]);
            __half2 hi = __floats2half2_rn(acc[mf][nf][2], acc[mf][nf][3]);
            *(__half2*)(Mb + (size_t)co * NBT + n) = lo;
            *(__half2*)(Mb + (size_t)(co + 8) * NBT + n) = hi;
        }
    }
}

// Output: o = A^T m A -> 2x2 per (co, tile) into g_t NCHW.
__global__ void k_wino_out(int C, int S, int T, int NBT, int useRmask) {
    if ((useRmask ? g_anyR : g_anyD) == 0) return;
    int idx = blockIdx.x * blockDim.x + threadIdx.x;
    if (idx >= C * NBT) return;
    int n  = idx % NBT;
    int co = idx / NBT;
    int b  = n / T;
    int t  = n - b * T;
    int W  = S >> 1;
    int ty = t / W, tx = t - ty * W;

    float m[4][4];
    #pragma unroll
    for (int i = 0; i < 4; i++)
        #pragma unroll
        for (int j = 0; j < 4; j++)
            m[i][j] = __half2float(g_M[((size_t)(i*4 + j) * C + co) * NBT + n]);

    float r[2][4];
    #pragma unroll
    for (int j = 0; j < 4; j++) {
        r[0][j] = m[0][j] + m[1][j] + m[2][j];
        r[1][j] = m[1][j] - m[2][j] - m[3][j];
    }
    float o00 = r[0][0] + r[0][1] + r[0][2];
    float o01 = r[0][1] - r[0][2] - r[0][3];
    float o10 = r[1][0] + r[1][1] + r[1][2];
    float o11 = r[1][1] - r[1][2] - r[1][3];

    float* dst = g_t + (((size_t)b * C + co) * S + 2*ty) * S + 2*tx;
    float2 row0; row0.x = o00; row0.y = o01;
    float2 row1; row1.x = o10; row1.y = o11;
    *(float2*)dst = row0;
    *(float2*)(dst + S) = row1;
}

// ---------------------------------------------------------------------------
// BN stats over (B, H, W) per channel -> fused scale/bias
// ---------------------------------------------------------------------------
__global__ void k_bnstats(const float* __restrict__ gamma,
                          const float* __restrict__ beta, int C, int S,
                          int useRmask) {
    if ((useRmask ? g_anyR : g_anyD) == 0) return;
    int c = blockIdx.x;
    int n = NB * S * S;
    float s = 0.0f, q = 0.0f;
    for (int i = threadIdx.x; i < n; i += 256) {
        int b = i / (S*S);
        int p = i - b * (S*S);
        float v = g_t[((size_t)b*C + c)*S*S + p];
        s += v; q += v*v;
    }
    __shared__ float ss[256], sq[256];
    ss[threadIdx.x] = s; sq[threadIdx.x] = q;
    __syncthreads();
    for (int o = 128; o > 0; o >>= 1) {
        if (threadIdx.x < o) {
            ss[threadIdx.x] += ss[threadIdx.x + o];
            sq[threadIdx.x] += sq[threadIdx.x + o];
        }
        __syncthreads();
    }
    if (threadIdx.x == 0) {
        float mean = ss[0] / (float)n;
        float var  = sq[0] / (float)n - mean*mean;
        float rstd = 1.0f / sqrtf(var + 1e-5f);
        float A = gamma[c] * rstd;
        g_bnA[c] = A;
        g_bnB[c] = beta[c] - mean * A;
    }
}

// ---------------------------------------------------------------------------
// Spatial attention: per-pixel channel mean/max (coalesced), 7x7 conv + sigmoid
// ---------------------------------------------------------------------------
__global__ void k_spstats(const float* __restrict__ mainp, int C, int S,
                          int useRmask) {
    if ((useRmask ? g_anyR : g_anyD) == 0) return;
    int b = blockIdx.y;
    int p = blockIdx.x * blockDim.x + threadIdx.x;
    if (p >= S*S) return;
    const float* base = mainp + (size_t)b*C*S*S + p;
    float m = 0.0f, mx = -3.402823466e38f;
    #pragma unroll 4
    for (int c = 0; c < C; c++) {
        float v = base[(size_t)c*S*S];
        m += v; mx = fmaxf(mx, v);
    }
    g_spmean[(size_t)b*S*S + p] = m / (float)C;
    g_spmax [(size_t)b*S*S + p] = mx;
}

__global__ void k_spconv(const float* __restrict__ saw, int S, int useRmask) {
    if ((useRmask ? g_anyR : g_anyD) == 0) return;
    __shared__ float sw_[196];
    int b = blockIdx.y, y = blockIdx.x, x = threadIdx.x;
    for (int i = x; i < 196; i += blockDim.x) sw_[i] = saw[i];
    __syncthreads();
    float step = 2.0f / (float)(S - 1);
    float acc = 0.0f;
    #pragma unroll
    for (int ky = 0; ky < 7; ky++) {
        int yy = y + ky - 3;
        if (yy < 0 || yy >= S) continue;
        #pragma unroll
        for (int kx = 0; kx < 7; kx++) {
            int xx = x + kx - 3;
            if (xx < 0 || xx >= S) continue;
            int widx = ky*7 + kx;
            acc += sw_[widx]        * g_spmean[(size_t)b*S*S + yy*S + xx];
            acc += sw_[49 + widx]   * g_spmax [(size_t)b*S*S + yy*S + xx];
            acc += sw_[98 + widx]   * (-1.0f + (float)xx * step);
            acc += sw_[147 + widx]  * (-1.0f + (float)yy * step);
        }
    }
    g_sw[(size_t)b*S*S + y*S + x] = 1.0f / (1.0f + expf(-acc));
}

// ---------------------------------------------------------------------------
// Channel attention: GAP -> ca1 -> relu -> ca2 -> sigmoid
// ---------------------------------------------------------------------------
__global__ void k_gap(const float* __restrict__ mainp, int C, int S,
                      int useRmask) {
    if ((useRmask ? g_anyR : g_anyD) == 0) return;
    int c = blockIdx.x, b = blockIdx.y;
    const float* p = mainp + ((size_t)b*C + c)*S*S;
    float s = 0.0f;
    for (int i = threadIdx.x; i < S*S; i += 128) s += p[i];
    __shared__ float sm[128];
    sm[threadIdx.x] = s;
    __syncthreads();
    for (int o = 64; o > 0; o >>= 1) {
        if (threadIdx.x < o) sm[threadIdx.x] += sm[threadIdx.x + o];
        __syncthreads();
    }
    if (threadIdx.x == 0) g_gap[b*C + c] = sm[0] / (float)(S*S);
}

__global__ void k_ca(const float* __restrict__ ca1, const float* __restrict__ ca2,
                     int C, int Rr, int useRmask) {
    if ((useRmask ? g_anyR : g_anyD) == 0) return;
    int b = blockIdx.x;
    __shared__ float sg[1024];
    __shared__ float sh[64];
    for (int c = threadIdx.x; c < C; c += 128) sg[c] = g_gap[b*C + c];
    __syncthreads();
    for (int rr = threadIdx.x; rr < Rr; rr += 128) {
        float h = 0.0f;
        for (int c = 0; c < C; c++) h += ca1[(size_t)rr*C + c] * sg[c];
        sh[rr] = fmaxf(h, 0.0f);
    }
    __syncthreads();
    for (int c = threadIdx.x; c < C; c += 128) {
        float v = 0.0f;
        for (int rr = 0; rr < Rr; rr++) v += ca2[(size_t)c*Rr + rr] * sh[rr];
        g_cw[b*C + c] = 1.0f / (1.0f + expf(-v));
    }
}

// ---------------------------------------------------------------------------
// Final blend: out = (inv==0) ? main : 2 * relu(A*t+B) * sw * cw
// ---------------------------------------------------------------------------
__global__ void k_final(const float* __restrict__ mainp, float* __restrict__ outp,
                        int C, int S, int step, int useRmask) {
    int idx = blockIdx.x * blockDim.x + threadIdx.x;
    int N = NB * C * S * S;
    if (idx >= N) return;
    int b   = idx / (C*S*S);
    int rem = idx - b * (C*S*S);
    int c   = rem / (S*S);
    int p   = rem - c * (S*S);
    int y = p / S, x = p - y * S;
    const float* maskp = useRmask ? g_maskR : g_maskD;
    float inv = maskp[((size_t)b*64 + y*step)*64 + x*step];
    float res;
    if (inv == 0.0f) {
        res = mainp[idx];
    } else {
        float tv = g_t[idx];
        float a  = fmaxf(g_bnA[c]*tv + g_bnB[c], 0.0f);
        res = ((a * g_sw[(size_t)b*S*S + p]) * g_cw[b*C + c]) * 2.0f;
    }
    outp[idx] = res;
}

// ---------------------------------------------------------------------------
// Host orchestration
// ---------------------------------------------------------------------------
struct LvlParams {
    const float *ft, *g, *b, *sa, *ca1, *ca2;
};

template<int C, int S>
static void run_dir(const float* mainp, const float* auxp, int useRmask,
                    float* outp, const LvlParams& P) {
    int S2 = S + 2;
    int nPad4 = NB * S2 * S2 * C / 8;
    k_zero_aux<<<(nPad4 + 255)/256, 256>>>(nPad4, useRmask);
    int S32 = (S + 31) / 32;
    k_cvtaux_pad<<<dim3(S32 * (C/32), S, NB), 256>>>(auxp, C, S, useRmask);

    constexpr int T = (S/2) * (S/2);
    constexpr int NBT = NB * T;
    k_wino_in<<<(NBT * C + 255)/256, 256>>>(C, S, T, NBT, useRmask);
    cudaFuncSetAttribute(k_wino_mm<C>,
                         cudaFuncAttributeMaxDynamicSharedMemorySize, WSMEM_BYTES);
    dim3 mgrid(NBT/256, C/64, 16);
    k_wino_mm<C><<<mgrid, 256, WSMEM_BYTES>>>(NBT, useRmask);
    k_wino_out<<<(C * NBT + 255)/256, 256>>>(C, S, T, NBT, useRmask);

    k_bnstats<<<C, 256>>>(P.g, P.b, C, S, useRmask);
    k_spstats<<<dim3((S*S + 255)/256, NB), 256>>>(mainp, C, S, useRmask);
    k_spconv<<<dim3(S, NB), S>>>(P.sa, S, useRmask);
    k_gap<<<dim3(C, NB), 128>>>(mainp, C, S, useRmask);
    k_ca<<<NB, 128>>>(P.ca1, P.ca2, C, C/16, useRmask);
    int N = NB * C * S * S;
    k_final<<<(N + 255)/256, 256>>>(mainp, outp, C, S, 64/S, useRmask);
}

extern "C" void kernel_launch(void* const* d_in, const int* in_sizes, int n_in,
                              void* d_out, int out_size) {
    // metadata order follows setup_inputs() dict insertion order:
    // rgb_feat0, depth_feat0, rgb_feat1, depth_feat1, rgb_feat2, depth_feat2,
    // rgb_img, depth_img, then per level: ft_w, bn_g, bn_b, sa_w, ca1_w, ca2_w
    const float* rgbF[3] = {(const float*)d_in[0], (const float*)d_in[2], (const float*)d_in[4]};
    const float* depF[3] = {(const float*)d_in[1], (const float*)d_in[3], (const float*)d_in[5]};
    const float* rgb_img   = (const float*)d_in[6];
    const float* depth_img = (const float*)d_in[7];
    LvlParams P[3];
    for (int i = 0; i < 3; i++) {
        int base = 8 + i*6;
        P[i].ft  = (const float*)d_in[base + 0];
        P[i].g   = (const float*)d_in[base + 1];
        P[i].b   = (const float*)d_in[base + 2];
        P[i].sa  = (const float*)d_in[base + 3];
        P[i].ca1 = (const float*)d_in[base + 4];
        P[i].ca2 = (const float*)d_in[base + 5];
    }
    float* out = (float*)d_out;

    // masks
    int npix = NB * IMG * IMG;
    k_zeroflags<<<1, 1>>>();
    k_gray <<<(npix + 255)/256, 256>>>(rgb_img);
    k_lap  <<<(npix + 255)/256, 256>>>();
    k_flags<<<(NB*127*127 + 255)/256, 256>>>();
    k_masks<<<(NB*64*64 + 255)/256, 256>>>(depth_img);

    const size_t szR0 = (size_t)NB*256*64*64;
    const size_t szR1 = (size_t)NB*512*32*32;
    const size_t szR2 = (size_t)NB*1024*16*16;
    float* oR0 = out;
    float* oR1 = oR0 + szR0;
    float* oR2 = oR1 + szR1;
    float* oD0 = oR2 + szR2;
    float* oD1 = oD0 + szR0;
    float* oD2 = oD1 + szR1;

    // level 0
    k_wino_w<<<(256*256 + 255)/256, 256>>>(P[0].ft, 256);
    run_dir<256, 64>(rgbF[0], depF[0], 1, oR0, P[0]);
    run_dir<256, 64>(depF[0], rgbF[0], 0, oD0, P[0]);
    // level 1
    k_wino_w<<<(512*512 + 255)/256, 256>>>(P[1].ft, 512);
    run_dir<512, 32>(rgbF[1], depF[1], 1, oR1, P[1]);
    run_dir<512, 32>(depF[1], rgbF[1], 0, oD1, P[1]);
    // level 2
    k_wino_w<<<(1024*1024 + 255)/256, 256>>>(P[2].ft, 1024);
    run_dir<1024,16>(rgbF[2], depF[2], 1, oR2, P[2]);
    run_dir<1024,16>(depF[2], rgbF[2], 0, oD2, P[2]);
}